// round 6
// baseline (speedup 1.0000x reference)
#include <cuda_runtime.h>
#include <cuda_bf16.h>
#include <cuda_fp16.h>
#include <mma.h>
#include <math.h>
#include <stdint.h>

using namespace nvcuda;

#define BATCH 16
#define INDIM 512
#define MIDC  256
#define HW    4096
#define HEADS 8

// ---------------- scratch (device globals; no allocation) ----------------
__device__ float  g_buf1[BATCH*MIDC*HW];    // reduce-GEMM output (pre-dw), fp32
__device__ __half g_xr_h[BATCH*MIDC*HW];    // xr (post dw+BN+ReLU), fp16, spatial
__device__ float  g_means[BATCH*MIDC];
__device__ float  g_nrm  [BATCH*MIDC];
__device__ float  g_gate [BATCH*MIDC];
__device__ float  g_gram_part[BATCH*HEADS*8*1024];
__device__ float  g_attnW[BATCH*HEADS*1024];
__device__ __nv_bfloat16 g_fused_bf[BATCH*INDIM*HW]; // [attn_out | fwm(unscaled)]
__device__ __nv_bfloat16 g_wred    [MIDC*INDIM];
__device__ __nv_bfloat16 g_wpost   [INDIM*2*MIDC];

// ================= wmma bf16 GEMM =================
#define AS_STRIDE 40
#define BS_STRIDE 136
#define CS_STRIDE 132
#define GEMM_SMEM (128*CS_STRIDE*4)

template<bool F32ACT, bool GATESCALE>
__global__ void __launch_bounds__(256)
k_wmma_gemm(const __nv_bfloat16* __restrict__ W,
            const void* __restrict__ actv,
            const float* __restrict__ bias,
            const float* __restrict__ resid,
            float* __restrict__ out,
            int Mtot) {
    extern __shared__ char sm[];
    __nv_bfloat16* As = (__nv_bfloat16*)sm;
    __nv_bfloat16* Bs = (__nv_bfloat16*)(sm + 128*AS_STRIDE*2);
    float*         Cs = (float*)sm;

    int tid = threadIdx.x;
    int w   = tid >> 5;
    int wm  = w & 3;
    int wn  = w >> 2;
    int nb = blockIdx.x * 128, mb = blockIdx.y * 128, b = blockIdx.z;

    const __nv_bfloat16* Ag = W + (size_t)mb * 512;
    const float*         Bg32 = (const float*)actv + (size_t)b * 512 * 4096 + nb;
    const __nv_bfloat16* Bg16 = (const __nv_bfloat16*)actv + (size_t)b * 512 * 4096 + nb;

    wmma::fragment<wmma::accumulator, 16, 16, 16, float> acc[2][4];
#pragma unroll
    for (int i = 0; i < 2; i++)
#pragma unroll
        for (int j = 0; j < 4; j++) wmma::fill_fragment(acc[i][j], 0.0f);

    for (int kc = 0; kc < 512; kc += 32) {
        __syncthreads();
#pragma unroll
        for (int t = 0; t < 2; t++) {
            int id = tid + t * 256;
            int r = id >> 2, c8 = (id & 3) * 8;
            uint4 v = *(const uint4*)(Ag + (size_t)r * 512 + kc + c8);
            *(uint4*)(As + r * AS_STRIDE + c8) = v;
        }
#pragma unroll
        for (int t = 0; t < 2; t++) {
            int id = tid + t * 256;
            int r = id >> 4, c8 = (id & 15) * 8;
            if (F32ACT) {
                float4 v0 = *(const float4*)(Bg32 + (size_t)(kc + r) * 4096 + c8);
                float4 v1 = *(const float4*)(Bg32 + (size_t)(kc + r) * 4096 + c8 + 4);
                __nv_bfloat162 p0 = __floats2bfloat162_rn(v0.x, v0.y);
                __nv_bfloat162 p1 = __floats2bfloat162_rn(v0.z, v0.w);
                __nv_bfloat162 p2 = __floats2bfloat162_rn(v1.x, v1.y);
                __nv_bfloat162 p3 = __floats2bfloat162_rn(v1.z, v1.w);
                uint4 pk;
                pk.x = *(uint32_t*)&p0; pk.y = *(uint32_t*)&p1;
                pk.z = *(uint32_t*)&p2; pk.w = *(uint32_t*)&p3;
                *(uint4*)(Bs + r * BS_STRIDE + c8) = pk;
            } else {
                uint4 v = *(const uint4*)(Bg16 + (size_t)(kc + r) * 4096 + c8);
                if (GATESCALE) {
                    int kr = kc + r;
                    if (kr >= 256) {
                        float gs = g_gate[b*MIDC + kr - 256];
                        __nv_bfloat162* p = (__nv_bfloat162*)&v;
#pragma unroll
                        for (int e = 0; e < 4; e++) {
                            float2 f = __bfloat1622float2(p[e]);
                            p[e] = __floats2bfloat162_rn(f.x * gs, f.y * gs);
                        }
                    }
                }
                *(uint4*)(Bs + r * BS_STRIDE + c8) = v;
            }
        }
        __syncthreads();
#pragma unroll
        for (int ks = 0; ks < 2; ks++) {
            wmma::fragment<wmma::matrix_a, 16, 16, 16, __nv_bfloat16, wmma::row_major> af[2];
            wmma::fragment<wmma::matrix_b, 16, 16, 16, __nv_bfloat16, wmma::row_major> bf[4];
#pragma unroll
            for (int i = 0; i < 2; i++)
                wmma::load_matrix_sync(af[i], As + (wm*32 + i*16) * AS_STRIDE + ks*16, AS_STRIDE);
#pragma unroll
            for (int j = 0; j < 4; j++)
                wmma::load_matrix_sync(bf[j], Bs + (ks*16) * BS_STRIDE + wn*64 + j*16, BS_STRIDE);
#pragma unroll
            for (int i = 0; i < 2; i++)
#pragma unroll
                for (int j = 0; j < 4; j++)
                    wmma::mma_sync(acc[i][j], af[i], bf[j], acc[i][j]);
        }
    }
    __syncthreads();
#pragma unroll
    for (int i = 0; i < 2; i++)
#pragma unroll
        for (int j = 0; j < 4; j++)
            wmma::store_matrix_sync(Cs + (wm*32 + i*16) * CS_STRIDE + wn*64 + j*16,
                                    acc[i][j], CS_STRIDE, wmma::mem_row_major);
    __syncthreads();
#pragma unroll
    for (int t = 0; t < 16; t++) {
        int id = tid + t * 256;
        int r = id >> 5, c = (id & 31) * 4;
        float bi = bias ? bias[mb + r] : 0.0f;
        float4 v = *(float4*)(Cs + r * CS_STRIDE + c);
        v.x += bi; v.y += bi; v.z += bi; v.w += bi;
        size_t off = ((size_t)b * Mtot + mb + r) * 4096 + nb + c;
        if (resid) {
            float4 rr = *(const float4*)(resid + off);
            v.x += rr.x; v.y += rr.y; v.z += rr.z; v.w += rr.w;
        }
        *(float4*)(out + off) = v;
    }
}

// ---------------- conversion (weights only) ----------------
__global__ void __launch_bounds__(256) k_cvt(const float* __restrict__ src,
                                             __nv_bfloat16* __restrict__ dst, int n) {
    int i = (blockIdx.x * 256 + threadIdx.x) * 4;
    if (i < n) {
        float4 v = *(const float4*)(src + i);
        __nv_bfloat162 p0 = __floats2bfloat162_rn(v.x, v.y);
        __nv_bfloat162 p1 = __floats2bfloat162_rn(v.z, v.w);
        uint2 pk;
        pk.x = *(uint32_t*)&p0; pk.y = *(uint32_t*)&p1;
        *(uint2*)(dst + i) = pk;
    }
}

// ================= radix-4 FFT (64-pt, 3 stages, in-place smem) =================
template<int Q, int M>
__device__ __forceinline__ void fft4s_fwd(float* Ar, float* Ai,
                                          const float* twr, const float* twi,
                                          int tid, bool col) {
#pragma unroll
    for (int i = 0; i < 4; i++) {
        int t = tid + (i << 8);
        int line = t >> 4;
        int j16 = t & 15;
        int blk = j16 / Q, j = j16 - blk * Q;
        int base = blk * (4 * Q) + j;
        int p0 = base, p1 = base + Q, p2 = base + 2*Q, p3 = base + 3*Q;
        int a0 = col ? p0*65 + line : line*65 + p0;
        int a1 = col ? p1*65 + line : line*65 + p1;
        int a2 = col ? p2*65 + line : line*65 + p2;
        int a3 = col ? p3*65 + line : line*65 + p3;
        float x0r=Ar[a0], x0i=Ai[a0], x1r=Ar[a1], x1i=Ai[a1];
        float x2r=Ar[a2], x2i=Ai[a2], x3r=Ar[a3], x3i=Ai[a3];
        float t0r=x0r+x2r, t0i=x0i+x2i;
        float t1r=x0r-x2r, t1i=x0i-x2i;
        float t2r=x1r+x3r, t2i=x1i+x3i;
        float t3r=x1i-x3i, t3i=x3r-x1r;          // -i*(x1-x3)
        Ar[a0]=t0r+t2r; Ai[a0]=t0i+t2i;
        float w1r=twr[M*j],   w1i=twi[M*j];
        float w2r=twr[2*M*j], w2i=twi[2*M*j];
        float w3r=twr[3*M*j], w3i=twi[3*M*j];
        float u1r=t1r+t3r, u1i=t1i+t3i;
        Ar[a1]=u1r*w1r-u1i*w1i; Ai[a1]=u1r*w1i+u1i*w1r;
        float u2r=t0r-t2r, u2i=t0i-t2i;
        Ar[a2]=u2r*w2r-u2i*w2i; Ai[a2]=u2r*w2i+u2i*w2r;
        float u3r=t1r-t3r, u3i=t1i-t3i;
        Ar[a3]=u3r*w3r-u3i*w3i; Ai[a3]=u3r*w3i+u3i*w3r;
    }
}

template<int Q, int M>
__device__ __forceinline__ void fft4s_inv(float* Ar, float* Ai,
                                          const float* twr, const float* twi,
                                          int tid, bool col) {
#pragma unroll
    for (int i = 0; i < 4; i++) {
        int t = tid + (i << 8);
        int line = t >> 4;
        int j16 = t & 15;
        int blk = j16 / Q, j = j16 - blk * Q;
        int base = blk * (4 * Q) + j;
        int p0 = base, p1 = base + Q, p2 = base + 2*Q, p3 = base + 3*Q;
        int a0 = col ? p0*65 + line : line*65 + p0;
        int a1 = col ? p1*65 + line : line*65 + p1;
        int a2 = col ? p2*65 + line : line*65 + p2;
        int a3 = col ? p3*65 + line : line*65 + p3;
        float u0r=Ar[a0], u0i=Ai[a0];
        float v1r=Ar[a1], v1i=Ai[a1];
        float v2r=Ar[a2], v2i=Ai[a2];
        float v3r=Ar[a3], v3i=Ai[a3];
        float w1r=twr[M*j],   w1i=twi[M*j];
        float w2r=twr[2*M*j], w2i=twi[2*M*j];
        float w3r=twr[3*M*j], w3i=twi[3*M*j];
        float b1r=v1r*w1r+v1i*w1i, b1i=v1i*w1r-v1r*w1i;
        float b2r=v2r*w2r+v2i*w2i, b2i=v2i*w2r-v2r*w2i;
        float b3r=v3r*w3r+v3i*w3i, b3i=v3i*w3r-v3r*w3i;
        float s0r=u0r+b2r, s0i=u0i+b2i;
        float s1r=u0r-b2r, s1i=u0i-b2i;
        float s2r=b1r+b3r, s2i=b1i+b3i;
        float s3r=b3i-b1i, s3i=b1r-b3r;          // +i*(b1-b3)
        Ar[a0]=s0r+s2r; Ai[a0]=s0i+s2i;
        Ar[a1]=s1r+s3r; Ai[a1]=s1i+s3i;
        Ar[a2]=s0r-s2r; Ai[a2]=s0i-s2i;
        Ar[a3]=s1r-s3r; Ai[a3]=s1i-s3i;
    }
}

__device__ __forceinline__ void fft4_fwd_dim(float* Ar, float* Ai,
                                             const float* twr, const float* twi,
                                             int tid, bool col) {
    fft4s_fwd<16,1>(Ar, Ai, twr, twi, tid, col); __syncthreads();
    fft4s_fwd<4,4> (Ar, Ai, twr, twi, tid, col); __syncthreads();
    fft4s_fwd<1,16>(Ar, Ai, twr, twi, tid, col); __syncthreads();
}

__device__ __forceinline__ void fft4_inv_dim(float* Ar, float* Ai,
                                             const float* twr, const float* twi,
                                             int tid, bool col) {
    fft4s_inv<1,16>(Ar, Ai, twr, twi, tid, col); __syncthreads();
    fft4s_inv<4,4> (Ar, Ai, twr, twi, tid, col); __syncthreads();
    fft4s_inv<16,1>(Ar, Ai, twr, twi, tid, col); __syncthreads();
}

__device__ __forceinline__ void fft_load_tw64(float* twr, float* twi, int tid) {
    if (tid < 64) {
        float s, c;
        sincosf(-6.28318530717958647692f * (float)tid * (1.0f/64.0f), &s, &c);
        twr[tid] = c; twi[tid] = s;
    }
}

// ---- K2: dw3x3 + BN + ReLU + stats + xr store + fwd FFT + square + inv FFT -> fwm ----
__global__ void __launch_bounds__(256) k_dwfft(const float* __restrict__ dww,
                                               const float* __restrict__ dwb,
                                               const float* __restrict__ gamma,
                                               const float* __restrict__ beta,
                                               const float* __restrict__ mean,
                                               const float* __restrict__ var) {
    __shared__ float Abuf[66*66];        // halo tile, then reused as Ar[64*65]
    __shared__ float Ai[64*65];
    __shared__ float twr[64], twi[64];
    __shared__ float rs[8], rq[8];
    int plane = blockIdx.x;
    int b = plane >> 8, c = plane & (MIDC-1);
    int tid = threadIdx.x;
    const float* src = g_buf1 + (size_t)plane*HW;
    for (int idx = tid; idx < 66*66; idx += 256) {
        int r = idx / 66, cc = idx - r*66;
        int y = r - 1, x = cc - 1;
        float v = 0.f;
        if ((unsigned)y < 64u && (unsigned)x < 64u) v = src[y*64 + x];
        Abuf[idx] = v;
    }
    fft_load_tw64(twr, twi, tid);
    __syncthreads();
    float w0 = dww[c*9+0], w1 = dww[c*9+1], w2 = dww[c*9+2];
    float w3 = dww[c*9+3], w4 = dww[c*9+4], w5 = dww[c*9+5];
    float w6 = dww[c*9+6], w7 = dww[c*9+7], w8 = dww[c*9+8];
    float scale = gamma[c] * rsqrtf(var[c] + 1e-5f);
    float shift = beta[c] - mean[c]*scale;
    float bia = dwb[c];
    float xr[16];
    float s = 0.f, sq = 0.f;
    __half* xh = g_xr_h + (size_t)plane*HW;
#pragma unroll
    for (int i = 0; i < 16; i++) {
        int p = tid + i*256;
        int py = p >> 6, px = p & 63;
        const float* t0 = &Abuf[py*66 + px];
        float acc = t0[0]*w0 + t0[1]*w1 + t0[2]*w2
                  + t0[66]*w3 + t0[67]*w4 + t0[68]*w5
                  + t0[132]*w6 + t0[133]*w7 + t0[134]*w8;
        acc = fmaxf((acc + bia)*scale + shift, 0.f);
        xr[i] = acc; s += acc; sq += acc*acc;
        xh[p] = __float2half(acc);
    }
    __syncthreads();   // all reads of halo tile done
#pragma unroll
    for (int i = 0; i < 16; i++) {
        int p = tid + i*256; int r = p >> 6, cc = p & 63;
        Abuf[r*65 + cc] = xr[i];
        Ai[r*65 + cc] = 0.f;
    }
#pragma unroll
    for (int o = 16; o; o >>= 1) {
        s  += __shfl_xor_sync(0xffffffffu, s,  o);
        sq += __shfl_xor_sync(0xffffffffu, sq, o);
    }
    int wid = tid >> 5;
    if ((tid & 31) == 0) { rs[wid] = s; rq[wid] = sq; }
    __syncthreads();
    if (tid == 0) {
        float ts = 0.f, tq = 0.f;
#pragma unroll
        for (int w = 0; w < 8; w++) { ts += rs[w]; tq += rq[w]; }
        g_means[plane] = ts * (1.f/4096.f);
        g_nrm[plane]   = sqrtf(tq);   // Parseval
    }
    // forward FFT (unscaled, digit-rev)
    fft4_fwd_dim(Abuf, Ai, twr, twi, tid, false);
    fft4_fwd_dim(Abuf, Ai, twr, twi, tid, true);
    // complex square elementwise (digit-rev order is fine)
#pragma unroll
    for (int i = 0; i < 16; i++) {
        int p = tid + i*256; int r = p >> 6, cc = p & 63;
        int a = r*65 + cc;
        float ar = Abuf[a], ai = Ai[a];
        Abuf[a] = ar*ar - ai*ai;
        Ai[a]   = 2.f*ar*ai;
    }
    __syncthreads();
    // inverse FFT (digit-rev -> natural, unscaled)
    fft4_inv_dim(Abuf, Ai, twr, twi, tid, false);
    fft4_inv_dim(Abuf, Ai, twr, twi, tid, true);
    // fwm_unscaled = IDFT_u(A^2) / 262144 ; SE gate applied in post GEMM
    __nv_bfloat16* dst = g_fused_bf + ((size_t)b*INDIM + MIDC + c)*HW;
#pragma unroll
    for (int i = 0; i < 16; i++) {
        int p = tid + i*256; int r = p >> 6, cc = p & 63;
        dst[p] = __float2bfloat16(Abuf[r*65+cc] * (1.f/262144.f));
    }
}

// ---------------- K3: SE gate MLP ----------------
__global__ void __launch_bounds__(256) k_gate(const float* __restrict__ w1,
                                              const float* __restrict__ b1,
                                              const float* __restrict__ w2,
                                              const float* __restrict__ b2) {
    int b = blockIdx.x;
    __shared__ float sm[MIDC];
    __shared__ float sh[32];
    int tid = threadIdx.x;
    sm[tid] = g_means[b*MIDC + tid];
    __syncthreads();
    if (tid < 32) {
        float a = b1[tid];
        const float* wr = w1 + tid*MIDC;
        for (int c2 = 0; c2 < MIDC; c2++) a += wr[c2]*sm[c2];
        sh[tid] = fmaxf(a, 0.f);
    }
    __syncthreads();
    float a = b2[tid];
    const float* wr = w2 + tid*32;
#pragma unroll
    for (int j = 0; j < 32; j++) a += wr[j]*sh[j];
    g_gate[b*MIDC + tid] = 1.f / (1.f + expf(-a));
}

// ---------------- K4a: spatial Gram[c,d] = sum_n xr_c(n) * xr_d(-n) ----------------
__global__ void __launch_bounds__(256) k_gram() {
    int sl = blockIdx.x, h = blockIdx.y, b = blockIdx.z;
    size_t base = ((size_t)b*MIDC + h*32) * HW;
    __shared__ float sX[32][65], sY[32][65];
    __shared__ float sRed[4][1024];
    int tid = threadIdx.x;
    int nsub = tid >> 6;
    int tt = tid & 63;
    int c0 = (tt >> 3) * 4, d0 = (tt & 7) * 4;
    float acc[4][4] = {};
    for (int n0 = 0; n0 < 512; n0 += 64) {
        int o = sl*512 + n0;          // 64-aligned -> one image row
        int row = o >> 6;
        int grow = (64 - row) & 63;
        __syncthreads();
        for (int idx = tid; idx < 2048; idx += 256) {
            int cc = idx >> 6, nn = idx & 63;
            sX[cc][nn] = __half2float(g_xr_h[base + (size_t)cc*HW + o + nn]);
            // reversed operand: store column nn of reversed row at reversed position
            sY[cc][(64 - nn) & 63] = __half2float(g_xr_h[base + (size_t)cc*HW + grow*64 + nn]);
        }
        __syncthreads();
        int nlo = nsub * 16;
#pragma unroll 4
        for (int nn = nlo; nn < nlo + 16; nn++) {
            float rc[4], rd[4];
#pragma unroll
            for (int i = 0; i < 4; i++) rc[i] = sX[c0+i][nn];
#pragma unroll
            for (int j = 0; j < 4; j++) rd[j] = sY[d0+j][nn];
#pragma unroll
            for (int i = 0; i < 4; i++)
#pragma unroll
                for (int j = 0; j < 4; j++)
                    acc[i][j] += rc[i]*rd[j];
        }
    }
#pragma unroll
    for (int i = 0; i < 4; i++)
#pragma unroll
        for (int j = 0; j < 4; j++)
            sRed[nsub][tt*16 + i*4 + j] = acc[i][j];
    __syncthreads();
    float* part = g_gram_part + ((size_t)(b*HEADS + h)*8 + sl)*1024;
#pragma unroll
    for (int q = 0; q < 4; q++) {
        int e = tid*4 + q;
        int te = e >> 4, sub = e & 15;
        int i = sub >> 2, j = sub & 3;
        int c = (te >> 3)*4 + i, d = (te & 7)*4 + j;
        part[c*32 + d] = sRed[0][e] + sRed[1][e] + sRed[2][e] + sRed[3][e];
    }
}

// ---------------- K4b: reduce partials + normalize + softmax ----------------
__global__ void __launch_bounds__(256) k_soft(const float* __restrict__ temp) {
    int h = blockIdx.x, b = blockIdx.y;
    __shared__ float sA[32][33], sN[32];
    int tid = threadIdx.x;
    if (tid < 32) sN[tid] = fmaxf(g_nrm[b*MIDC + h*32 + tid], 1e-12f);
    __syncthreads();
    float tK = temp[h];
    const float* part = g_gram_part + (size_t)(b*HEADS + h)*8*1024;
#pragma unroll
    for (int q = 0; q < 4; q++) {
        int e = tid*4 + q;
        int c = e >> 5, d = e & 31;
        float v = 0.f;
#pragma unroll
        for (int s = 0; s < 8; s++) v += part[s*1024 + e];
        sA[c][d] = v * tK / (sN[c] * sN[d]);
    }
    __syncthreads();
    int lane = tid & 31;
    float* aw = g_attnW + (size_t)(b*HEADS + h)*1024;
#pragma unroll
    for (int rr = 0; rr < 4; rr++) {
        int row = (tid >> 5)*4 + rr;
        float v = sA[row][lane];
        float mx = v;
#pragma unroll
        for (int o = 16; o; o >>= 1) mx = fmaxf(mx, __shfl_xor_sync(0xffffffffu, mx, o));
        float e = expf(v - mx);
        float smv = e;
#pragma unroll
        for (int o = 16; o; o >>= 1) smv += __shfl_xor_sync(0xffffffffu, smv, o);
        aw[row*32 + lane] = e / smv;
    }
}

// ---- K4c: spatial mix: out[c](n) = sum_d A[c,d]*(xr_d(n)+xr_d(-n))/2 -> fused[:,0:256] ----
__global__ void __launch_bounds__(256) k_mix() {
    int sl = blockIdx.x, h = blockIdx.y, b = blockIdx.z;
    size_t base = ((size_t)b*MIDC + h*32) * HW;
    __shared__ float sA[32][33];
    __shared__ float sS[32][65];
    int tid = threadIdx.x;
    const float* aw = g_attnW + (size_t)(b*HEADS + h)*1024;
#pragma unroll
    for (int q = 0; q < 4; q++) {
        int e = tid*4 + q;
        sA[e >> 5][e & 31] = aw[e];
    }
    int cm = (tid >> 4) * 2;
    int nm = (tid & 15) * 4;
    for (int n0 = 0; n0 < 512; n0 += 64) {
        int o = sl*512 + n0;
        int row = o >> 6;
        int grow = (64 - row) & 63;
        __syncthreads();
        for (int idx = tid; idx < 2048; idx += 256) {
            int cc = idx >> 6, nn = idx & 63;
            float a = __half2float(g_xr_h[base + (size_t)cc*HW + o + nn]);
            float bb = __half2float(g_xr_h[base + (size_t)cc*HW + grow*64 + ((64 - nn) & 63)]);
            sS[cc][nn] = 0.5f * (a + bb);
        }
        __syncthreads();
        float o0[4] = {}, o1[4] = {};
#pragma unroll
        for (int d = 0; d < 32; d++) {
            float a0 = sA[cm][d], a1 = sA[cm+1][d];
            float f0 = sS[d][nm], f1 = sS[d][nm+1], f2 = sS[d][nm+2], f3 = sS[d][nm+3];
            o0[0] += a0*f0; o0[1] += a0*f1; o0[2] += a0*f2; o0[3] += a0*f3;
            o1[0] += a1*f0; o1[1] += a1*f1; o1[2] += a1*f2; o1[3] += a1*f3;
        }
        __nv_bfloat162 q00 = __floats2bfloat162_rn(o0[0], o0[1]);
        __nv_bfloat162 q01 = __floats2bfloat162_rn(o0[2], o0[3]);
        __nv_bfloat162 q10 = __floats2bfloat162_rn(o1[0], o1[1]);
        __nv_bfloat162 q11 = __floats2bfloat162_rn(o1[2], o1[3]);
        uint2 pk0, pk1;
        pk0.x = *(uint32_t*)&q00; pk0.y = *(uint32_t*)&q01;
        pk1.x = *(uint32_t*)&q10; pk1.y = *(uint32_t*)&q11;
        size_t fb = ((size_t)b*INDIM + h*32) * HW;
        *(uint2*)&g_fused_bf[fb + (size_t)cm*HW + o + nm]     = pk0;
        *(uint2*)&g_fused_bf[fb + (size_t)(cm+1)*HW + o + nm] = pk1;
    }
}

// ---------------- launch ----------------
extern "C" void kernel_launch(void* const* d_in, const int* in_sizes, int n_in,
                              void* d_out, int out_size) {
    (void)in_sizes; (void)n_in; (void)out_size;
    const float* x        = (const float*)d_in[0];
    const float* reduce_w = (const float*)d_in[1];
    const float* reduce_b = (const float*)d_in[2];
    const float* dw_w     = (const float*)d_in[3];
    const float* dw_b     = (const float*)d_in[4];
    const float* bn_gamma = (const float*)d_in[5];
    const float* bn_beta  = (const float*)d_in[6];
    const float* bn_mean  = (const float*)d_in[7];
    const float* bn_var   = (const float*)d_in[8];
    const float* gate_w1  = (const float*)d_in[9];
    const float* gate_b1  = (const float*)d_in[10];
    const float* gate_w2  = (const float*)d_in[11];
    const float* gate_b2  = (const float*)d_in[12];
    const float* temp     = (const float*)d_in[13];
    const float* post_w   = (const float*)d_in[14];
    const float* post_b   = (const float*)d_in[15];
    float* out = (float*)d_out;

    cudaFuncSetAttribute((const void*)k_wmma_gemm<true,false>,
                         cudaFuncAttributeMaxDynamicSharedMemorySize, GEMM_SMEM);
    cudaFuncSetAttribute((const void*)k_wmma_gemm<false,true>,
                         cudaFuncAttributeMaxDynamicSharedMemorySize, GEMM_SMEM);

    __nv_bfloat16 *p_fbf, *p_wred, *p_wpost;
    cudaGetSymbolAddress((void**)&p_fbf,   g_fused_bf);
    cudaGetSymbolAddress((void**)&p_wred,  g_wred);
    cudaGetSymbolAddress((void**)&p_wpost, g_wpost);
    float* p_buf1;
    cudaGetSymbolAddress((void**)&p_buf1, g_buf1);

    // weight conversions
    k_cvt<<<(MIDC*INDIM/4 + 255)/256, 256>>>(reduce_w, p_wred, MIDC*INDIM);
    k_cvt<<<(INDIM*2*MIDC/4 + 255)/256, 256>>>(post_w, p_wpost, INDIM*2*MIDC);

    // reduce GEMM (x read fp32, converted in-stage)
    k_wmma_gemm<true,false><<<dim3(32, 2, BATCH), 256, GEMM_SMEM>>>(
        p_wred, x, reduce_b, nullptr, p_buf1, MIDC);

    // dw + BN + ReLU + stats + xr + fwdFFT + square + invFFT -> fwm (unscaled)
    k_dwfft<<<BATCH*MIDC, 256>>>(dw_w, dw_b, bn_gamma, bn_beta, bn_mean, bn_var);
    k_gate<<<BATCH, 256>>>(gate_w1, gate_b1, gate_w2, gate_b2);

    // spatial attention
    k_gram<<<dim3(8, HEADS, BATCH), 256>>>();
    k_soft<<<dim3(HEADS, BATCH), 256>>>(temp);
    k_mix<<<dim3(8, HEADS, BATCH), 256>>>();

    // post GEMM: gate scaling fused into B-stage for rows >= 256
    k_wmma_gemm<false,true><<<dim3(32, 4, BATCH), 256, GEMM_SMEM>>>(
        p_wpost, p_fbf, post_b, x, out, INDIM);
}

// round 7
// speedup vs baseline: 1.8251x; 1.8251x over previous
#include <cuda_runtime.h>
#include <cuda_bf16.h>
#include <cuda_fp16.h>
#include <mma.h>
#include <math.h>
#include <stdint.h>

using namespace nvcuda;

#define BATCH 16
#define INDIM 512
#define MIDC  256
#define HW    4096
#define HEADS 8

// ---------------- scratch (device globals; no allocation) ----------------
__device__ float  g_buf1[BATCH*MIDC*HW];    // reduce-GEMM output (pre-dw), fp32
__device__ __half g_xr_h[BATCH*MIDC*HW];    // xr (post dw+BN+ReLU), fp16, spatial
__device__ float  g_means[BATCH*MIDC];
__device__ float  g_nrm  [BATCH*MIDC];
__device__ float  g_gate [BATCH*MIDC];
__device__ float  g_gram_part[BATCH*HEADS*8*1024];
__device__ float  g_attnW[BATCH*HEADS*1024];
__device__ __nv_bfloat16 g_fused_bf[BATCH*INDIM*HW]; // [attn_out | fwm(unscaled)]
__device__ __nv_bfloat16 g_wred    [MIDC*INDIM];
__device__ __nv_bfloat16 g_wpost   [INDIM*2*MIDC];

// ================= wmma bf16 GEMM =================
#define AS_STRIDE 40
#define BS_STRIDE 136
#define CS_STRIDE 132
#define GEMM_SMEM (128*CS_STRIDE*4)

template<bool F32ACT, bool GATESCALE>
__global__ void __launch_bounds__(256)
k_wmma_gemm(const __nv_bfloat16* __restrict__ W,
            const void* __restrict__ actv,
            const float* __restrict__ bias,
            const float* __restrict__ resid,
            float* __restrict__ out,
            int Mtot) {
    extern __shared__ char sm[];
    __nv_bfloat16* As = (__nv_bfloat16*)sm;
    __nv_bfloat16* Bs = (__nv_bfloat16*)(sm + 128*AS_STRIDE*2);
    float*         Cs = (float*)sm;

    int tid = threadIdx.x;
    int w   = tid >> 5;
    int wm  = w & 3;
    int wn  = w >> 2;
    int nb = blockIdx.x * 128, mb = blockIdx.y * 128, b = blockIdx.z;

    const __nv_bfloat16* Ag = W + (size_t)mb * 512;
    const float*         Bg32 = (const float*)actv + (size_t)b * 512 * 4096 + nb;
    const __nv_bfloat16* Bg16 = (const __nv_bfloat16*)actv + (size_t)b * 512 * 4096 + nb;

    wmma::fragment<wmma::accumulator, 16, 16, 16, float> acc[2][4];
#pragma unroll
    for (int i = 0; i < 2; i++)
#pragma unroll
        for (int j = 0; j < 4; j++) wmma::fill_fragment(acc[i][j], 0.0f);

    for (int kc = 0; kc < 512; kc += 32) {
        __syncthreads();
#pragma unroll
        for (int t = 0; t < 2; t++) {
            int id = tid + t * 256;
            int r = id >> 2, c8 = (id & 3) * 8;
            uint4 v = *(const uint4*)(Ag + (size_t)r * 512 + kc + c8);
            *(uint4*)(As + r * AS_STRIDE + c8) = v;
        }
#pragma unroll
        for (int t = 0; t < 2; t++) {
            int id = tid + t * 256;
            int r = id >> 4, c8 = (id & 15) * 8;
            if (F32ACT) {
                float4 v0 = *(const float4*)(Bg32 + (size_t)(kc + r) * 4096 + c8);
                float4 v1 = *(const float4*)(Bg32 + (size_t)(kc + r) * 4096 + c8 + 4);
                __nv_bfloat162 p0 = __floats2bfloat162_rn(v0.x, v0.y);
                __nv_bfloat162 p1 = __floats2bfloat162_rn(v0.z, v0.w);
                __nv_bfloat162 p2 = __floats2bfloat162_rn(v1.x, v1.y);
                __nv_bfloat162 p3 = __floats2bfloat162_rn(v1.z, v1.w);
                uint4 pk;
                pk.x = *(uint32_t*)&p0; pk.y = *(uint32_t*)&p1;
                pk.z = *(uint32_t*)&p2; pk.w = *(uint32_t*)&p3;
                *(uint4*)(Bs + r * BS_STRIDE + c8) = pk;
            } else {
                uint4 v = *(const uint4*)(Bg16 + (size_t)(kc + r) * 4096 + c8);
                if (GATESCALE) {
                    int kr = kc + r;
                    if (kr >= 256) {
                        float gs = g_gate[b*MIDC + kr - 256];
                        __nv_bfloat162* p = (__nv_bfloat162*)&v;
#pragma unroll
                        for (int e = 0; e < 4; e++) {
                            float2 f = __bfloat1622float2(p[e]);
                            p[e] = __floats2bfloat162_rn(f.x * gs, f.y * gs);
                        }
                    }
                }
                *(uint4*)(Bs + r * BS_STRIDE + c8) = v;
            }
        }
        __syncthreads();
#pragma unroll
        for (int ks = 0; ks < 2; ks++) {
            wmma::fragment<wmma::matrix_a, 16, 16, 16, __nv_bfloat16, wmma::row_major> af[2];
            wmma::fragment<wmma::matrix_b, 16, 16, 16, __nv_bfloat16, wmma::row_major> bf[4];
#pragma unroll
            for (int i = 0; i < 2; i++)
                wmma::load_matrix_sync(af[i], As + (wm*32 + i*16) * AS_STRIDE + ks*16, AS_STRIDE);
#pragma unroll
            for (int j = 0; j < 4; j++)
                wmma::load_matrix_sync(bf[j], Bs + (ks*16) * BS_STRIDE + wn*64 + j*16, BS_STRIDE);
#pragma unroll
            for (int i = 0; i < 2; i++)
#pragma unroll
                for (int j = 0; j < 4; j++)
                    wmma::mma_sync(acc[i][j], af[i], bf[j], acc[i][j]);
        }
    }
    __syncthreads();
#pragma unroll
    for (int i = 0; i < 2; i++)
#pragma unroll
        for (int j = 0; j < 4; j++)
            wmma::store_matrix_sync(Cs + (wm*32 + i*16) * CS_STRIDE + wn*64 + j*16,
                                    acc[i][j], CS_STRIDE, wmma::mem_row_major);
    __syncthreads();
#pragma unroll
    for (int t = 0; t < 16; t++) {
        int id = tid + t * 256;
        int r = id >> 5, c = (id & 31) * 4;
        float bi = bias ? bias[mb + r] : 0.0f;
        float4 v = *(float4*)(Cs + r * CS_STRIDE + c);
        v.x += bi; v.y += bi; v.z += bi; v.w += bi;
        size_t off = ((size_t)b * Mtot + mb + r) * 4096 + nb + c;
        if (resid) {
            float4 rr = *(const float4*)(resid + off);
            v.x += rr.x; v.y += rr.y; v.z += rr.z; v.w += rr.w;
        }
        *(float4*)(out + off) = v;
    }
}

// ---------------- conversion (weights only) ----------------
__global__ void __launch_bounds__(256) k_cvt(const float* __restrict__ src,
                                             __nv_bfloat16* __restrict__ dst, int n) {
    int i = (blockIdx.x * 256 + threadIdx.x) * 4;
    if (i < n) {
        float4 v = *(const float4*)(src + i);
        __nv_bfloat162 p0 = __floats2bfloat162_rn(v.x, v.y);
        __nv_bfloat162 p1 = __floats2bfloat162_rn(v.z, v.w);
        uint2 pk;
        pk.x = *(uint32_t*)&p0; pk.y = *(uint32_t*)&p1;
        *(uint2*)(dst + i) = pk;
    }
}

// ================= radix-4 FFT (64-pt, 3 stages, in-place smem) =================
template<int Q, int M>
__device__ __forceinline__ void fft4s_fwd(float* Ar, float* Ai,
                                          const float* twr, const float* twi,
                                          int tid, bool col) {
#pragma unroll
    for (int i = 0; i < 4; i++) {
        int t = tid + (i << 8);
        int line = t >> 4;
        int j16 = t & 15;
        int blk = j16 / Q, j = j16 - blk * Q;
        int base = blk * (4 * Q) + j;
        int p0 = base, p1 = base + Q, p2 = base + 2*Q, p3 = base + 3*Q;
        int a0 = col ? p0*65 + line : line*65 + p0;
        int a1 = col ? p1*65 + line : line*65 + p1;
        int a2 = col ? p2*65 + line : line*65 + p2;
        int a3 = col ? p3*65 + line : line*65 + p3;
        float x0r=Ar[a0], x0i=Ai[a0], x1r=Ar[a1], x1i=Ai[a1];
        float x2r=Ar[a2], x2i=Ai[a2], x3r=Ar[a3], x3i=Ai[a3];
        float t0r=x0r+x2r, t0i=x0i+x2i;
        float t1r=x0r-x2r, t1i=x0i-x2i;
        float t2r=x1r+x3r, t2i=x1i+x3i;
        float t3r=x1i-x3i, t3i=x3r-x1r;          // -i*(x1-x3)
        Ar[a0]=t0r+t2r; Ai[a0]=t0i+t2i;
        float w1r=twr[M*j],   w1i=twi[M*j];
        float w2r=twr[2*M*j], w2i=twi[2*M*j];
        float w3r=twr[3*M*j], w3i=twi[3*M*j];
        float u1r=t1r+t3r, u1i=t1i+t3i;
        Ar[a1]=u1r*w1r-u1i*w1i; Ai[a1]=u1r*w1i+u1i*w1r;
        float u2r=t0r-t2r, u2i=t0i-t2i;
        Ar[a2]=u2r*w2r-u2i*w2i; Ai[a2]=u2r*w2i+u2i*w2r;
        float u3r=t1r-t3r, u3i=t1i-t3i;
        Ar[a3]=u3r*w3r-u3i*w3i; Ai[a3]=u3r*w3i+u3i*w3r;
    }
}

template<int Q, int M>
__device__ __forceinline__ void fft4s_inv(float* Ar, float* Ai,
                                          const float* twr, const float* twi,
                                          int tid, bool col) {
#pragma unroll
    for (int i = 0; i < 4; i++) {
        int t = tid + (i << 8);
        int line = t >> 4;
        int j16 = t & 15;
        int blk = j16 / Q, j = j16 - blk * Q;
        int base = blk * (4 * Q) + j;
        int p0 = base, p1 = base + Q, p2 = base + 2*Q, p3 = base + 3*Q;
        int a0 = col ? p0*65 + line : line*65 + p0;
        int a1 = col ? p1*65 + line : line*65 + p1;
        int a2 = col ? p2*65 + line : line*65 + p2;
        int a3 = col ? p3*65 + line : line*65 + p3;
        float u0r=Ar[a0], u0i=Ai[a0];
        float v1r=Ar[a1], v1i=Ai[a1];
        float v2r=Ar[a2], v2i=Ai[a2];
        float v3r=Ar[a3], v3i=Ai[a3];
        float w1r=twr[M*j],   w1i=twi[M*j];
        float w2r=twr[2*M*j], w2i=twi[2*M*j];
        float w3r=twr[3*M*j], w3i=twi[3*M*j];
        float b1r=v1r*w1r+v1i*w1i, b1i=v1i*w1r-v1r*w1i;
        float b2r=v2r*w2r+v2i*w2i, b2i=v2i*w2r-v2r*w2i;
        float b3r=v3r*w3r+v3i*w3i, b3i=v3i*w3r-v3r*w3i;
        float s0r=u0r+b2r, s0i=u0i+b2i;
        float s1r=u0r-b2r, s1i=u0i-b2i;
        float s2r=b1r+b3r, s2i=b1i+b3i;
        float s3r=b3i-b1i, s3i=b1r-b3r;          // +i*(b1-b3)
        Ar[a0]=s0r+s2r; Ai[a0]=s0i+s2i;
        Ar[a1]=s1r+s3r; Ai[a1]=s1i+s3i;
        Ar[a2]=s0r-s2r; Ai[a2]=s0i-s2i;
        Ar[a3]=s1r-s3r; Ai[a3]=s1i-s3i;
    }
}

__device__ __forceinline__ void fft4_fwd_dim(float* Ar, float* Ai,
                                             const float* twr, const float* twi,
                                             int tid, bool col) {
    fft4s_fwd<16,1>(Ar, Ai, twr, twi, tid, col); __syncthreads();
    fft4s_fwd<4,4> (Ar, Ai, twr, twi, tid, col); __syncthreads();
    fft4s_fwd<1,16>(Ar, Ai, twr, twi, tid, col); __syncthreads();
}

__device__ __forceinline__ void fft4_inv_dim(float* Ar, float* Ai,
                                             const float* twr, const float* twi,
                                             int tid, bool col) {
    fft4s_inv<1,16>(Ar, Ai, twr, twi, tid, col); __syncthreads();
    fft4s_inv<4,4> (Ar, Ai, twr, twi, tid, col); __syncthreads();
    fft4s_inv<16,1>(Ar, Ai, twr, twi, tid, col); __syncthreads();
}

__device__ __forceinline__ void fft_load_tw64(float* twr, float* twi, int tid) {
    if (tid < 64) {
        float s, c;
        sincosf(-6.28318530717958647692f * (float)tid * (1.0f/64.0f), &s, &c);
        twr[tid] = c; twi[tid] = s;
    }
}

// ---------------- K2: lean depthwise 3x3 + BN + ReLU + stats -> xr fp16 ----------
__global__ void __launch_bounds__(256) k_dw(const float* __restrict__ dww,
                                            const float* __restrict__ dwb,
                                            const float* __restrict__ gamma,
                                            const float* __restrict__ beta,
                                            const float* __restrict__ mean,
                                            const float* __restrict__ var) {
    int plane = blockIdx.x;
    int c = plane & (MIDC-1);
    __shared__ float tile[66*66];
    __shared__ float rs[8], rq[8];
    const float* src = g_buf1 + (size_t)plane*HW;
    for (int idx = threadIdx.x; idx < 66*66; idx += 256) {
        int r = idx / 66, cc = idx - r*66;
        int y = r - 1, x = cc - 1;
        float v = 0.f;
        if ((unsigned)y < 64u && (unsigned)x < 64u) v = src[y*64 + x];
        tile[idx] = v;
    }
    __syncthreads();
    float w0 = dww[c*9+0], w1 = dww[c*9+1], w2 = dww[c*9+2];
    float w3 = dww[c*9+3], w4 = dww[c*9+4], w5 = dww[c*9+5];
    float w6 = dww[c*9+6], w7 = dww[c*9+7], w8 = dww[c*9+8];
    float scale = gamma[c] * rsqrtf(var[c] + 1e-5f);
    float shift = beta[c] - mean[c]*scale;
    float bia = dwb[c];
    float s = 0.f, sq = 0.f;
    __half* dst = g_xr_h + (size_t)plane*HW;
#pragma unroll
    for (int i = 0; i < 16; i++) {
        int p = threadIdx.x + i*256;
        int py = p >> 6, px = p & 63;
        const float* t0 = &tile[py*66 + px];
        float acc = t0[0]*w0 + t0[1]*w1 + t0[2]*w2
                  + t0[66]*w3 + t0[67]*w4 + t0[68]*w5
                  + t0[132]*w6 + t0[133]*w7 + t0[134]*w8;
        acc = fmaxf((acc + bia)*scale + shift, 0.f);
        dst[p] = __float2half(acc);
        s += acc; sq += acc*acc;
    }
#pragma unroll
    for (int o = 16; o; o >>= 1) {
        s  += __shfl_xor_sync(0xffffffffu, s,  o);
        sq += __shfl_xor_sync(0xffffffffu, sq, o);
    }
    int wid = threadIdx.x >> 5;
    if ((threadIdx.x & 31) == 0) { rs[wid] = s; rq[wid] = sq; }
    __syncthreads();
    if (threadIdx.x == 0) {
        float ts = 0.f, tq = 0.f;
#pragma unroll
        for (int w = 0; w < 8; w++) { ts += rs[w]; tq += rq[w]; }
        g_means[plane] = ts * (1.f/4096.f);
        g_nrm[plane]   = sqrtf(tq);   // Parseval
    }
}

// ---- K7: packed-real fwm, 2 planes/CTA: z=xr0+i*xr1, W=F1^2+i*F2^2, one inverse ----
__global__ void __launch_bounds__(256) k_fwm2() {
    __shared__ float Ar[64*65], Ai[64*65], twr[64], twi[64];
    __shared__ int mate[64];
    int pp = blockIdx.x;                // pair id: planes 2pp, 2pp+1 (same batch)
    int plane0 = pp * 2;
    int b = plane0 >> 8, c0 = plane0 & (MIDC-1);
    int tid = threadIdx.x;
    const __half* x0 = g_xr_h + (size_t)plane0*HW;
    const __half* x1 = x0 + HW;
#pragma unroll
    for (int i = 0; i < 16; i++) {
        int p = tid + i*256; int r = p >> 6, cc = p & 63;
        Ar[r*65+cc] = __half2float(x0[p]);
        Ai[r*65+cc] = __half2float(x1[p]);
    }
    fft_load_tw64(twr, twi, tid);
    if (tid < 64) {
        int rv = ((tid & 3) << 4) | (tid & 12) | (tid >> 4);   // rev4
        int nk = (64 - rv) & 63;
        mate[tid] = ((nk & 3) << 4) | (nk & 12) | (nk >> 4);
    }
    __syncthreads();
    // forward DFT (unscaled), digit-reversed both dims
    fft4_fwd_dim(Ar, Ai, twr, twi, tid, false);
    fft4_fwd_dim(Ar, Ai, twr, twi, tid, true);
    // Hermitian unpack + square + repack. Pair-ownership: thread with flat p <= flat m
    // writes both W(p) and W(m) = conj(W1) + i*conj(W2). Disjoint pairs -> no races.
#pragma unroll
    for (int i = 0; i < 16; i++) {
        int p = tid + i*256; int r = p >> 6, cc = p & 63;
        int mr = mate[r], mc = mate[cc];
        int fm = mr*64 + mc;
        if (p <= fm) {
            int a  = r*65 + cc;
            int am = mr*65 + mc;
            float zpr = Ar[a],  zpi = Ai[a];
            float zmr = Ar[am], zmi = Ai[am];
            float f1r = 0.5f*(zpr + zmr), f1i = 0.5f*(zpi - zmi);
            float f2r = 0.5f*(zpi + zmi), f2i = 0.5f*(zmr - zpr);
            float W1r = f1r*f1r - f1i*f1i, W1i = 2.f*f1r*f1i;
            float W2r = f2r*f2r - f2i*f2i, W2i = 2.f*f2r*f2i;
            Ar[a]  = W1r - W2i;  Ai[a]  = W1i + W2r;
            Ar[am] = W1r + W2i;  Ai[am] = W2r - W1i;
        }
    }
    __syncthreads();
    // inverse DFT (unscaled): result = fwm0_u + i*fwm1_u
    fft4_inv_dim(Ar, Ai, twr, twi, tid, false);
    fft4_inv_dim(Ar, Ai, twr, twi, tid, true);
    __nv_bfloat16* dst0 = g_fused_bf + ((size_t)b*INDIM + MIDC + c0)*HW;
    __nv_bfloat16* dst1 = dst0 + HW;
#pragma unroll
    for (int i = 0; i < 16; i++) {
        int p = tid + i*256; int r = p >> 6, cc = p & 63;
        int a = r*65 + cc;
        dst0[p] = __float2bfloat16(Ar[a] * (1.f/262144.f));
        dst1[p] = __float2bfloat16(Ai[a] * (1.f/262144.f));
    }
}

// ---------------- K3: SE gate MLP ----------------
__global__ void __launch_bounds__(256) k_gate(const float* __restrict__ w1,
                                              const float* __restrict__ b1,
                                              const float* __restrict__ w2,
                                              const float* __restrict__ b2) {
    int b = blockIdx.x;
    __shared__ float sm[MIDC];
    __shared__ float sh[32];
    int tid = threadIdx.x;
    sm[tid] = g_means[b*MIDC + tid];
    __syncthreads();
    if (tid < 32) {
        float a = b1[tid];
        const float* wr = w1 + tid*MIDC;
        for (int c2 = 0; c2 < MIDC; c2++) a += wr[c2]*sm[c2];
        sh[tid] = fmaxf(a, 0.f);
    }
    __syncthreads();
    float a = b2[tid];
    const float* wr = w2 + tid*32;
#pragma unroll
    for (int j = 0; j < 32; j++) a += wr[j]*sh[j];
    g_gate[b*MIDC + tid] = 1.f / (1.f + expf(-a));
}

// ---------------- K4a: spatial Gram[c,d] = sum_n xr_c(n) * xr_d(-n) ----------------
__global__ void __launch_bounds__(256) k_gram() {
    int sl = blockIdx.x, h = blockIdx.y, b = blockIdx.z;
    size_t base = ((size_t)b*MIDC + h*32) * HW;
    __shared__ float sX[32][65], sY[32][65];
    __shared__ float sRed[4][1024];
    int tid = threadIdx.x;
    int nsub = tid >> 6;
    int tt = tid & 63;
    int c0 = (tt >> 3) * 4, d0 = (tt & 7) * 4;
    float acc[4][4] = {};
    for (int n0 = 0; n0 < 512; n0 += 64) {
        int o = sl*512 + n0;
        int row = o >> 6;
        int grow = (64 - row) & 63;
        __syncthreads();
        for (int idx = tid; idx < 2048; idx += 256) {
            int cc = idx >> 6, nn = idx & 63;
            sX[cc][nn] = __half2float(g_xr_h[base + (size_t)cc*HW + o + nn]);
            sY[cc][(64 - nn) & 63] = __half2float(g_xr_h[base + (size_t)cc*HW + grow*64 + nn]);
        }
        __syncthreads();
        int nlo = nsub * 16;
#pragma unroll 4
        for (int nn = nlo; nn < nlo + 16; nn++) {
            float rc[4], rd[4];
#pragma unroll
            for (int i = 0; i < 4; i++) rc[i] = sX[c0+i][nn];
#pragma unroll
            for (int j = 0; j < 4; j++) rd[j] = sY[d0+j][nn];
#pragma unroll
            for (int i = 0; i < 4; i++)
#pragma unroll
                for (int j = 0; j < 4; j++)
                    acc[i][j] += rc[i]*rd[j];
        }
    }
#pragma unroll
    for (int i = 0; i < 4; i++)
#pragma unroll
        for (int j = 0; j < 4; j++)
            sRed[nsub][tt*16 + i*4 + j] = acc[i][j];
    __syncthreads();
    float* part = g_gram_part + ((size_t)(b*HEADS + h)*8 + sl)*1024;
#pragma unroll
    for (int q = 0; q < 4; q++) {
        int e = tid*4 + q;
        int te = e >> 4, sub = e & 15;
        int i = sub >> 2, j = sub & 3;
        int c = (te >> 3)*4 + i, d = (te & 7)*4 + j;
        part[c*32 + d] = sRed[0][e] + sRed[1][e] + sRed[2][e] + sRed[3][e];
    }
}

// ---------------- K4b: reduce partials + normalize + softmax ----------------
__global__ void __launch_bounds__(256) k_soft(const float* __restrict__ temp) {
    int h = blockIdx.x, b = blockIdx.y;
    __shared__ float sA[32][33], sN[32];
    int tid = threadIdx.x;
    if (tid < 32) sN[tid] = fmaxf(g_nrm[b*MIDC + h*32 + tid], 1e-12f);
    __syncthreads();
    float tK = temp[h];
    const float* part = g_gram_part + (size_t)(b*HEADS + h)*8*1024;
#pragma unroll
    for (int q = 0; q < 4; q++) {
        int e = tid*4 + q;
        int c = e >> 5, d = e & 31;
        float v = 0.f;
#pragma unroll
        for (int s = 0; s < 8; s++) v += part[s*1024 + e];
        sA[c][d] = v * tK / (sN[c] * sN[d]);
    }
    __syncthreads();
    int lane = tid & 31;
    float* aw = g_attnW + (size_t)(b*HEADS + h)*1024;
#pragma unroll
    for (int rr = 0; rr < 4; rr++) {
        int row = (tid >> 5)*4 + rr;
        float v = sA[row][lane];
        float mx = v;
#pragma unroll
        for (int o = 16; o; o >>= 1) mx = fmaxf(mx, __shfl_xor_sync(0xffffffffu, mx, o));
        float e = expf(v - mx);
        float smv = e;
#pragma unroll
        for (int o = 16; o; o >>= 1) smv += __shfl_xor_sync(0xffffffffu, smv, o);
        aw[row*32 + lane] = e / smv;
    }
}

// ---- K4c: spatial mix: out[c](n) = sum_d A[c,d]*(xr_d(n)+xr_d(-n))/2 -> fused[:,0:256] ----
__global__ void __launch_bounds__(256) k_mix() {
    int sl = blockIdx.x, h = blockIdx.y, b = blockIdx.z;
    size_t base = ((size_t)b*MIDC + h*32) * HW;
    __shared__ float sA[32][33];
    __shared__ float sS[32][65];
    int tid = threadIdx.x;
    const float* aw = g_attnW + (size_t)(b*HEADS + h)*1024;
#pragma unroll
    for (int q = 0; q < 4; q++) {
        int e = tid*4 + q;
        sA[e >> 5][e & 31] = aw[e];
    }
    int cm = (tid >> 4) * 2;
    int nm = (tid & 15) * 4;
    for (int n0 = 0; n0 < 512; n0 += 64) {
        int o = sl*512 + n0;
        int row = o >> 6;
        int grow = (64 - row) & 63;
        __syncthreads();
        for (int idx = tid; idx < 2048; idx += 256) {
            int cc = idx >> 6, nn = idx & 63;
            float a = __half2float(g_xr_h[base + (size_t)cc*HW + o + nn]);
            float bb = __half2float(g_xr_h[base + (size_t)cc*HW + grow*64 + ((64 - nn) & 63)]);
            sS[cc][nn] = 0.5f * (a + bb);
        }
        __syncthreads();
        float o0[4] = {}, o1[4] = {};
#pragma unroll
        for (int d = 0; d < 32; d++) {
            float a0 = sA[cm][d], a1 = sA[cm+1][d];
            float f0 = sS[d][nm], f1 = sS[d][nm+1], f2 = sS[d][nm+2], f3 = sS[d][nm+3];
            o0[0] += a0*f0; o0[1] += a0*f1; o0[2] += a0*f2; o0[3] += a0*f3;
            o1[0] += a1*f0; o1[1] += a1*f1; o1[2] += a1*f2; o1[3] += a1*f3;
        }
        __nv_bfloat162 q00 = __floats2bfloat162_rn(o0[0], o0[1]);
        __nv_bfloat162 q01 = __floats2bfloat162_rn(o0[2], o0[3]);
        __nv_bfloat162 q10 = __floats2bfloat162_rn(o1[0], o1[1]);
        __nv_bfloat162 q11 = __floats2bfloat162_rn(o1[2], o1[3]);
        uint2 pk0, pk1;
        pk0.x = *(uint32_t*)&q00; pk0.y = *(uint32_t*)&q01;
        pk1.x = *(uint32_t*)&q10; pk1.y = *(uint32_t*)&q11;
        size_t fb = ((size_t)b*INDIM + h*32) * HW;
        *(uint2*)&g_fused_bf[fb + (size_t)cm*HW + o + nm]     = pk0;
        *(uint2*)&g_fused_bf[fb + (size_t)(cm+1)*HW + o + nm] = pk1;
    }
}

// ---------------- launch ----------------
extern "C" void kernel_launch(void* const* d_in, const int* in_sizes, int n_in,
                              void* d_out, int out_size) {
    (void)in_sizes; (void)n_in; (void)out_size;
    const float* x        = (const float*)d_in[0];
    const float* reduce_w = (const float*)d_in[1];
    const float* reduce_b = (const float*)d_in[2];
    const float* dw_w     = (const float*)d_in[3];
    const float* dw_b     = (const float*)d_in[4];
    const float* bn_gamma = (const float*)d_in[5];
    const float* bn_beta  = (const float*)d_in[6];
    const float* bn_mean  = (const float*)d_in[7];
    const float* bn_var   = (const float*)d_in[8];
    const float* gate_w1  = (const float*)d_in[9];
    const float* gate_b1  = (const float*)d_in[10];
    const float* gate_w2  = (const float*)d_in[11];
    const float* gate_b2  = (const float*)d_in[12];
    const float* temp     = (const float*)d_in[13];
    const float* post_w   = (const float*)d_in[14];
    const float* post_b   = (const float*)d_in[15];
    float* out = (float*)d_out;

    cudaFuncSetAttribute((const void*)k_wmma_gemm<true,false>,
                         cudaFuncAttributeMaxDynamicSharedMemorySize, GEMM_SMEM);
    cudaFuncSetAttribute((const void*)k_wmma_gemm<false,true>,
                         cudaFuncAttributeMaxDynamicSharedMemorySize, GEMM_SMEM);

    __nv_bfloat16 *p_fbf, *p_wred, *p_wpost;
    cudaGetSymbolAddress((void**)&p_fbf,   g_fused_bf);
    cudaGetSymbolAddress((void**)&p_wred,  g_wred);
    cudaGetSymbolAddress((void**)&p_wpost, g_wpost);
    float* p_buf1;
    cudaGetSymbolAddress((void**)&p_buf1, g_buf1);

    // weight conversions
    k_cvt<<<(MIDC*INDIM/4 + 255)/256, 256>>>(reduce_w, p_wred, MIDC*INDIM);
    k_cvt<<<(INDIM*2*MIDC/4 + 255)/256, 256>>>(post_w, p_wpost, INDIM*2*MIDC);

    // reduce GEMM (x read fp32, converted in-stage)
    k_wmma_gemm<true,false><<<dim3(32, 2, BATCH), 256, GEMM_SMEM>>>(
        p_wred, x, reduce_b, nullptr, p_buf1, MIDC);

    // lean dw + BN + ReLU + stats -> xr fp16
    k_dw<<<BATCH*MIDC, 256>>>(dw_w, dw_b, bn_gamma, bn_beta, bn_mean, bn_var);
    k_gate<<<BATCH, 256>>>(gate_w1, gate_b1, gate_w2, gate_b2);

    // packed-real fwm (2 planes per CTA)
    k_fwm2<<<BATCH*MIDC/2, 256>>>();

    // spatial attention
    k_gram<<<dim3(8, HEADS, BATCH), 256>>>();
    k_soft<<<dim3(HEADS, BATCH), 256>>>(temp);
    k_mix<<<dim3(8, HEADS, BATCH), 256>>>();

    // post GEMM: gate scaling fused into B-stage for rows >= 256
    k_wmma_gemm<false,true><<<dim3(32, 4, BATCH), 256, GEMM_SMEM>>>(
        p_wpost, p_fbf, post_b, x, out, INDIM);
}

// round 8
// speedup vs baseline: 2.1214x; 1.1624x over previous
#include <cuda_runtime.h>
#include <cuda_bf16.h>
#include <cuda_fp16.h>
#include <mma.h>
#include <math.h>
#include <stdint.h>

using namespace nvcuda;

#define BATCH 16
#define INDIM 512
#define MIDC  256
#define HW    4096
#define HEADS 8

// ---------------- scratch (device globals; no allocation) ----------------
__device__ float  g_buf1[BATCH*MIDC*HW];    // reduce-GEMM output (pre-dw), fp32
__device__ __half g_xr_h[BATCH*MIDC*HW];    // xr (post dw+BN+ReLU), fp16, spatial
__device__ float  g_means[BATCH*MIDC];
__device__ float  g_nrm  [BATCH*MIDC];
__device__ float  g_gate [BATCH*MIDC];
__device__ float  g_gram_part[BATCH*HEADS*8*1024];
__device__ float  g_attnW[BATCH*HEADS*1024];
__device__ __nv_bfloat16 g_fused_bf[BATCH*INDIM*HW]; // [attn_out | gated fwm]
__device__ __nv_bfloat16 g_wred    [MIDC*INDIM];
__device__ __nv_bfloat16 g_wpost   [INDIM*2*MIDC];

// ================= GEMM common =================
#define AS_STRIDE 40
#define BS_STRIDE 136
#define CS_STRIDE 132
#define GEMM_SMEM (128*CS_STRIDE*4)

__device__ __forceinline__ void cp16(void* sdst, const void* gsrc) {
    uint32_t a = (uint32_t)__cvta_generic_to_shared(sdst);
    asm volatile("cp.async.cg.shared.global [%0], [%1], 16;\n" :: "r"(a), "l"(gsrc));
}
#define CP_COMMIT() asm volatile("cp.async.commit_group;\n" ::: "memory")
#define CP_WAIT(n)  asm volatile("cp.async.wait_group %0;\n" :: "n"(n) : "memory")

// ---------------- reduce GEMM: fp32 act, single-buffered (proven) ----------------
__global__ void __launch_bounds__(256)
k_gemm_f32(const __nv_bfloat16* __restrict__ W,
           const float* __restrict__ act,
           const float* __restrict__ bias,
           float* __restrict__ out,
           int Mtot) {
    extern __shared__ char sm[];
    __nv_bfloat16* As = (__nv_bfloat16*)sm;
    __nv_bfloat16* Bs = (__nv_bfloat16*)(sm + 128*AS_STRIDE*2);
    float*         Cs = (float*)sm;

    int tid = threadIdx.x;
    int w   = tid >> 5;
    int wm  = w & 3;
    int wn  = w >> 2;
    int nb = blockIdx.x * 128, mb = blockIdx.y * 128, b = blockIdx.z;

    const __nv_bfloat16* Ag = W + (size_t)mb * 512;
    const float* Bg = act + (size_t)b * 512 * 4096 + nb;

    wmma::fragment<wmma::accumulator, 16, 16, 16, float> acc[2][4];
#pragma unroll
    for (int i = 0; i < 2; i++)
#pragma unroll
        for (int j = 0; j < 4; j++) wmma::fill_fragment(acc[i][j], 0.0f);

    for (int kc = 0; kc < 512; kc += 32) {
        __syncthreads();
#pragma unroll
        for (int t = 0; t < 2; t++) {
            int id = tid + t * 256;
            int r = id >> 2, c8 = (id & 3) * 8;
            uint4 v = *(const uint4*)(Ag + (size_t)r * 512 + kc + c8);
            *(uint4*)(As + r * AS_STRIDE + c8) = v;
        }
#pragma unroll
        for (int t = 0; t < 2; t++) {
            int id = tid + t * 256;
            int r = id >> 4, c8 = (id & 15) * 8;
            float4 v0 = *(const float4*)(Bg + (size_t)(kc + r) * 4096 + c8);
            float4 v1 = *(const float4*)(Bg + (size_t)(kc + r) * 4096 + c8 + 4);
            __nv_bfloat162 p0 = __floats2bfloat162_rn(v0.x, v0.y);
            __nv_bfloat162 p1 = __floats2bfloat162_rn(v0.z, v0.w);
            __nv_bfloat162 p2 = __floats2bfloat162_rn(v1.x, v1.y);
            __nv_bfloat162 p3 = __floats2bfloat162_rn(v1.z, v1.w);
            uint4 pk;
            pk.x = *(uint32_t*)&p0; pk.y = *(uint32_t*)&p1;
            pk.z = *(uint32_t*)&p2; pk.w = *(uint32_t*)&p3;
            *(uint4*)(Bs + r * BS_STRIDE + c8) = pk;
        }
        __syncthreads();
#pragma unroll
        for (int ks = 0; ks < 2; ks++) {
            wmma::fragment<wmma::matrix_a, 16, 16, 16, __nv_bfloat16, wmma::row_major> af[2];
            wmma::fragment<wmma::matrix_b, 16, 16, 16, __nv_bfloat16, wmma::row_major> bf[4];
#pragma unroll
            for (int i = 0; i < 2; i++)
                wmma::load_matrix_sync(af[i], As + (wm*32 + i*16) * AS_STRIDE + ks*16, AS_STRIDE);
#pragma unroll
            for (int j = 0; j < 4; j++)
                wmma::load_matrix_sync(bf[j], Bs + (ks*16) * BS_STRIDE + wn*64 + j*16, BS_STRIDE);
#pragma unroll
            for (int i = 0; i < 2; i++)
#pragma unroll
                for (int j = 0; j < 4; j++)
                    wmma::mma_sync(acc[i][j], af[i], bf[j], acc[i][j]);
        }
    }
    __syncthreads();
#pragma unroll
    for (int i = 0; i < 2; i++)
#pragma unroll
        for (int j = 0; j < 4; j++)
            wmma::store_matrix_sync(Cs + (wm*32 + i*16) * CS_STRIDE + wn*64 + j*16,
                                    acc[i][j], CS_STRIDE, wmma::mem_row_major);
    __syncthreads();
#pragma unroll
    for (int t = 0; t < 16; t++) {
        int id = tid + t * 256;
        int r = id >> 5, c = (id & 31) * 4;
        float bi = bias[mb + r];
        float4 v = *(float4*)(Cs + r * CS_STRIDE + c);
        v.x += bi; v.y += bi; v.z += bi; v.w += bi;
        size_t off = ((size_t)b * Mtot + mb + r) * 4096 + nb + c;
        *(float4*)(out + off) = v;
    }
}

// ---------------- post GEMM: bf16 act, cp.async 2-stage pipeline ----------------
__global__ void __launch_bounds__(256)
k_gemm_pipe(const __nv_bfloat16* __restrict__ W,
            const __nv_bfloat16* __restrict__ act,
            const float* __restrict__ bias,
            const float* __restrict__ resid,
            float* __restrict__ out,
            int Mtot) {
    extern __shared__ char sm[];
    __nv_bfloat16* As0 = (__nv_bfloat16*)sm;                        // 2 x 128*AS_STRIDE
    __nv_bfloat16* Bs0 = (__nv_bfloat16*)(sm + 2*128*AS_STRIDE*2);  // 2 x 32*BS_STRIDE
    float*         Cs  = (float*)sm;

    int tid = threadIdx.x;
    int w   = tid >> 5;
    int wm  = w & 3;
    int wn  = w >> 2;
    int nb = blockIdx.x * 128, mb = blockIdx.y * 128, b = blockIdx.z;

    const __nv_bfloat16* Ag = W + (size_t)mb * 512;
    const __nv_bfloat16* Bg = act + (size_t)b * 512 * 4096 + nb;

    // per-thread copy coordinates
    int ar0 = tid >> 2,  ac0 = (tid & 3) * 8;
    int br0 = tid >> 4,  bc0 = (tid & 15) * 8;

    wmma::fragment<wmma::accumulator, 16, 16, 16, float> acc[2][4];
#pragma unroll
    for (int i = 0; i < 2; i++)
#pragma unroll
        for (int j = 0; j < 4; j++) wmma::fill_fragment(acc[i][j], 0.0f);

    // prefetch chunk 0 into stage 0
    {
        __nv_bfloat16* As = As0;
        __nv_bfloat16* Bs = Bs0;
#pragma unroll
        for (int t = 0; t < 2; t++) {
            int r = ar0 + t*64;
            cp16(As + r*AS_STRIDE + ac0, Ag + (size_t)r*512 + ac0);
        }
#pragma unroll
        for (int t = 0; t < 2; t++) {
            int r = br0 + t*16;
            cp16(Bs + r*BS_STRIDE + bc0, Bg + (size_t)r*4096 + bc0);
        }
        CP_COMMIT();
    }

    for (int it = 0; it < 16; it++) {
        int cur = it & 1;
        if (it < 15) {
            int kc = (it + 1) * 32;
            __nv_bfloat16* As = As0 + (cur^1)*128*AS_STRIDE;
            __nv_bfloat16* Bs = Bs0 + (cur^1)*32*BS_STRIDE;
#pragma unroll
            for (int t = 0; t < 2; t++) {
                int r = ar0 + t*64;
                cp16(As + r*AS_STRIDE + ac0, Ag + (size_t)r*512 + kc + ac0);
            }
#pragma unroll
            for (int t = 0; t < 2; t++) {
                int r = br0 + t*16;
                cp16(Bs + r*BS_STRIDE + bc0, Bg + (size_t)(kc + r)*4096 + bc0);
            }
            CP_COMMIT();
            CP_WAIT(1);
        } else {
            CP_WAIT(0);
        }
        __syncthreads();
        const __nv_bfloat16* As = As0 + cur*128*AS_STRIDE;
        const __nv_bfloat16* Bs = Bs0 + cur*32*BS_STRIDE;
#pragma unroll
        for (int ks = 0; ks < 2; ks++) {
            wmma::fragment<wmma::matrix_a, 16, 16, 16, __nv_bfloat16, wmma::row_major> af[2];
            wmma::fragment<wmma::matrix_b, 16, 16, 16, __nv_bfloat16, wmma::row_major> bf[4];
#pragma unroll
            for (int i = 0; i < 2; i++)
                wmma::load_matrix_sync(af[i], As + (wm*32 + i*16) * AS_STRIDE + ks*16, AS_STRIDE);
#pragma unroll
            for (int j = 0; j < 4; j++)
                wmma::load_matrix_sync(bf[j], Bs + (ks*16) * BS_STRIDE + wn*64 + j*16, BS_STRIDE);
#pragma unroll
            for (int i = 0; i < 2; i++)
#pragma unroll
                for (int j = 0; j < 4; j++)
                    wmma::mma_sync(acc[i][j], af[i], bf[j], acc[i][j]);
        }
        __syncthreads();   // buffer cur free for prefetch at it+1
    }
    // epilogue via smem staging (Cs overlaps As/Bs; all MMA consumption done)
#pragma unroll
    for (int i = 0; i < 2; i++)
#pragma unroll
        for (int j = 0; j < 4; j++)
            wmma::store_matrix_sync(Cs + (wm*32 + i*16) * CS_STRIDE + wn*64 + j*16,
                                    acc[i][j], CS_STRIDE, wmma::mem_row_major);
    __syncthreads();
#pragma unroll
    for (int t = 0; t < 16; t++) {
        int id = tid + t * 256;
        int r = id >> 5, c = (id & 31) * 4;
        float bi = bias[mb + r];
        float4 v = *(float4*)(Cs + r * CS_STRIDE + c);
        v.x += bi; v.y += bi; v.z += bi; v.w += bi;
        size_t off = ((size_t)b * Mtot + mb + r) * 4096 + nb + c;
        float4 rr = *(const float4*)(resid + off);
        v.x += rr.x; v.y += rr.y; v.z += rr.z; v.w += rr.w;
        *(float4*)(out + off) = v;
    }
}

// ---------------- conversion (weights only) ----------------
__global__ void __launch_bounds__(256) k_cvt(const float* __restrict__ src,
                                             __nv_bfloat16* __restrict__ dst, int n) {
    int i = (blockIdx.x * 256 + threadIdx.x) * 4;
    if (i < n) {
        float4 v = *(const float4*)(src + i);
        __nv_bfloat162 p0 = __floats2bfloat162_rn(v.x, v.y);
        __nv_bfloat162 p1 = __floats2bfloat162_rn(v.z, v.w);
        uint2 pk;
        pk.x = *(uint32_t*)&p0; pk.y = *(uint32_t*)&p1;
        *(uint2*)(dst + i) = pk;
    }
}

// ================= radix-8 FFT (64-pt, 2 stages/dim, in-place smem) =================
// Forward: DIF, natural -> octal-digit-reversed. Inverse: DIT, reversed -> natural
// (unscaled). tw[k] = e^{-2*pi*i*k/64}. Conflict-free mapping: line varies fastest.
template<int Q, int M, bool INV>
__device__ __forceinline__ void fft8s(float* Ar, float* Ai,
                                      const float* twr, const float* twi,
                                      int tid, bool col) {
    const float S2 = 0.70710678118654752440f;
#pragma unroll
    for (int i = 0; i < 2; i++) {
        int bf = tid + (i << 8);      // 0..511
        int line = bf & 63;
        int j8 = bf >> 6;             // 0..7
        int blk = j8 / Q, j = j8 - blk * Q;
        int base = blk * (8 * Q) + j;
        int idx[8];
#pragma unroll
        for (int r = 0; r < 8; r++) {
            int p = base + r * Q;
            idx[r] = col ? p*65 + line : line*65 + p;
        }
        float xr[8], xi[8];
#pragma unroll
        for (int r = 0; r < 8; r++) { xr[r] = Ar[idx[r]]; xi[r] = Ai[idx[r]]; }
        if (INV) {
#pragma unroll
            for (int r = 1; r < 8; r++) {
                float wr = twr[M*j*r], wi = twi[M*j*r];
                float a = xr[r], bb = xi[r];
                xr[r] = a*wr + bb*wi;       // x * conj(w)
                xi[r] = bb*wr - a*wi;
            }
        }
        // DFT8 (fwd) / IDFT8 (inv, unscaled): even part
        float t0r=xr[0]+xr[4], t0i=xi[0]+xi[4];
        float t1r=xr[0]-xr[4], t1i=xi[0]-xi[4];
        float t2r=xr[2]+xr[6], t2i=xi[2]+xi[6];
        float d2r=xr[2]-xr[6], d2i=xi[2]-xi[6];
        float t3r, t3i;
        if (INV) { t3r = -d2i; t3i =  d2r; } else { t3r =  d2i; t3i = -d2r; }
        float e0r=t0r+t2r, e0i=t0i+t2i;
        float e1r=t1r+t3r, e1i=t1i+t3i;
        float e2r=t0r-t2r, e2i=t0i-t2i;
        float e3r=t1r-t3r, e3i=t1i-t3i;
        // odd part
        float u0r=xr[1]+xr[5], u0i=xi[1]+xi[5];
        float u1r=xr[1]-xr[5], u1i=xi[1]-xi[5];
        float u2r=xr[3]+xr[7], u2i=xi[3]+xi[7];
        float v2r=xr[3]-xr[7], v2i=xi[3]-xi[7];
        float u3r, u3i;
        if (INV) { u3r = -v2i; u3i =  v2r; } else { u3r =  v2i; u3i = -v2r; }
        float o0r=u0r+u2r, o0i=u0i+u2i;
        float o1r=u1r+u3r, o1i=u1i+u3i;
        float o2r=u0r-u2r, o2i=u0i-u2i;
        float o3r=u1r-u3r, o3i=u1i-u3i;
        // W8^k on odd outputs (fwd: W8=(S2,-S2), W8^2=-i, W8^3=(-S2,-S2); inv conj)
        float w1i = INV ?  S2 : -S2;
        { float a=o1r, bb=o1i; o1r = S2*a - w1i*bb; o1i = S2*bb + w1i*a; }
        { float a=o2r, bb=o2i; if (INV) { o2r = -bb; o2i = a; } else { o2r = bb; o2i = -a; } }
        { float a=o3r, bb=o3i; o3r = -S2*a - w1i*bb; o3i = -S2*bb + w1i*a; }
        float yr[8], yi[8];
        yr[0]=e0r+o0r; yi[0]=e0i+o0i;
        yr[1]=e1r+o1r; yi[1]=e1i+o1i;
        yr[2]=e2r+o2r; yi[2]=e2i+o2i;
        yr[3]=e3r+o3r; yi[3]=e3i+o3i;
        yr[4]=e0r-o0r; yi[4]=e0i-o0i;
        yr[5]=e1r-o1r; yi[5]=e1i-o1i;
        yr[6]=e2r-o2r; yi[6]=e2i-o2i;
        yr[7]=e3r-o3r; yi[7]=e3i-o3i;
        if (!INV) {
#pragma unroll
            for (int r = 1; r < 8; r++) {
                float wr = twr[M*j*r], wi = twi[M*j*r];
                float a = yr[r], bb = yi[r];
                yr[r] = a*wr - bb*wi;
                yi[r] = a*wi + bb*wr;
            }
        }
#pragma unroll
        for (int r = 0; r < 8; r++) { Ar[idx[r]] = yr[r]; Ai[idx[r]] = yi[r]; }
    }
}

__device__ __forceinline__ void fft8_fwd_dim(float* Ar, float* Ai,
                                             const float* twr, const float* twi,
                                             int tid, bool col) {
    fft8s<8,1,false>(Ar, Ai, twr, twi, tid, col); __syncthreads();
    fft8s<1,8,false>(Ar, Ai, twr, twi, tid, col); __syncthreads();
}
__device__ __forceinline__ void fft8_inv_dim(float* Ar, float* Ai,
                                             const float* twr, const float* twi,
                                             int tid, bool col) {
    fft8s<1,8,true>(Ar, Ai, twr, twi, tid, col); __syncthreads();
    fft8s<8,1,true>(Ar, Ai, twr, twi, tid, col); __syncthreads();
}

__device__ __forceinline__ void fft_load_tw64(float* twr, float* twi, int tid) {
    if (tid < 64) {
        float s, c;
        sincosf(-6.28318530717958647692f * (float)tid * (1.0f/64.0f), &s, &c);
        twr[tid] = c; twi[tid] = s;
    }
}

// ---------------- K2: lean depthwise 3x3 + BN + ReLU + stats -> xr fp16 ----------
__global__ void __launch_bounds__(256) k_dw(const float* __restrict__ dww,
                                            const float* __restrict__ dwb,
                                            const float* __restrict__ gamma,
                                            const float* __restrict__ beta,
                                            const float* __restrict__ mean,
                                            const float* __restrict__ var) {
    int plane = blockIdx.x;
    int c = plane & (MIDC-1);
    __shared__ float tile[66*66];
    __shared__ float rs[8], rq[8];
    const float* src = g_buf1 + (size_t)plane*HW;
    for (int idx = threadIdx.x; idx < 66*66; idx += 256) {
        int r = idx / 66, cc = idx - r*66;
        int y = r - 1, x = cc - 1;
        float v = 0.f;
        if ((unsigned)y < 64u && (unsigned)x < 64u) v = src[y*64 + x];
        tile[idx] = v;
    }
    __syncthreads();
    float w0 = dww[c*9+0], w1 = dww[c*9+1], w2 = dww[c*9+2];
    float w3 = dww[c*9+3], w4 = dww[c*9+4], w5 = dww[c*9+5];
    float w6 = dww[c*9+6], w7 = dww[c*9+7], w8 = dww[c*9+8];
    float scale = gamma[c] * rsqrtf(var[c] + 1e-5f);
    float shift = beta[c] - mean[c]*scale;
    float bia = dwb[c];
    float s = 0.f, sq = 0.f;
    __half* dst = g_xr_h + (size_t)plane*HW;
#pragma unroll
    for (int i = 0; i < 16; i++) {
        int p = threadIdx.x + i*256;
        int py = p >> 6, px = p & 63;
        const float* t0 = &tile[py*66 + px];
        float acc = t0[0]*w0 + t0[1]*w1 + t0[2]*w2
                  + t0[66]*w3 + t0[67]*w4 + t0[68]*w5
                  + t0[132]*w6 + t0[133]*w7 + t0[134]*w8;
        acc = fmaxf((acc + bia)*scale + shift, 0.f);
        dst[p] = __float2half(acc);
        s += acc; sq += acc*acc;
    }
#pragma unroll
    for (int o = 16; o; o >>= 1) {
        s  += __shfl_xor_sync(0xffffffffu, s,  o);
        sq += __shfl_xor_sync(0xffffffffu, sq, o);
    }
    int wid = threadIdx.x >> 5;
    if ((threadIdx.x & 31) == 0) { rs[wid] = s; rq[wid] = sq; }
    __syncthreads();
    if (threadIdx.x == 0) {
        float ts = 0.f, tq = 0.f;
#pragma unroll
        for (int w = 0; w < 8; w++) { ts += rs[w]; tq += rq[w]; }
        g_means[plane] = ts * (1.f/4096.f);
        g_nrm[plane]   = sqrtf(tq);   // Parseval
    }
}

// ---- K7: packed-real fwm, 2 planes/CTA, radix-8, gate applied at output ----
__global__ void __launch_bounds__(256) k_fwm2() {
    __shared__ float Ar[64*65], Ai[64*65], twr[64], twi[64];
    __shared__ int mate[64];
    int pp = blockIdx.x;
    int plane0 = pp * 2;
    int b = plane0 >> 8, c0 = plane0 & (MIDC-1);
    int tid = threadIdx.x;
    const __half* x0 = g_xr_h + (size_t)plane0*HW;
    const __half* x1 = x0 + HW;
#pragma unroll
    for (int i = 0; i < 16; i++) {
        int p = tid + i*256; int r = p >> 6, cc = p & 63;
        Ar[r*65+cc] = __half2float(x0[p]);
        Ai[r*65+cc] = __half2float(x1[p]);
    }
    fft_load_tw64(twr, twi, tid);
    if (tid < 64) {
        int rv = ((tid & 7) << 3) | (tid >> 3);   // rev8
        int nk = (64 - rv) & 63;
        mate[tid] = ((nk & 7) << 3) | (nk >> 3);
    }
    __syncthreads();
    // forward DFT (unscaled), octal-digit-reversed both dims
    fft8_fwd_dim(Ar, Ai, twr, twi, tid, false);
    fft8_fwd_dim(Ar, Ai, twr, twi, tid, true);
    // Hermitian unpack + square + repack (pair-ownership: p <= mate)
#pragma unroll
    for (int i = 0; i < 16; i++) {
        int p = tid + i*256; int r = p >> 6, cc = p & 63;
        int mr = mate[r], mc = mate[cc];
        int fm = mr*64 + mc;
        if (p <= fm) {
            int a  = r*65 + cc;
            int am = mr*65 + mc;
            float zpr = Ar[a],  zpi = Ai[a];
            float zmr = Ar[am], zmi = Ai[am];
            float f1r = 0.5f*(zpr + zmr), f1i = 0.5f*(zpi - zmi);
            float f2r = 0.5f*(zpi + zmi), f2i = 0.5f*(zmr - zpr);
            float W1r = f1r*f1r - f1i*f1i, W1i = 2.f*f1r*f1i;
            float W2r = f2r*f2r - f2i*f2i, W2i = 2.f*f2r*f2i;
            Ar[a]  = W1r - W2i;  Ai[a]  = W1i + W2r;
            Ar[am] = W1r + W2i;  Ai[am] = W2r - W1i;
        }
    }
    __syncthreads();
    // inverse DFT (unscaled): result = fwm0_u + i*fwm1_u
    fft8_inv_dim(Ar, Ai, twr, twi, tid, false);
    fft8_inv_dim(Ar, Ai, twr, twi, tid, true);
    float sc0 = g_gate[b*MIDC + c0]     * (1.f/262144.f);
    float sc1 = g_gate[b*MIDC + c0 + 1] * (1.f/262144.f);
    __nv_bfloat16* dst0 = g_fused_bf + ((size_t)b*INDIM + MIDC + c0)*HW;
    __nv_bfloat16* dst1 = dst0 + HW;
#pragma unroll
    for (int i = 0; i < 16; i++) {
        int p = tid + i*256; int r = p >> 6, cc = p & 63;
        int a = r*65 + cc;
        dst0[p] = __float2bfloat16(Ar[a] * sc0);
        dst1[p] = __float2bfloat16(Ai[a] * sc1);
    }
}

// ---------------- K3: SE gate MLP ----------------
__global__ void __launch_bounds__(256) k_gate(const float* __restrict__ w1,
                                              const float* __restrict__ b1,
                                              const float* __restrict__ w2,
                                              const float* __restrict__ b2) {
    int b = blockIdx.x;
    __shared__ float sm[MIDC];
    __shared__ float sh[32];
    int tid = threadIdx.x;
    sm[tid] = g_means[b*MIDC + tid];
    __syncthreads();
    if (tid < 32) {
        float a = b1[tid];
        const float* wr = w1 + tid*MIDC;
        for (int c2 = 0; c2 < MIDC; c2++) a += wr[c2]*sm[c2];
        sh[tid] = fmaxf(a, 0.f);
    }
    __syncthreads();
    float a = b2[tid];
    const float* wr = w2 + tid*32;
#pragma unroll
    for (int j = 0; j < 32; j++) a += wr[j]*sh[j];
    g_gate[b*MIDC + tid] = 1.f / (1.f + expf(-a));
}

// ---------------- K4a: spatial Gram[c,d] = sum_n xr_c(n) * xr_d(-n) ----------------
__global__ void __launch_bounds__(256) k_gram() {
    int sl = blockIdx.x, h = blockIdx.y, b = blockIdx.z;
    size_t base = ((size_t)b*MIDC + h*32) * HW;
    __shared__ float sX[32][65], sY[32][65];
    __shared__ float sRed[4][1024];
    int tid = threadIdx.x;
    int nsub = tid >> 6;
    int tt = tid & 63;
    int c0 = (tt >> 3) * 4, d0 = (tt & 7) * 4;
    float acc[4][4] = {};
    for (int n0 = 0; n0 < 512; n0 += 64) {
        int o = sl*512 + n0;
        int row = o >> 6;
        int grow = (64 - row) & 63;
        __syncthreads();
        for (int idx = tid; idx < 2048; idx += 256) {
            int cc = idx >> 6, nn = idx & 63;
            sX[cc][nn] = __half2float(g_xr_h[base + (size_t)cc*HW + o + nn]);
            sY[cc][(64 - nn) & 63] = __half2float(g_xr_h[base + (size_t)cc*HW + grow*64 + nn]);
        }
        __syncthreads();
        int nlo = nsub * 16;
#pragma unroll 4
        for (int nn = nlo; nn < nlo + 16; nn++) {
            float rc[4], rd[4];
#pragma unroll
            for (int i = 0; i < 4; i++) rc[i] = sX[c0+i][nn];
#pragma unroll
            for (int j = 0; j < 4; j++) rd[j] = sY[d0+j][nn];
#pragma unroll
            for (int i = 0; i < 4; i++)
#pragma unroll
                for (int j = 0; j < 4; j++)
                    acc[i][j] += rc[i]*rd[j];
        }
    }
#pragma unroll
    for (int i = 0; i < 4; i++)
#pragma unroll
        for (int j = 0; j < 4; j++)
            sRed[nsub][tt*16 + i*4 + j] = acc[i][j];
    __syncthreads();
    float* part = g_gram_part + ((size_t)(b*HEADS + h)*8 + sl)*1024;
#pragma unroll
    for (int q = 0; q < 4; q++) {
        int e = tid*4 + q;
        int te = e >> 4, sub = e & 15;
        int i = sub >> 2, j = sub & 3;
        int c = (te >> 3)*4 + i, d = (te & 7)*4 + j;
        part[c*32 + d] = sRed[0][e] + sRed[1][e] + sRed[2][e] + sRed[3][e];
    }
}

// ---------------- K4b: reduce partials + normalize + softmax ----------------
__global__ void __launch_bounds__(256) k_soft(const float* __restrict__ temp) {
    int h = blockIdx.x, b = blockIdx.y;
    __shared__ float sA[32][33], sN[32];
    int tid = threadIdx.x;
    if (tid < 32) sN[tid] = fmaxf(g_nrm[b*MIDC + h*32 + tid], 1e-12f);
    __syncthreads();
    float tK = temp[h];
    const float* part = g_gram_part + (size_t)(b*HEADS + h)*8*1024;
#pragma unroll
    for (int q = 0; q < 4; q++) {
        int e = tid*4 + q;
        int c = e >> 5, d = e & 31;
        float v = 0.f;
#pragma unroll
        for (int s = 0; s < 8; s++) v += part[s*1024 + e];
        sA[c][d] = v * tK / (sN[c] * sN[d]);
    }
    __syncthreads();
    int lane = tid & 31;
    float* aw = g_attnW + (size_t)(b*HEADS + h)*1024;
#pragma unroll
    for (int rr = 0; rr < 4; rr++) {
        int row = (tid >> 5)*4 + rr;
        float v = sA[row][lane];
        float mx = v;
#pragma unroll
        for (int o = 16; o; o >>= 1) mx = fmaxf(mx, __shfl_xor_sync(0xffffffffu, mx, o));
        float e = expf(v - mx);
        float smv = e;
#pragma unroll
        for (int o = 16; o; o >>= 1) smv += __shfl_xor_sync(0xffffffffu, smv, o);
        aw[row*32 + lane] = e / smv;
    }
}

// ---- K4c: spatial mix: out[c](n) = sum_d A[c,d]*(xr_d(n)+xr_d(-n))/2 ----
__global__ void __launch_bounds__(256) k_mix() {
    int sl = blockIdx.x, h = blockIdx.y, b = blockIdx.z;
    size_t base = ((size_t)b*MIDC + h*32) * HW;
    __shared__ float sA[32][33];
    __shared__ float sS[32][65];
    int tid = threadIdx.x;
    const float* aw = g_attnW + (size_t)(b*HEADS + h)*1024;
#pragma unroll
    for (int q = 0; q < 4; q++) {
        int e = tid*4 + q;
        sA[e >> 5][e & 31] = aw[e];
    }
    int cm = (tid >> 4) * 2;
    int nm = (tid & 15) * 4;
    for (int n0 = 0; n0 < 512; n0 += 64) {
        int o = sl*512 + n0;
        int row = o >> 6;
        int grow = (64 - row) & 63;
        __syncthreads();
        for (int idx = tid; idx < 2048; idx += 256) {
            int cc = idx >> 6, nn = idx & 63;
            float a = __half2float(g_xr_h[base + (size_t)cc*HW + o + nn]);
            float bb = __half2float(g_xr_h[base + (size_t)cc*HW + grow*64 + ((64 - nn) & 63)]);
            sS[cc][nn] = 0.5f * (a + bb);
        }
        __syncthreads();
        float o0[4] = {}, o1[4] = {};
#pragma unroll
        for (int d = 0; d < 32; d++) {
            float a0 = sA[cm][d], a1 = sA[cm+1][d];
            float f0 = sS[d][nm], f1 = sS[d][nm+1], f2 = sS[d][nm+2], f3 = sS[d][nm+3];
            o0[0] += a0*f0; o0[1] += a0*f1; o0[2] += a0*f2; o0[3] += a0*f3;
            o1[0] += a1*f0; o1[1] += a1*f1; o1[2] += a1*f2; o1[3] += a1*f3;
        }
        __nv_bfloat162 q00 = __floats2bfloat162_rn(o0[0], o0[1]);
        __nv_bfloat162 q01 = __floats2bfloat162_rn(o0[2], o0[3]);
        __nv_bfloat162 q10 = __floats2bfloat162_rn(o1[0], o1[1]);
        __nv_bfloat162 q11 = __floats2bfloat162_rn(o1[2], o1[3]);
        uint2 pk0, pk1;
        pk0.x = *(uint32_t*)&q00; pk0.y = *(uint32_t*)&q01;
        pk1.x = *(uint32_t*)&q10; pk1.y = *(uint32_t*)&q11;
        size_t fb = ((size_t)b*INDIM + h*32) * HW;
        *(uint2*)&g_fused_bf[fb + (size_t)cm*HW + o + nm]     = pk0;
        *(uint2*)&g_fused_bf[fb + (size_t)(cm+1)*HW + o + nm] = pk1;
    }
}

// ---------------- launch ----------------
extern "C" void kernel_launch(void* const* d_in, const int* in_sizes, int n_in,
                              void* d_out, int out_size) {
    (void)in_sizes; (void)n_in; (void)out_size;
    const float* x        = (const float*)d_in[0];
    const float* reduce_w = (const float*)d_in[1];
    const float* reduce_b = (const float*)d_in[2];
    const float* dw_w     = (const float*)d_in[3];
    const float* dw_b     = (const float*)d_in[4];
    const float* bn_gamma = (const float*)d_in[5];
    const float* bn_beta  = (const float*)d_in[6];
    const float* bn_mean  = (const float*)d_in[7];
    const float* bn_var   = (const float*)d_in[8];
    const float* gate_w1  = (const float*)d_in[9];
    const float* gate_b1  = (const float*)d_in[10];
    const float* gate_w2  = (const float*)d_in[11];
    const float* gate_b2  = (const float*)d_in[12];
    const float* temp     = (const float*)d_in[13];
    const float* post_w   = (const float*)d_in[14];
    const float* post_b   = (const float*)d_in[15];
    float* out = (float*)d_out;

    cudaFuncSetAttribute((const void*)k_gemm_f32,
                         cudaFuncAttributeMaxDynamicSharedMemorySize, GEMM_SMEM);
    cudaFuncSetAttribute((const void*)k_gemm_pipe,
                         cudaFuncAttributeMaxDynamicSharedMemorySize, GEMM_SMEM);

    __nv_bfloat16 *p_fbf, *p_wred, *p_wpost;
    cudaGetSymbolAddress((void**)&p_fbf,   g_fused_bf);
    cudaGetSymbolAddress((void**)&p_wred,  g_wred);
    cudaGetSymbolAddress((void**)&p_wpost, g_wpost);
    float* p_buf1;
    cudaGetSymbolAddress((void**)&p_buf1, g_buf1);

    // weight conversions
    k_cvt<<<(MIDC*INDIM/4 + 255)/256, 256>>>(reduce_w, p_wred, MIDC*INDIM);
    k_cvt<<<(INDIM*2*MIDC/4 + 255)/256, 256>>>(post_w, p_wpost, INDIM*2*MIDC);

    // reduce GEMM (x read fp32, converted in-stage)
    k_gemm_f32<<<dim3(32, 2, BATCH), 256, GEMM_SMEM>>>(
        p_wred, x, reduce_b, p_buf1, MIDC);

    // lean dw + BN + ReLU + stats -> xr fp16
    k_dw<<<BATCH*MIDC, 256>>>(dw_w, dw_b, bn_gamma, bn_beta, bn_mean, bn_var);
    k_gate<<<BATCH, 256>>>(gate_w1, gate_b1, gate_w2, gate_b2);

    // packed-real fwm (2 planes per CTA, radix-8, gated output)
    k_fwm2<<<BATCH*MIDC/2, 256>>>();

    // spatial attention
    k_gram<<<dim3(8, HEADS, BATCH), 256>>>();
    k_soft<<<dim3(HEADS, BATCH), 256>>>(temp);
    k_mix<<<dim3(8, HEADS, BATCH), 256>>>();

    // post GEMM (cp.async pipelined, bias + residual)
    k_gemm_pipe<<<dim3(32, 4, BATCH), 256, GEMM_SMEM>>>(
        p_wpost, p_fbf, post_b, x, out, INDIM);
}

// round 9
// speedup vs baseline: 2.1625x; 1.0193x over previous
#include <cuda_runtime.h>
#include <cuda_bf16.h>
#include <cuda_fp16.h>
#include <mma.h>
#include <math.h>
#include <stdint.h>

using namespace nvcuda;

#define BATCH 16
#define INDIM 512
#define MIDC  256
#define HW    4096
#define HEADS 8

// ---------------- scratch (device globals; no allocation) ----------------
__device__ __half g_buf1h[BATCH*MIDC*HW];   // reduce-GEMM output (pre-dw), fp16
__device__ __half g_xr_h[BATCH*MIDC*HW];    // xr (post dw+BN+ReLU), fp16, spatial
__device__ float  g_means[BATCH*MIDC];
__device__ float  g_nrm  [BATCH*MIDC];
__device__ float  g_gate [BATCH*MIDC];
__device__ float  g_gram_part[BATCH*HEADS*8*1024];
__device__ float  g_attnW[BATCH*HEADS*1024];
__device__ __nv_bfloat16 g_fused_bf[BATCH*INDIM*HW]; // [attn_out | gated fwm]
__device__ __nv_bfloat16 g_wred    [MIDC*INDIM];
__device__ __nv_bfloat16 g_wpost   [INDIM*2*MIDC];

// ================= GEMM common =================
#define AS_STRIDE 40
#define BS_STRIDE 136
#define BF_STRIDE 132     // fp32 staging stride (floats)
#define CS_STRIDE 132
#define GEMM_SMEM (128*CS_STRIDE*4)

__device__ __forceinline__ void cp16(void* sdst, const void* gsrc) {
    uint32_t a = (uint32_t)__cvta_generic_to_shared(sdst);
    asm volatile("cp.async.cg.shared.global [%0], [%1], 16;\n" :: "r"(a), "l"(gsrc));
}
#define CP_COMMIT() asm volatile("cp.async.commit_group;\n" ::: "memory")
#define CP_WAIT(n)  asm volatile("cp.async.wait_group %0;\n" :: "n"(n) : "memory")

__device__ __forceinline__ void mma_step(
    const __nv_bfloat16* As, const __nv_bfloat16* Bs, int wm, int wn,
    wmma::fragment<wmma::accumulator, 16, 16, 16, float> acc[2][4]) {
#pragma unroll
    for (int ks = 0; ks < 2; ks++) {
        wmma::fragment<wmma::matrix_a, 16, 16, 16, __nv_bfloat16, wmma::row_major> af[2];
        wmma::fragment<wmma::matrix_b, 16, 16, 16, __nv_bfloat16, wmma::row_major> bf[4];
#pragma unroll
        for (int i = 0; i < 2; i++)
            wmma::load_matrix_sync(af[i], As + (wm*32 + i*16) * AS_STRIDE + ks*16, AS_STRIDE);
#pragma unroll
        for (int j = 0; j < 4; j++)
            wmma::load_matrix_sync(bf[j], Bs + (ks*16) * BS_STRIDE + wn*64 + j*16, BS_STRIDE);
#pragma unroll
        for (int i = 0; i < 2; i++)
#pragma unroll
            for (int j = 0; j < 4; j++)
                wmma::mma_sync(acc[i][j], af[i], bf[j], acc[i][j]);
    }
}

// ---------------- reduce GEMM: fp32 act, cp.async-staged + smem convert -----------
__global__ void __launch_bounds__(256)
k_gemm_red(const __nv_bfloat16* __restrict__ W,
           const float* __restrict__ act,
           const float* __restrict__ bias,
           __half* __restrict__ out,
           int Mtot) {
    extern __shared__ char sm[];
    __nv_bfloat16* As0 = (__nv_bfloat16*)sm;                       // 2 x 128*40 bf16
    float*         Bf0 = (float*)(sm + 2*128*AS_STRIDE*2);         // 2 x 32*132 f32
    __nv_bfloat16* Bs  = (__nv_bfloat16*)(sm + 2*128*AS_STRIDE*2 + 2*32*BF_STRIDE*4);
    float*         Cs  = (float*)sm;

    int tid = threadIdx.x;
    int w   = tid >> 5;
    int wm  = w & 3;
    int wn  = w >> 2;
    int nb = blockIdx.x * 128, mb = blockIdx.y * 128, b = blockIdx.z;

    const __nv_bfloat16* Ag = W + (size_t)mb * 512;
    const float* Bg = act + (size_t)b * 512 * 4096 + nb;

    int ar0 = tid >> 2,  ac0 = (tid & 3) * 8;   // A: 128x32 bf16, 2 cp16/thread
    int br0 = tid >> 5,  bs0 = (tid & 31) * 4;  // Bf32: 32x128 f32, 4 cp16/thread

    wmma::fragment<wmma::accumulator, 16, 16, 16, float> acc[2][4];
#pragma unroll
    for (int i = 0; i < 2; i++)
#pragma unroll
        for (int j = 0; j < 4; j++) wmma::fill_fragment(acc[i][j], 0.0f);

    // prefetch chunk 0 into stage 0
    {
#pragma unroll
        for (int t = 0; t < 2; t++) {
            int r = ar0 + t*64;
            cp16(As0 + r*AS_STRIDE + ac0, Ag + (size_t)r*512 + ac0);
        }
#pragma unroll
        for (int t = 0; t < 4; t++) {
            int r = br0 + t*8;
            cp16(Bf0 + r*BF_STRIDE + bs0, Bg + (size_t)r*4096 + bs0);
        }
        CP_COMMIT();
    }

    for (int it = 0; it < 16; it++) {
        int cur = it & 1;
        if (it < 15) {
            int kc = (it + 1) * 32;
            __nv_bfloat16* As = As0 + (cur^1)*128*AS_STRIDE;
            float*         Bf = Bf0 + (cur^1)*32*BF_STRIDE;
#pragma unroll
            for (int t = 0; t < 2; t++) {
                int r = ar0 + t*64;
                cp16(As + r*AS_STRIDE + ac0, Ag + (size_t)r*512 + kc + ac0);
            }
#pragma unroll
            for (int t = 0; t < 4; t++) {
                int r = br0 + t*8;
                cp16(Bf + r*BF_STRIDE + bs0, Bg + (size_t)(kc + r)*4096 + bs0);
            }
            CP_COMMIT();
            CP_WAIT(1);
        } else {
            CP_WAIT(0);
        }
        __syncthreads();
        // convert Bf[cur] (32x128 f32) -> Bs bf16
        const float* Bf = Bf0 + cur*32*BF_STRIDE;
#pragma unroll
        for (int t = 0; t < 8; t++) {
            int e2 = (tid + t*256) * 2;          // pair index
            int r = e2 >> 7, c = e2 & 127;
            __nv_bfloat162 pk = __floats2bfloat162_rn(Bf[r*BF_STRIDE + c],
                                                      Bf[r*BF_STRIDE + c + 1]);
            *(uint32_t*)(Bs + r*BS_STRIDE + c) = *(uint32_t*)&pk;
        }
        __syncthreads();
        mma_step(As0 + cur*128*AS_STRIDE, Bs, wm, wn, acc);
        __syncthreads();
    }
#pragma unroll
    for (int i = 0; i < 2; i++)
#pragma unroll
        for (int j = 0; j < 4; j++)
            wmma::store_matrix_sync(Cs + (wm*32 + i*16) * CS_STRIDE + wn*64 + j*16,
                                    acc[i][j], CS_STRIDE, wmma::mem_row_major);
    __syncthreads();
#pragma unroll
    for (int t = 0; t < 16; t++) {
        int id = tid + t * 256;
        int r = id >> 5, c = (id & 31) * 4;
        float bi = bias[mb + r];
        float4 v = *(float4*)(Cs + r * CS_STRIDE + c);
        __half2 h0 = __floats2half2_rn(v.x + bi, v.y + bi);
        __half2 h1 = __floats2half2_rn(v.z + bi, v.w + bi);
        uint2 pk; pk.x = *(uint32_t*)&h0; pk.y = *(uint32_t*)&h1;
        size_t off = ((size_t)b * Mtot + mb + r) * 4096 + nb + c;
        *(uint2*)(out + off) = pk;
    }
}

// ---------------- post GEMM: bf16 act, cp.async 2-stage pipeline ----------------
__global__ void __launch_bounds__(256)
k_gemm_pipe(const __nv_bfloat16* __restrict__ W,
            const __nv_bfloat16* __restrict__ act,
            const float* __restrict__ bias,
            const float* __restrict__ resid,
            float* __restrict__ out,
            int Mtot) {
    extern __shared__ char sm[];
    __nv_bfloat16* As0 = (__nv_bfloat16*)sm;
    __nv_bfloat16* Bs0 = (__nv_bfloat16*)(sm + 2*128*AS_STRIDE*2);
    float*         Cs  = (float*)sm;

    int tid = threadIdx.x;
    int w   = tid >> 5;
    int wm  = w & 3;
    int wn  = w >> 2;
    int nb = blockIdx.x * 128, mb = blockIdx.y * 128, b = blockIdx.z;

    const __nv_bfloat16* Ag = W + (size_t)mb * 512;
    const __nv_bfloat16* Bg = act + (size_t)b * 512 * 4096 + nb;

    int ar0 = tid >> 2,  ac0 = (tid & 3) * 8;
    int br0 = tid >> 4,  bc0 = (tid & 15) * 8;

    wmma::fragment<wmma::accumulator, 16, 16, 16, float> acc[2][4];
#pragma unroll
    for (int i = 0; i < 2; i++)
#pragma unroll
        for (int j = 0; j < 4; j++) wmma::fill_fragment(acc[i][j], 0.0f);

    {
#pragma unroll
        for (int t = 0; t < 2; t++) {
            int r = ar0 + t*64;
            cp16(As0 + r*AS_STRIDE + ac0, Ag + (size_t)r*512 + ac0);
        }
#pragma unroll
        for (int t = 0; t < 2; t++) {
            int r = br0 + t*16;
            cp16(Bs0 + r*BS_STRIDE + bc0, Bg + (size_t)r*4096 + bc0);
        }
        CP_COMMIT();
    }

    for (int it = 0; it < 16; it++) {
        int cur = it & 1;
        if (it < 15) {
            int kc = (it + 1) * 32;
            __nv_bfloat16* As = As0 + (cur^1)*128*AS_STRIDE;
            __nv_bfloat16* Bs = Bs0 + (cur^1)*32*BS_STRIDE;
#pragma unroll
            for (int t = 0; t < 2; t++) {
                int r = ar0 + t*64;
                cp16(As + r*AS_STRIDE + ac0, Ag + (size_t)r*512 + kc + ac0);
            }
#pragma unroll
            for (int t = 0; t < 2; t++) {
                int r = br0 + t*16;
                cp16(Bs + r*BS_STRIDE + bc0, Bg + (size_t)(kc + r)*4096 + bc0);
            }
            CP_COMMIT();
            CP_WAIT(1);
        } else {
            CP_WAIT(0);
        }
        __syncthreads();
        mma_step(As0 + cur*128*AS_STRIDE, Bs0 + cur*32*BS_STRIDE, wm, wn, acc);
        __syncthreads();
    }
#pragma unroll
    for (int i = 0; i < 2; i++)
#pragma unroll
        for (int j = 0; j < 4; j++)
            wmma::store_matrix_sync(Cs + (wm*32 + i*16) * CS_STRIDE + wn*64 + j*16,
                                    acc[i][j], CS_STRIDE, wmma::mem_row_major);
    __syncthreads();
#pragma unroll
    for (int t = 0; t < 16; t++) {
        int id = tid + t * 256;
        int r = id >> 5, c = (id & 31) * 4;
        float bi = bias[mb + r];
        float4 v = *(float4*)(Cs + r * CS_STRIDE + c);
        v.x += bi; v.y += bi; v.z += bi; v.w += bi;
        size_t off = ((size_t)b * Mtot + mb + r) * 4096 + nb + c;
        float4 rr = *(const float4*)(resid + off);
        v.x += rr.x; v.y += rr.y; v.z += rr.z; v.w += rr.w;
        *(float4*)(out + off) = v;
    }
}

// ---------------- conversion (weights only) ----------------
__global__ void __launch_bounds__(256) k_cvt(const float* __restrict__ src,
                                             __nv_bfloat16* __restrict__ dst, int n) {
    int i = (blockIdx.x * 256 + threadIdx.x) * 4;
    if (i < n) {
        float4 v = *(const float4*)(src + i);
        __nv_bfloat162 p0 = __floats2bfloat162_rn(v.x, v.y);
        __nv_bfloat162 p1 = __floats2bfloat162_rn(v.z, v.w);
        uint2 pk;
        pk.x = *(uint32_t*)&p0; pk.y = *(uint32_t*)&p1;
        *(uint2*)(dst + i) = pk;
    }
}

// ================= radix-8 FFT (64-pt, 2 stages/dim, 512 threads, 1 bfly/thr) ======
template<int Q, int M, bool INV>
__device__ __forceinline__ void fft8s(float* Ar, float* Ai,
                                      const float* twr, const float* twi,
                                      int tid, bool col) {
    const float S2 = 0.70710678118654752440f;
    int bf = tid;                 // 0..511
    int line = bf & 63;
    int j8 = bf >> 6;             // 0..7
    int blk = j8 / Q, j = j8 - blk * Q;
    int base = blk * (8 * Q) + j;
    int idx[8];
#pragma unroll
    for (int r = 0; r < 8; r++) {
        int p = base + r * Q;
        idx[r] = col ? p*65 + line : line*65 + p;
    }
    float xr[8], xi[8];
#pragma unroll
    for (int r = 0; r < 8; r++) { xr[r] = Ar[idx[r]]; xi[r] = Ai[idx[r]]; }
    if (INV) {
#pragma unroll
        for (int r = 1; r < 8; r++) {
            float wr = twr[M*j*r], wi = twi[M*j*r];
            float a = xr[r], bb = xi[r];
            xr[r] = a*wr + bb*wi;
            xi[r] = bb*wr - a*wi;
        }
    }
    float t0r=xr[0]+xr[4], t0i=xi[0]+xi[4];
    float t1r=xr[0]-xr[4], t1i=xi[0]-xi[4];
    float t2r=xr[2]+xr[6], t2i=xi[2]+xi[6];
    float d2r=xr[2]-xr[6], d2i=xi[2]-xi[6];
    float t3r, t3i;
    if (INV) { t3r = -d2i; t3i =  d2r; } else { t3r =  d2i; t3i = -d2r; }
    float e0r=t0r+t2r, e0i=t0i+t2i;
    float e1r=t1r+t3r, e1i=t1i+t3i;
    float e2r=t0r-t2r, e2i=t0i-t2i;
    float e3r=t1r-t3r, e3i=t1i-t3i;
    float u0r=xr[1]+xr[5], u0i=xi[1]+xi[5];
    float u1r=xr[1]-xr[5], u1i=xi[1]-xi[5];
    float u2r=xr[3]+xr[7], u2i=xi[3]+xi[7];
    float v2r=xr[3]-xr[7], v2i=xi[3]-xi[7];
    float u3r, u3i;
    if (INV) { u3r = -v2i; u3i =  v2r; } else { u3r =  v2i; u3i = -v2r; }
    float o0r=u0r+u2r, o0i=u0i+u2i;
    float o1r=u1r+u3r, o1i=u1i+u3i;
    float o2r=u0r-u2r, o2i=u0i-u2i;
    float o3r=u1r-u3r, o3i=u1i-u3i;
    float w1i = INV ?  S2 : -S2;
    { float a=o1r, bb=o1i; o1r = S2*a - w1i*bb; o1i = S2*bb + w1i*a; }
    { float a=o2r, bb=o2i; if (INV) { o2r = -bb; o2i = a; } else { o2r = bb; o2i = -a; } }
    { float a=o3r, bb=o3i; o3r = -S2*a - w1i*bb; o3i = -S2*bb + w1i*a; }
    float yr[8], yi[8];
    yr[0]=e0r+o0r; yi[0]=e0i+o0i;
    yr[1]=e1r+o1r; yi[1]=e1i+o1i;
    yr[2]=e2r+o2r; yi[2]=e2i+o2i;
    yr[3]=e3r+o3r; yi[3]=e3i+o3i;
    yr[4]=e0r-o0r; yi[4]=e0i-o0i;
    yr[5]=e1r-o1r; yi[5]=e1i-o1i;
    yr[6]=e2r-o2r; yi[6]=e2i-o2i;
    yr[7]=e3r-o3r; yi[7]=e3i-o3i;
    if (!INV) {
#pragma unroll
        for (int r = 1; r < 8; r++) {
            float wr = twr[M*j*r], wi = twi[M*j*r];
            float a = yr[r], bb = yi[r];
            yr[r] = a*wr - bb*wi;
            yi[r] = a*wi + bb*wr;
        }
    }
#pragma unroll
    for (int r = 0; r < 8; r++) { Ar[idx[r]] = yr[r]; Ai[idx[r]] = yi[r]; }
}

__device__ __forceinline__ void fft8_fwd_dim(float* Ar, float* Ai,
                                             const float* twr, const float* twi,
                                             int tid, bool col) {
    fft8s<8,1,false>(Ar, Ai, twr, twi, tid, col); __syncthreads();
    fft8s<1,8,false>(Ar, Ai, twr, twi, tid, col); __syncthreads();
}
__device__ __forceinline__ void fft8_inv_dim(float* Ar, float* Ai,
                                             const float* twr, const float* twi,
                                             int tid, bool col) {
    fft8s<1,8,true>(Ar, Ai, twr, twi, tid, col); __syncthreads();
    fft8s<8,1,true>(Ar, Ai, twr, twi, tid, col); __syncthreads();
}

__device__ __forceinline__ void fft_load_tw64(float* twr, float* twi, int tid) {
    if (tid < 64) {
        float s, c;
        sincosf(-6.28318530717958647692f * (float)tid * (1.0f/64.0f), &s, &c);
        twr[tid] = c; twi[tid] = s;
    }
}

// ---------------- K2: lean depthwise 3x3 + BN + ReLU + stats -> xr fp16 ----------
__global__ void __launch_bounds__(256) k_dw(const float* __restrict__ dww,
                                            const float* __restrict__ dwb,
                                            const float* __restrict__ gamma,
                                            const float* __restrict__ beta,
                                            const float* __restrict__ mean,
                                            const float* __restrict__ var) {
    int plane = blockIdx.x;
    int c = plane & (MIDC-1);
    __shared__ float tile[66*66];
    __shared__ float rs[8], rq[8];
    const __half* src = g_buf1h + (size_t)plane*HW;
    for (int idx = threadIdx.x; idx < 66*66; idx += 256) {
        int r = idx / 66, cc = idx - r*66;
        int y = r - 1, x = cc - 1;
        float v = 0.f;
        if ((unsigned)y < 64u && (unsigned)x < 64u) v = __half2float(src[y*64 + x]);
        tile[idx] = v;
    }
    __syncthreads();
    float w0 = dww[c*9+0], w1 = dww[c*9+1], w2 = dww[c*9+2];
    float w3 = dww[c*9+3], w4 = dww[c*9+4], w5 = dww[c*9+5];
    float w6 = dww[c*9+6], w7 = dww[c*9+7], w8 = dww[c*9+8];
    float scale = gamma[c] * rsqrtf(var[c] + 1e-5f);
    float shift = beta[c] - mean[c]*scale;
    float bia = dwb[c];
    float s = 0.f, sq = 0.f;
    __half* dst = g_xr_h + (size_t)plane*HW;
#pragma unroll
    for (int i = 0; i < 16; i++) {
        int p = threadIdx.x + i*256;
        int py = p >> 6, px = p & 63;
        const float* t0 = &tile[py*66 + px];
        float acc = t0[0]*w0 + t0[1]*w1 + t0[2]*w2
                  + t0[66]*w3 + t0[67]*w4 + t0[68]*w5
                  + t0[132]*w6 + t0[133]*w7 + t0[134]*w8;
        acc = fmaxf((acc + bia)*scale + shift, 0.f);
        dst[p] = __float2half(acc);
        s += acc; sq += acc*acc;
    }
#pragma unroll
    for (int o = 16; o; o >>= 1) {
        s  += __shfl_xor_sync(0xffffffffu, s,  o);
        sq += __shfl_xor_sync(0xffffffffu, sq, o);
    }
    int wid = threadIdx.x >> 5;
    if ((threadIdx.x & 31) == 0) { rs[wid] = s; rq[wid] = sq; }
    __syncthreads();
    if (threadIdx.x == 0) {
        float ts = 0.f, tq = 0.f;
#pragma unroll
        for (int w = 0; w < 8; w++) { ts += rs[w]; tq += rq[w]; }
        g_means[plane] = ts * (1.f/4096.f);
        g_nrm[plane]   = sqrtf(tq);   // Parseval
    }
}

// ---- K7: packed-real fwm, 2 planes/CTA, radix-8, 512 threads, gated output ----
__global__ void __launch_bounds__(512) k_fwm2() {
    __shared__ float Ar[64*65], Ai[64*65], twr[64], twi[64];
    __shared__ int mate[64];
    int pp = blockIdx.x;
    int plane0 = pp * 2;
    int b = plane0 >> 8, c0 = plane0 & (MIDC-1);
    int tid = threadIdx.x;
    const __half* x0 = g_xr_h + (size_t)plane0*HW;
    const __half* x1 = x0 + HW;
#pragma unroll
    for (int i = 0; i < 8; i++) {
        int p = tid + i*512; int r = p >> 6, cc = p & 63;
        Ar[r*65+cc] = __half2float(x0[p]);
        Ai[r*65+cc] = __half2float(x1[p]);
    }
    fft_load_tw64(twr, twi, tid);
    if (tid < 64) {
        int rv = ((tid & 7) << 3) | (tid >> 3);   // rev8
        int nk = (64 - rv) & 63;
        mate[tid] = ((nk & 7) << 3) | (nk >> 3);
    }
    __syncthreads();
    fft8_fwd_dim(Ar, Ai, twr, twi, tid, false);
    fft8_fwd_dim(Ar, Ai, twr, twi, tid, true);
#pragma unroll
    for (int i = 0; i < 8; i++) {
        int p = tid + i*512; int r = p >> 6, cc = p & 63;
        int mr = mate[r], mc = mate[cc];
        int fm = mr*64 + mc;
        if (p <= fm) {
            int a  = r*65 + cc;
            int am = mr*65 + mc;
            float zpr = Ar[a],  zpi = Ai[a];
            float zmr = Ar[am], zmi = Ai[am];
            float f1r = 0.5f*(zpr + zmr), f1i = 0.5f*(zpi - zmi);
            float f2r = 0.5f*(zpi + zmi), f2i = 0.5f*(zmr - zpr);
            float W1r = f1r*f1r - f1i*f1i, W1i = 2.f*f1r*f1i;
            float W2r = f2r*f2r - f2i*f2i, W2i = 2.f*f2r*f2i;
            Ar[a]  = W1r - W2i;  Ai[a]  = W1i + W2r;
            Ar[am] = W1r + W2i;  Ai[am] = W2r - W1i;
        }
    }
    __syncthreads();
    fft8_inv_dim(Ar, Ai, twr, twi, tid, false);
    fft8_inv_dim(Ar, Ai, twr, twi, tid, true);
    float sc0 = g_gate[b*MIDC + c0]     * (1.f/262144.f);
    float sc1 = g_gate[b*MIDC + c0 + 1] * (1.f/262144.f);
    __nv_bfloat16* dst0 = g_fused_bf + ((size_t)b*INDIM + MIDC + c0)*HW;
    __nv_bfloat16* dst1 = dst0 + HW;
#pragma unroll
    for (int i = 0; i < 8; i++) {
        int p = tid + i*512; int r = p >> 6, cc = p & 63;
        int a = r*65 + cc;
        dst0[p] = __float2bfloat16(Ar[a] * sc0);
        dst1[p] = __float2bfloat16(Ai[a] * sc1);
    }
}

// ---------------- K3: SE gate MLP ----------------
__global__ void __launch_bounds__(256) k_gate(const float* __restrict__ w1,
                                              const float* __restrict__ b1,
                                              const float* __restrict__ w2,
                                              const float* __restrict__ b2) {
    int b = blockIdx.x;
    __shared__ float sm[MIDC];
    __shared__ float sh[32];
    int tid = threadIdx.x;
    sm[tid] = g_means[b*MIDC + tid];
    __syncthreads();
    if (tid < 32) {
        float a = b1[tid];
        const float* wr = w1 + tid*MIDC;
        for (int c2 = 0; c2 < MIDC; c2++) a += wr[c2]*sm[c2];
        sh[tid] = fmaxf(a, 0.f);
    }
    __syncthreads();
    float a = b2[tid];
    const float* wr = w2 + tid*32;
#pragma unroll
    for (int j = 0; j < 32; j++) a += wr[j]*sh[j];
    g_gate[b*MIDC + tid] = 1.f / (1.f + expf(-a));
}

// ---------------- K4a: spatial Gram[c,d] = sum_n xr_c(n) * xr_d(-n) ----------------
__global__ void __launch_bounds__(256) k_gram() {
    int sl = blockIdx.x, h = blockIdx.y, b = blockIdx.z;
    size_t base = ((size_t)b*MIDC + h*32) * HW;
    __shared__ float sX[32][65], sY[32][65];
    __shared__ float sRed[4][1024];
    int tid = threadIdx.x;
    int nsub = tid >> 6;
    int tt = tid & 63;
    int c0 = (tt >> 3) * 4, d0 = (tt & 7) * 4;
    float acc[4][4] = {};
    for (int n0 = 0; n0 < 512; n0 += 64) {
        int o = sl*512 + n0;
        int row = o >> 6;
        int grow = (64 - row) & 63;
        __syncthreads();
        for (int idx = tid; idx < 2048; idx += 256) {
            int cc = idx >> 6, nn = idx & 63;
            sX[cc][nn] = __half2float(g_xr_h[base + (size_t)cc*HW + o + nn]);
            sY[cc][(64 - nn) & 63] = __half2float(g_xr_h[base + (size_t)cc*HW + grow*64 + nn]);
        }
        __syncthreads();
        int nlo = nsub * 16;
#pragma unroll 4
        for (int nn = nlo; nn < nlo + 16; nn++) {
            float rc[4], rd[4];
#pragma unroll
            for (int i = 0; i < 4; i++) rc[i] = sX[c0+i][nn];
#pragma unroll
            for (int j = 0; j < 4; j++) rd[j] = sY[d0+j][nn];
#pragma unroll
            for (int i = 0; i < 4; i++)
#pragma unroll
                for (int j = 0; j < 4; j++)
                    acc[i][j] += rc[i]*rd[j];
        }
    }
#pragma unroll
    for (int i = 0; i < 4; i++)
#pragma unroll
        for (int j = 0; j < 4; j++)
            sRed[nsub][tt*16 + i*4 + j] = acc[i][j];
    __syncthreads();
    float* part = g_gram_part + ((size_t)(b*HEADS + h)*8 + sl)*1024;
#pragma unroll
    for (int q = 0; q < 4; q++) {
        int e = tid*4 + q;
        int te = e >> 4, sub = e & 15;
        int i = sub >> 2, j = sub & 3;
        int c = (te >> 3)*4 + i, d = (te & 7)*4 + j;
        part[c*32 + d] = sRed[0][e] + sRed[1][e] + sRed[2][e] + sRed[3][e];
    }
}

// ---------------- K4b: reduce partials + normalize + softmax ----------------
__global__ void __launch_bounds__(256) k_soft(const float* __restrict__ temp) {
    int h = blockIdx.x, b = blockIdx.y;
    __shared__ float sA[32][33], sN[32];
    int tid = threadIdx.x;
    if (tid < 32) sN[tid] = fmaxf(g_nrm[b*MIDC + h*32 + tid], 1e-12f);
    __syncthreads();
    float tK = temp[h];
    const float* part = g_gram_part + (size_t)(b*HEADS + h)*8*1024;
#pragma unroll
    for (int q = 0; q < 4; q++) {
        int e = tid*4 + q;
        int c = e >> 5, d = e & 31;
        float v = 0.f;
#pragma unroll
        for (int s = 0; s < 8; s++) v += part[s*1024 + e];
        sA[c][d] = v * tK / (sN[c] * sN[d]);
    }
    __syncthreads();
    int lane = tid & 31;
    float* aw = g_attnW + (size_t)(b*HEADS + h)*1024;
#pragma unroll
    for (int rr = 0; rr < 4; rr++) {
        int row = (tid >> 5)*4 + rr;
        float v = sA[row][lane];
        float mx = v;
#pragma unroll
        for (int o = 16; o; o >>= 1) mx = fmaxf(mx, __shfl_xor_sync(0xffffffffu, mx, o));
        float e = expf(v - mx);
        float smv = e;
#pragma unroll
        for (int o = 16; o; o >>= 1) smv += __shfl_xor_sync(0xffffffffu, smv, o);
        aw[row*32 + lane] = e / smv;
    }
}

// ---- K4c: spatial mix: out[c](n) = sum_d A[c,d]*(xr_d(n)+xr_d(-n))/2 ----
__global__ void __launch_bounds__(256) k_mix() {
    int sl = blockIdx.x, h = blockIdx.y, b = blockIdx.z;
    size_t base = ((size_t)b*MIDC + h*32) * HW;
    __shared__ float sA[32][33];
    __shared__ float sS[32][65];
    int tid = threadIdx.x;
    const float* aw = g_attnW + (size_t)(b*HEADS + h)*1024;
#pragma unroll
    for (int q = 0; q < 4; q++) {
        int e = tid*4 + q;
        sA[e >> 5][e & 31] = aw[e];
    }
    int cm = (tid >> 4) * 2;
    int nm = (tid & 15) * 4;
    for (int n0 = 0; n0 < 512; n0 += 64) {
        int o = sl*512 + n0;
        int row = o >> 6;
        int grow = (64 - row) & 63;
        __syncthreads();
        for (int idx = tid; idx < 2048; idx += 256) {
            int cc = idx >> 6, nn = idx & 63;
            float a = __half2float(g_xr_h[base + (size_t)cc*HW + o + nn]);
            float bb = __half2float(g_xr_h[base + (size_t)cc*HW + grow*64 + ((64 - nn) & 63)]);
            sS[cc][nn] = 0.5f * (a + bb);
        }
        __syncthreads();
        float o0[4] = {}, o1[4] = {};
#pragma unroll
        for (int d = 0; d < 32; d++) {
            float a0 = sA[cm][d], a1 = sA[cm+1][d];
            float f0 = sS[d][nm], f1 = sS[d][nm+1], f2 = sS[d][nm+2], f3 = sS[d][nm+3];
            o0[0] += a0*f0; o0[1] += a0*f1; o0[2] += a0*f2; o0[3] += a0*f3;
            o1[0] += a1*f0; o1[1] += a1*f1; o1[2] += a1*f2; o1[3] += a1*f3;
        }
        __nv_bfloat162 q00 = __floats2bfloat162_rn(o0[0], o0[1]);
        __nv_bfloat162 q01 = __floats2bfloat162_rn(o0[2], o0[3]);
        __nv_bfloat162 q10 = __floats2bfloat162_rn(o1[0], o1[1]);
        __nv_bfloat162 q11 = __floats2bfloat162_rn(o1[2], o1[3]);
        uint2 pk0, pk1;
        pk0.x = *(uint32_t*)&q00; pk0.y = *(uint32_t*)&q01;
        pk1.x = *(uint32_t*)&q10; pk1.y = *(uint32_t*)&q11;
        size_t fb = ((size_t)b*INDIM + h*32) * HW;
        *(uint2*)&g_fused_bf[fb + (size_t)cm*HW + o + nm]     = pk0;
        *(uint2*)&g_fused_bf[fb + (size_t)(cm+1)*HW + o + nm] = pk1;
    }
}

// ---------------- launch ----------------
extern "C" void kernel_launch(void* const* d_in, const int* in_sizes, int n_in,
                              void* d_out, int out_size) {
    (void)in_sizes; (void)n_in; (void)out_size;
    const float* x        = (const float*)d_in[0];
    const float* reduce_w = (const float*)d_in[1];
    const float* reduce_b = (const float*)d_in[2];
    const float* dw_w     = (const float*)d_in[3];
    const float* dw_b     = (const float*)d_in[4];
    const float* bn_gamma = (const float*)d_in[5];
    const float* bn_beta  = (const float*)d_in[6];
    const float* bn_mean  = (const float*)d_in[7];
    const float* bn_var   = (const float*)d_in[8];
    const float* gate_w1  = (const float*)d_in[9];
    const float* gate_b1  = (const float*)d_in[10];
    const float* gate_w2  = (const float*)d_in[11];
    const float* gate_b2  = (const float*)d_in[12];
    const float* temp     = (const float*)d_in[13];
    const float* post_w   = (const float*)d_in[14];
    const float* post_b   = (const float*)d_in[15];
    float* out = (float*)d_out;

    cudaFuncSetAttribute((const void*)k_gemm_red,
                         cudaFuncAttributeMaxDynamicSharedMemorySize, GEMM_SMEM);
    cudaFuncSetAttribute((const void*)k_gemm_pipe,
                         cudaFuncAttributeMaxDynamicSharedMemorySize, GEMM_SMEM);

    __nv_bfloat16 *p_fbf, *p_wred, *p_wpost;
    cudaGetSymbolAddress((void**)&p_fbf,   g_fused_bf);
    cudaGetSymbolAddress((void**)&p_wred,  g_wred);
    cudaGetSymbolAddress((void**)&p_wpost, g_wpost);
    __half* p_buf1h;
    cudaGetSymbolAddress((void**)&p_buf1h, g_buf1h);

    // weight conversions
    k_cvt<<<(MIDC*INDIM/4 + 255)/256, 256>>>(reduce_w, p_wred, MIDC*INDIM);
    k_cvt<<<(INDIM*2*MIDC/4 + 255)/256, 256>>>(post_w, p_wpost, INDIM*2*MIDC);

    // reduce GEMM (fp32 act staged via cp.async, converted in smem) -> fp16
    k_gemm_red<<<dim3(32, 2, BATCH), 256, GEMM_SMEM>>>(
        p_wred, x, reduce_b, p_buf1h, MIDC);

    // lean dw + BN + ReLU + stats -> xr fp16
    k_dw<<<BATCH*MIDC, 256>>>(dw_w, dw_b, bn_gamma, bn_beta, bn_mean, bn_var);
    k_gate<<<BATCH, 256>>>(gate_w1, gate_b1, gate_w2, gate_b2);

    // packed-real fwm (2 planes per CTA, radix-8, 512 threads)
    k_fwm2<<<BATCH*MIDC/2, 512>>>();

    // spatial attention
    k_gram<<<dim3(8, HEADS, BATCH), 256>>>();
    k_soft<<<dim3(HEADS, BATCH), 256>>>(temp);
    k_mix<<<dim3(8, HEADS, BATCH), 256>>>();

    // post GEMM (cp.async pipelined, bias + residual)
    k_gemm_pipe<<<dim3(32, 4, BATCH), 256, GEMM_SMEM>>>(
        p_wpost, p_fbf, post_b, x, out, INDIM);
}

// round 10
// speedup vs baseline: 2.2395x; 1.0356x over previous
#include <cuda_runtime.h>
#include <cuda_bf16.h>
#include <cuda_fp16.h>
#include <mma.h>
#include <math.h>
#include <stdint.h>

using namespace nvcuda;

#define BATCH 16
#define INDIM 512
#define MIDC  256
#define HW    4096
#define HEADS 8

// ---------------- scratch (device globals; no allocation) ----------------
__device__ __half g_buf1h[BATCH*MIDC*HW];   // reduce-GEMM output (pre-dw), fp16
__device__ __half g_xr_h[BATCH*MIDC*HW];    // xr (post dw+BN+ReLU), fp16, spatial
__device__ float  g_means[BATCH*MIDC];
__device__ float  g_nrm  [BATCH*MIDC];
__device__ float  g_gate [BATCH*MIDC];
__device__ float  g_gram_part[BATCH*HEADS*8*1024];
__device__ float  g_attnW[BATCH*HEADS*1024];
__device__ __nv_bfloat16 g_fused_bf[BATCH*INDIM*HW]; // [attn_out | gated fwm]
__device__ __nv_bfloat16 g_wred    [MIDC*INDIM];
__device__ __nv_bfloat16 g_wpost   [INDIM*2*MIDC];

// ================= GEMM common =================
#define AS_STRIDE 40
#define BS_STRIDE 136
#define BF_STRIDE 132
#define CS_STRIDE 132
#define GEMM_SMEM (128*CS_STRIDE*4)

__device__ __forceinline__ void cp16(void* sdst, const void* gsrc) {
    uint32_t a = (uint32_t)__cvta_generic_to_shared(sdst);
    asm volatile("cp.async.cg.shared.global [%0], [%1], 16;\n" :: "r"(a), "l"(gsrc));
}
#define CP_COMMIT() asm volatile("cp.async.commit_group;\n" ::: "memory")
#define CP_WAIT(n)  asm volatile("cp.async.wait_group %0;\n" :: "n"(n) : "memory")

__device__ __forceinline__ void mma_step(
    const __nv_bfloat16* As, const __nv_bfloat16* Bs, int wm, int wn,
    wmma::fragment<wmma::accumulator, 16, 16, 16, float> acc[2][4]) {
#pragma unroll
    for (int ks = 0; ks < 2; ks++) {
        wmma::fragment<wmma::matrix_a, 16, 16, 16, __nv_bfloat16, wmma::row_major> af[2];
        wmma::fragment<wmma::matrix_b, 16, 16, 16, __nv_bfloat16, wmma::row_major> bf[4];
#pragma unroll
        for (int i = 0; i < 2; i++)
            wmma::load_matrix_sync(af[i], As + (wm*32 + i*16) * AS_STRIDE + ks*16, AS_STRIDE);
#pragma unroll
        for (int j = 0; j < 4; j++)
            wmma::load_matrix_sync(bf[j], Bs + (ks*16) * BS_STRIDE + wn*64 + j*16, BS_STRIDE);
#pragma unroll
        for (int i = 0; i < 2; i++)
#pragma unroll
            for (int j = 0; j < 4; j++)
                wmma::mma_sync(acc[i][j], af[i], bf[j], acc[i][j]);
    }
}

// ---------------- reduce GEMM: fp32 act, cp.async-staged + smem convert -----------
__global__ void __launch_bounds__(256)
k_gemm_red(const __nv_bfloat16* __restrict__ W,
           const float* __restrict__ act,
           const float* __restrict__ bias,
           __half* __restrict__ out,
           int Mtot) {
    extern __shared__ char sm[];
    __nv_bfloat16* As0 = (__nv_bfloat16*)sm;
    float*         Bf0 = (float*)(sm + 2*128*AS_STRIDE*2);
    __nv_bfloat16* Bs  = (__nv_bfloat16*)(sm + 2*128*AS_STRIDE*2 + 2*32*BF_STRIDE*4);
    float*         Cs  = (float*)sm;

    int tid = threadIdx.x;
    int w   = tid >> 5;
    int wm  = w & 3;
    int wn  = w >> 2;
    int nb = blockIdx.x * 128, mb = blockIdx.y * 128, b = blockIdx.z;

    const __nv_bfloat16* Ag = W + (size_t)mb * 512;
    const float* Bg = act + (size_t)b * 512 * 4096 + nb;

    int ar0 = tid >> 2,  ac0 = (tid & 3) * 8;
    int br0 = tid >> 5,  bs0 = (tid & 31) * 4;

    wmma::fragment<wmma::accumulator, 16, 16, 16, float> acc[2][4];
#pragma unroll
    for (int i = 0; i < 2; i++)
#pragma unroll
        for (int j = 0; j < 4; j++) wmma::fill_fragment(acc[i][j], 0.0f);

    {
#pragma unroll
        for (int t = 0; t < 2; t++) {
            int r = ar0 + t*64;
            cp16(As0 + r*AS_STRIDE + ac0, Ag + (size_t)r*512 + ac0);
        }
#pragma unroll
        for (int t = 0; t < 4; t++) {
            int r = br0 + t*8;
            cp16(Bf0 + r*BF_STRIDE + bs0, Bg + (size_t)r*4096 + bs0);
        }
        CP_COMMIT();
    }

    for (int it = 0; it < 16; it++) {
        int cur = it & 1;
        if (it < 15) {
            int kc = (it + 1) * 32;
            __nv_bfloat16* As = As0 + (cur^1)*128*AS_STRIDE;
            float*         Bf = Bf0 + (cur^1)*32*BF_STRIDE;
#pragma unroll
            for (int t = 0; t < 2; t++) {
                int r = ar0 + t*64;
                cp16(As + r*AS_STRIDE + ac0, Ag + (size_t)r*512 + kc + ac0);
            }
#pragma unroll
            for (int t = 0; t < 4; t++) {
                int r = br0 + t*8;
                cp16(Bf + r*BF_STRIDE + bs0, Bg + (size_t)(kc + r)*4096 + bs0);
            }
            CP_COMMIT();
            CP_WAIT(1);
        } else {
            CP_WAIT(0);
        }
        __syncthreads();
        const float* Bf = Bf0 + cur*32*BF_STRIDE;
#pragma unroll
        for (int t = 0; t < 8; t++) {
            int e2 = (tid + t*256) * 2;
            int r = e2 >> 7, c = e2 & 127;
            __nv_bfloat162 pk = __floats2bfloat162_rn(Bf[r*BF_STRIDE + c],
                                                      Bf[r*BF_STRIDE + c + 1]);
            *(uint32_t*)(Bs + r*BS_STRIDE + c) = *(uint32_t*)&pk;
        }
        __syncthreads();
        mma_step(As0 + cur*128*AS_STRIDE, Bs, wm, wn, acc);
        __syncthreads();
    }
#pragma unroll
    for (int i = 0; i < 2; i++)
#pragma unroll
        for (int j = 0; j < 4; j++)
            wmma::store_matrix_sync(Cs + (wm*32 + i*16) * CS_STRIDE + wn*64 + j*16,
                                    acc[i][j], CS_STRIDE, wmma::mem_row_major);
    __syncthreads();
#pragma unroll
    for (int t = 0; t < 16; t++) {
        int id = tid + t * 256;
        int r = id >> 5, c = (id & 31) * 4;
        float bi = bias[mb + r];
        float4 v = *(float4*)(Cs + r * CS_STRIDE + c);
        __half2 h0 = __floats2half2_rn(v.x + bi, v.y + bi);
        __half2 h1 = __floats2half2_rn(v.z + bi, v.w + bi);
        uint2 pk; pk.x = *(uint32_t*)&h0; pk.y = *(uint32_t*)&h1;
        size_t off = ((size_t)b * Mtot + mb + r) * 4096 + nb + c;
        *(uint2*)(out + off) = pk;
    }
}

// ---------------- post GEMM: bf16 act, cp.async 2-stage pipeline ----------------
__global__ void __launch_bounds__(256)
k_gemm_pipe(const __nv_bfloat16* __restrict__ W,
            const __nv_bfloat16* __restrict__ act,
            const float* __restrict__ bias,
            const float* __restrict__ resid,
            float* __restrict__ out,
            int Mtot) {
    extern __shared__ char sm[];
    __nv_bfloat16* As0 = (__nv_bfloat16*)sm;
    __nv_bfloat16* Bs0 = (__nv_bfloat16*)(sm + 2*128*AS_STRIDE*2);
    float*         Cs  = (float*)sm;

    int tid = threadIdx.x;
    int w   = tid >> 5;
    int wm  = w & 3;
    int wn  = w >> 2;
    int nb = blockIdx.x * 128, mb = blockIdx.y * 128, b = blockIdx.z;

    const __nv_bfloat16* Ag = W + (size_t)mb * 512;
    const __nv_bfloat16* Bg = act + (size_t)b * 512 * 4096 + nb;

    int ar0 = tid >> 2,  ac0 = (tid & 3) * 8;
    int br0 = tid >> 4,  bc0 = (tid & 15) * 8;

    wmma::fragment<wmma::accumulator, 16, 16, 16, float> acc[2][4];
#pragma unroll
    for (int i = 0; i < 2; i++)
#pragma unroll
        for (int j = 0; j < 4; j++) wmma::fill_fragment(acc[i][j], 0.0f);

    {
#pragma unroll
        for (int t = 0; t < 2; t++) {
            int r = ar0 + t*64;
            cp16(As0 + r*AS_STRIDE + ac0, Ag + (size_t)r*512 + ac0);
        }
#pragma unroll
        for (int t = 0; t < 2; t++) {
            int r = br0 + t*16;
            cp16(Bs0 + r*BS_STRIDE + bc0, Bg + (size_t)r*4096 + bc0);
        }
        CP_COMMIT();
    }

    for (int it = 0; it < 16; it++) {
        int cur = it & 1;
        if (it < 15) {
            int kc = (it + 1) * 32;
            __nv_bfloat16* As = As0 + (cur^1)*128*AS_STRIDE;
            __nv_bfloat16* Bs = Bs0 + (cur^1)*32*BS_STRIDE;
#pragma unroll
            for (int t = 0; t < 2; t++) {
                int r = ar0 + t*64;
                cp16(As + r*AS_STRIDE + ac0, Ag + (size_t)r*512 + kc + ac0);
            }
#pragma unroll
            for (int t = 0; t < 2; t++) {
                int r = br0 + t*16;
                cp16(Bs + r*BS_STRIDE + bc0, Bg + (size_t)(kc + r)*4096 + bc0);
            }
            CP_COMMIT();
            CP_WAIT(1);
        } else {
            CP_WAIT(0);
        }
        __syncthreads();
        mma_step(As0 + cur*128*AS_STRIDE, Bs0 + cur*32*BS_STRIDE, wm, wn, acc);
        __syncthreads();
    }
#pragma unroll
    for (int i = 0; i < 2; i++)
#pragma unroll
        for (int j = 0; j < 4; j++)
            wmma::store_matrix_sync(Cs + (wm*32 + i*16) * CS_STRIDE + wn*64 + j*16,
                                    acc[i][j], CS_STRIDE, wmma::mem_row_major);
    __syncthreads();
#pragma unroll
    for (int t = 0; t < 16; t++) {
        int id = tid + t * 256;
        int r = id >> 5, c = (id & 31) * 4;
        float bi = bias[mb + r];
        float4 v = *(float4*)(Cs + r * CS_STRIDE + c);
        v.x += bi; v.y += bi; v.z += bi; v.w += bi;
        size_t off = ((size_t)b * Mtot + mb + r) * 4096 + nb + c;
        float4 rr = *(const float4*)(resid + off);
        v.x += rr.x; v.y += rr.y; v.z += rr.z; v.w += rr.w;
        *(float4*)(out + off) = v;
    }
}

// ---------------- merged weight conversion ----------------
__global__ void __launch_bounds__(256) k_cvt2(const float* __restrict__ s1,
                                              __nv_bfloat16* __restrict__ d1, int n1,
                                              const float* __restrict__ s2,
                                              __nv_bfloat16* __restrict__ d2, int n2) {
    int i = (blockIdx.x * 256 + threadIdx.x) * 4;
    const float* src; __nv_bfloat16* dst; int idx;
    if (i < n1) { src = s1; dst = d1; idx = i; }
    else { idx = i - n1; if (idx >= n2) return; src = s2; dst = d2; }
    float4 v = *(const float4*)(src + idx);
    __nv_bfloat162 p0 = __floats2bfloat162_rn(v.x, v.y);
    __nv_bfloat162 p1 = __floats2bfloat162_rn(v.z, v.w);
    uint2 pk;
    pk.x = *(uint32_t*)&p0; pk.y = *(uint32_t*)&p1;
    *(uint2*)(dst + idx) = pk;
}

// ================= radix-8 FFT (64-pt, 2 stages/dim, 512 threads, 1 bfly/thr) ======
template<int Q, int M, bool INV>
__device__ __forceinline__ void fft8s(float* Ar, float* Ai,
                                      const float* twr, const float* twi,
                                      int tid, bool col) {
    const float S2 = 0.70710678118654752440f;
    int bf = tid;
    int line = bf & 63;
    int j8 = bf >> 6;
    int blk = j8 / Q, j = j8 - blk * Q;
    int base = blk * (8 * Q) + j;
    int idx[8];
#pragma unroll
    for (int r = 0; r < 8; r++) {
        int p = base + r * Q;
        idx[r] = col ? p*65 + line : line*65 + p;
    }
    float xr[8], xi[8];
#pragma unroll
    for (int r = 0; r < 8; r++) { xr[r] = Ar[idx[r]]; xi[r] = Ai[idx[r]]; }
    if (INV) {
#pragma unroll
        for (int r = 1; r < 8; r++) {
            float wr = twr[M*j*r], wi = twi[M*j*r];
            float a = xr[r], bb = xi[r];
            xr[r] = a*wr + bb*wi;
            xi[r] = bb*wr - a*wi;
        }
    }
    float t0r=xr[0]+xr[4], t0i=xi[0]+xi[4];
    float t1r=xr[0]-xr[4], t1i=xi[0]-xi[4];
    float t2r=xr[2]+xr[6], t2i=xi[2]+xi[6];
    float d2r=xr[2]-xr[6], d2i=xi[2]-xi[6];
    float t3r, t3i;
    if (INV) { t3r = -d2i; t3i =  d2r; } else { t3r =  d2i; t3i = -d2r; }
    float e0r=t0r+t2r, e0i=t0i+t2i;
    float e1r=t1r+t3r, e1i=t1i+t3i;
    float e2r=t0r-t2r, e2i=t0i-t2i;
    float e3r=t1r-t3r, e3i=t1i-t3i;
    float u0r=xr[1]+xr[5], u0i=xi[1]+xi[5];
    float u1r=xr[1]-xr[5], u1i=xi[1]-xi[5];
    float u2r=xr[3]+xr[7], u2i=xi[3]+xi[7];
    float v2r=xr[3]-xr[7], v2i=xi[3]-xi[7];
    float u3r, u3i;
    if (INV) { u3r = -v2i; u3i =  v2r; } else { u3r =  v2i; u3i = -v2r; }
    float o0r=u0r+u2r, o0i=u0i+u2i;
    float o1r=u1r+u3r, o1i=u1i+u3i;
    float o2r=u0r-u2r, o2i=u0i-u2i;
    float o3r=u1r-u3r, o3i=u1i-u3i;
    float w1i = INV ?  S2 : -S2;
    { float a=o1r, bb=o1i; o1r = S2*a - w1i*bb; o1i = S2*bb + w1i*a; }
    { float a=o2r, bb=o2i; if (INV) { o2r = -bb; o2i = a; } else { o2r = bb; o2i = -a; } }
    { float a=o3r, bb=o3i; o3r = -S2*a - w1i*bb; o3i = -S2*bb + w1i*a; }
    float yr[8], yi[8];
    yr[0]=e0r+o0r; yi[0]=e0i+o0i;
    yr[1]=e1r+o1r; yi[1]=e1i+o1i;
    yr[2]=e2r+o2r; yi[2]=e2i+o2i;
    yr[3]=e3r+o3r; yi[3]=e3i+o3i;
    yr[4]=e0r-o0r; yi[4]=e0i-o0i;
    yr[5]=e1r-o1r; yi[5]=e1i-o1i;
    yr[6]=e2r-o2r; yi[6]=e2i-o2i;
    yr[7]=e3r-o3r; yi[7]=e3i-o3i;
    if (!INV) {
#pragma unroll
        for (int r = 1; r < 8; r++) {
            float wr = twr[M*j*r], wi = twi[M*j*r];
            float a = yr[r], bb = yi[r];
            yr[r] = a*wr - bb*wi;
            yi[r] = a*wi + bb*wr;
        }
    }
#pragma unroll
    for (int r = 0; r < 8; r++) { Ar[idx[r]] = yr[r]; Ai[idx[r]] = yi[r]; }
}

__device__ __forceinline__ void fft8_fwd_dim(float* Ar, float* Ai,
                                             const float* twr, const float* twi,
                                             int tid, bool col) {
    fft8s<8,1,false>(Ar, Ai, twr, twi, tid, col); __syncthreads();
    fft8s<1,8,false>(Ar, Ai, twr, twi, tid, col); __syncthreads();
}
__device__ __forceinline__ void fft8_inv_dim(float* Ar, float* Ai,
                                             const float* twr, const float* twi,
                                             int tid, bool col) {
    fft8s<1,8,true>(Ar, Ai, twr, twi, tid, col); __syncthreads();
    fft8s<8,1,true>(Ar, Ai, twr, twi, tid, col); __syncthreads();
}

__device__ __forceinline__ void fft_load_tw64(float* twr, float* twi, int tid) {
    if (tid < 64) {
        float s, c;
        sincosf(-6.28318530717958647692f * (float)tid * (1.0f/64.0f), &s, &c);
        twr[tid] = c; twi[tid] = s;
    }
}

// ---------------- K2: dw 3x3 + BN + ReLU + stats, 2 px/thread ----------
__global__ void __launch_bounds__(256) k_dw(const float* __restrict__ dww,
                                            const float* __restrict__ dwb,
                                            const float* __restrict__ gamma,
                                            const float* __restrict__ beta,
                                            const float* __restrict__ mean,
                                            const float* __restrict__ var) {
    int plane = blockIdx.x;
    int c = plane & (MIDC-1);
    __shared__ float tile[66*66];
    __shared__ float rs[8], rq[8];
    const __half* src = g_buf1h + (size_t)plane*HW;
    int tid = threadIdx.x;
    // interior: 2048 half2 loads
#pragma unroll
    for (int i = 0; i < 8; i++) {
        int e = tid + i*256;
        int p = e*2;
        int r = p >> 6, cc = p & 63;
        __half2 h = *(const __half2*)(src + p);
        float2 f = __half22float2(h);
        float* t = &tile[(r+1)*66 + cc + 1];
        t[0] = f.x; t[1] = f.y;
    }
    // border zeros (260 cells)
    for (int i = tid; i < 260; i += 256) {
        int a;
        if (i < 66)       a = i;
        else if (i < 132) a = 65*66 + (i - 66);
        else if (i < 196) a = (i - 131)*66;
        else              a = (i - 195)*66 + 65;
        tile[a] = 0.f;
    }
    __syncthreads();
    float w0 = dww[c*9+0], w1 = dww[c*9+1], w2 = dww[c*9+2];
    float w3 = dww[c*9+3], w4 = dww[c*9+4], w5 = dww[c*9+5];
    float w6 = dww[c*9+6], w7 = dww[c*9+7], w8 = dww[c*9+8];
    float scale = gamma[c] * rsqrtf(var[c] + 1e-5f);
    float shift = beta[c] - mean[c]*scale;
    float bia = dwb[c];
    float s = 0.f, sq = 0.f;
    __half* dst = g_xr_h + (size_t)plane*HW;
#pragma unroll
    for (int i = 0; i < 8; i++) {
        int e = tid + i*256;
        int p = e*2;
        int py = p >> 6, px = p & 63;
        const float* t0 = &tile[py*66 + px];
        float r00=t0[0],  r01=t0[1],  r02=t0[2],  r03=t0[3];
        float r10=t0[66], r11=t0[67], r12=t0[68], r13=t0[69];
        float r20=t0[132],r21=t0[133],r22=t0[134],r23=t0[135];
        float a0 = r00*w0 + r01*w1 + r02*w2
                 + r10*w3 + r11*w4 + r12*w5
                 + r20*w6 + r21*w7 + r22*w8;
        float a1 = r01*w0 + r02*w1 + r03*w2
                 + r11*w3 + r12*w4 + r13*w5
                 + r21*w6 + r22*w7 + r23*w8;
        a0 = fmaxf((a0 + bia)*scale + shift, 0.f);
        a1 = fmaxf((a1 + bia)*scale + shift, 0.f);
        *(__half2*)(dst + p) = __floats2half2_rn(a0, a1);
        s += a0 + a1; sq += a0*a0 + a1*a1;
    }
#pragma unroll
    for (int o = 16; o; o >>= 1) {
        s  += __shfl_xor_sync(0xffffffffu, s,  o);
        sq += __shfl_xor_sync(0xffffffffu, sq, o);
    }
    int wid = tid >> 5;
    if ((tid & 31) == 0) { rs[wid] = s; rq[wid] = sq; }
    __syncthreads();
    if (tid == 0) {
        float ts = 0.f, tq = 0.f;
#pragma unroll
        for (int w = 0; w < 8; w++) { ts += rs[w]; tq += rq[w]; }
        g_means[plane] = ts * (1.f/4096.f);
        g_nrm[plane]   = sqrtf(tq);   // Parseval
    }
}

// ---- K7: packed-real fwm, 2 planes/CTA, radix-8, 512 threads, gated output ----
__global__ void __launch_bounds__(512) k_fwm2() {
    __shared__ float Ar[64*65], Ai[64*65], twr[64], twi[64];
    __shared__ int mate[64];
    int pp = blockIdx.x;
    int plane0 = pp * 2;
    int b = plane0 >> 8, c0 = plane0 & (MIDC-1);
    int tid = threadIdx.x;
    const __half* x0 = g_xr_h + (size_t)plane0*HW;
    const __half* x1 = x0 + HW;
#pragma unroll
    for (int i = 0; i < 8; i++) {
        int p = tid + i*512; int r = p >> 6, cc = p & 63;
        Ar[r*65+cc] = __half2float(x0[p]);
        Ai[r*65+cc] = __half2float(x1[p]);
    }
    fft_load_tw64(twr, twi, tid);
    if (tid < 64) {
        int rv = ((tid & 7) << 3) | (tid >> 3);
        int nk = (64 - rv) & 63;
        mate[tid] = ((nk & 7) << 3) | (nk >> 3);
    }
    __syncthreads();
    fft8_fwd_dim(Ar, Ai, twr, twi, tid, false);
    fft8_fwd_dim(Ar, Ai, twr, twi, tid, true);
#pragma unroll
    for (int i = 0; i < 8; i++) {
        int p = tid + i*512; int r = p >> 6, cc = p & 63;
        int mr = mate[r], mc = mate[cc];
        int fm = mr*64 + mc;
        if (p <= fm) {
            int a  = r*65 + cc;
            int am = mr*65 + mc;
            float zpr = Ar[a],  zpi = Ai[a];
            float zmr = Ar[am], zmi = Ai[am];
            float f1r = 0.5f*(zpr + zmr), f1i = 0.5f*(zpi - zmi);
            float f2r = 0.5f*(zpi + zmi), f2i = 0.5f*(zmr - zpr);
            float W1r = f1r*f1r - f1i*f1i, W1i = 2.f*f1r*f1i;
            float W2r = f2r*f2r - f2i*f2i, W2i = 2.f*f2r*f2i;
            Ar[a]  = W1r - W2i;  Ai[a]  = W1i + W2r;
            Ar[am] = W1r + W2i;  Ai[am] = W2r - W1i;
        }
    }
    __syncthreads();
    fft8_inv_dim(Ar, Ai, twr, twi, tid, false);
    fft8_inv_dim(Ar, Ai, twr, twi, tid, true);
    float sc0 = g_gate[b*MIDC + c0]     * (1.f/262144.f);
    float sc1 = g_gate[b*MIDC + c0 + 1] * (1.f/262144.f);
    __nv_bfloat16* dst0 = g_fused_bf + ((size_t)b*INDIM + MIDC + c0)*HW;
    __nv_bfloat16* dst1 = dst0 + HW;
#pragma unroll
    for (int i = 0; i < 8; i++) {
        int p = tid + i*512; int r = p >> 6, cc = p & 63;
        int a = r*65 + cc;
        dst0[p] = __float2bfloat16(Ar[a] * sc0);
        dst1[p] = __float2bfloat16(Ai[a] * sc1);
    }
}

// ---------------- K3: SE gate MLP ----------------
__global__ void __launch_bounds__(256) k_gate(const float* __restrict__ w1,
                                              const float* __restrict__ b1,
                                              const float* __restrict__ w2,
                                              const float* __restrict__ b2) {
    int b = blockIdx.x;
    __shared__ float sm[MIDC];
    __shared__ float sh[32];
    int tid = threadIdx.x;
    sm[tid] = g_means[b*MIDC + tid];
    __syncthreads();
    if (tid < 32) {
        float a = b1[tid];
        const float* wr = w1 + tid*MIDC;
        for (int c2 = 0; c2 < MIDC; c2++) a += wr[c2]*sm[c2];
        sh[tid] = fmaxf(a, 0.f);
    }
    __syncthreads();
    float a = b2[tid];
    const float* wr = w2 + tid*32;
#pragma unroll
    for (int j = 0; j < 32; j++) a += wr[j]*sh[j];
    g_gate[b*MIDC + tid] = 1.f / (1.f + expf(-a));
}

// ---------------- K4a: spatial Gram[c,d] = sum_n xr_c(n) * xr_d(-n) ----------------
__global__ void __launch_bounds__(256) k_gram() {
    int sl = blockIdx.x, h = blockIdx.y, b = blockIdx.z;
    size_t base = ((size_t)b*MIDC + h*32) * HW;
    __shared__ float sX[32][65], sY[32][65];
    __shared__ float sRed[4][1024];
    int tid = threadIdx.x;
    int nsub = tid >> 6;
    int tt = tid & 63;
    int c0 = (tt >> 3) * 4, d0 = (tt & 7) * 4;
    float acc[4][4] = {};
    for (int n0 = 0; n0 < 512; n0 += 64) {
        int o = sl*512 + n0;
        int row = o >> 6;
        int grow = (64 - row) & 63;
        __syncthreads();
        for (int idx = tid; idx < 1024; idx += 256) {
            int cc = idx >> 5, nn = (idx & 31) * 2;
            float2 fx = __half22float2(*(const __half2*)(&g_xr_h[base + (size_t)cc*HW + o + nn]));
            sX[cc][nn] = fx.x; sX[cc][nn+1] = fx.y;
            float2 fy = __half22float2(*(const __half2*)(&g_xr_h[base + (size_t)cc*HW + grow*64 + nn]));
            sY[cc][(64 - nn) & 63] = fy.x;
            sY[cc][63 - nn]        = fy.y;
        }
        __syncthreads();
        int nlo = nsub * 16;
#pragma unroll 4
        for (int nn = nlo; nn < nlo + 16; nn++) {
            float rc[4], rd[4];
#pragma unroll
            for (int i = 0; i < 4; i++) rc[i] = sX[c0+i][nn];
#pragma unroll
            for (int j = 0; j < 4; j++) rd[j] = sY[d0+j][nn];
#pragma unroll
            for (int i = 0; i < 4; i++)
#pragma unroll
                for (int j = 0; j < 4; j++)
                    acc[i][j] += rc[i]*rd[j];
        }
    }
#pragma unroll
    for (int i = 0; i < 4; i++)
#pragma unroll
        for (int j = 0; j < 4; j++)
            sRed[nsub][tt*16 + i*4 + j] = acc[i][j];
    __syncthreads();
    float* part = g_gram_part + ((size_t)(b*HEADS + h)*8 + sl)*1024;
#pragma unroll
    for (int q = 0; q < 4; q++) {
        int e = tid*4 + q;
        int te = e >> 4, sub = e & 15;
        int i = sub >> 2, j = sub & 3;
        int c = (te >> 3)*4 + i, d = (te & 7)*4 + j;
        part[c*32 + d] = sRed[0][e] + sRed[1][e] + sRed[2][e] + sRed[3][e];
    }
}

// ---------------- K4b: reduce partials + normalize + softmax ----------------
__global__ void __launch_bounds__(256) k_soft(const float* __restrict__ temp) {
    int h = blockIdx.x, b = blockIdx.y;
    __shared__ float sA[32][33], sN[32];
    int tid = threadIdx.x;
    if (tid < 32) sN[tid] = fmaxf(g_nrm[b*MIDC + h*32 + tid], 1e-12f);
    __syncthreads();
    float tK = temp[h];
    const float* part = g_gram_part + (size_t)(b*HEADS + h)*8*1024;
#pragma unroll
    for (int q = 0; q < 4; q++) {
        int e = tid*4 + q;
        int c = e >> 5, d = e & 31;
        float v = 0.f;
#pragma unroll
        for (int s = 0; s < 8; s++) v += part[s*1024 + e];
        sA[c][d] = v * tK / (sN[c] * sN[d]);
    }
    __syncthreads();
    int lane = tid & 31;
    float* aw = g_attnW + (size_t)(b*HEADS + h)*1024;
#pragma unroll
    for (int rr = 0; rr < 4; rr++) {
        int row = (tid >> 5)*4 + rr;
        float v = sA[row][lane];
        float mx = v;
#pragma unroll
        for (int o = 16; o; o >>= 1) mx = fmaxf(mx, __shfl_xor_sync(0xffffffffu, mx, o));
        float e = expf(v - mx);
        float smv = e;
#pragma unroll
        for (int o = 16; o; o >>= 1) smv += __shfl_xor_sync(0xffffffffu, smv, o);
        aw[row*32 + lane] = e / smv;
    }
}

// ---- K4c: spatial mix: out[c](n) = sum_d A[c,d]*(xr_d(n)+xr_d(-n))/2 ----
__global__ void __launch_bounds__(256) k_mix() {
    int sl = blockIdx.x, h = blockIdx.y, b = blockIdx.z;
    size_t base = ((size_t)b*MIDC + h*32) * HW;
    __shared__ float sA[32][33];
    __shared__ float sS[32][65];
    int tid = threadIdx.x;
    const float* aw = g_attnW + (size_t)(b*HEADS + h)*1024;
#pragma unroll
    for (int q = 0; q < 4; q++) {
        int e = tid*4 + q;
        sA[e >> 5][e & 31] = aw[e];
    }
    int cm = (tid >> 4) * 2;
    int nm = (tid & 15) * 4;
    for (int n0 = 0; n0 < 512; n0 += 64) {
        int o = sl*512 + n0;
        int row = o >> 6;
        int grow = (64 - row) & 63;
        __syncthreads();
        // pass 1: forward half
        for (int idx = tid; idx < 1024; idx += 256) {
            int cc = idx >> 5, nn = (idx & 31) * 2;
            float2 fa = __half22float2(*(const __half2*)(&g_xr_h[base + (size_t)cc*HW + o + nn]));
            sS[cc][nn]   = 0.5f * fa.x;
            sS[cc][nn+1] = 0.5f * fa.y;
        }
        __syncthreads();
        // pass 2: add reversed half (distinct addresses per thread)
        for (int idx = tid; idx < 1024; idx += 256) {
            int cc = idx >> 5, nn = (idx & 31) * 2;
            float2 fb = __half22float2(*(const __half2*)(&g_xr_h[base + (size_t)cc*HW + grow*64 + nn]));
            sS[cc][(64 - nn) & 63] += 0.5f * fb.x;
            sS[cc][63 - nn]        += 0.5f * fb.y;
        }
        __syncthreads();
        float o0[4] = {}, o1[4] = {};
#pragma unroll
        for (int d = 0; d < 32; d++) {
            float a0 = sA[cm][d], a1 = sA[cm+1][d];
            float f0 = sS[d][nm], f1 = sS[d][nm+1], f2 = sS[d][nm+2], f3 = sS[d][nm+3];
            o0[0] += a0*f0; o0[1] += a0*f1; o0[2] += a0*f2; o0[3] += a0*f3;
            o1[0] += a1*f0; o1[1] += a1*f1; o1[2] += a1*f2; o1[3] += a1*f3;
        }
        __nv_bfloat162 q00 = __floats2bfloat162_rn(o0[0], o0[1]);
        __nv_bfloat162 q01 = __floats2bfloat162_rn(o0[2], o0[3]);
        __nv_bfloat162 q10 = __floats2bfloat162_rn(o1[0], o1[1]);
        __nv_bfloat162 q11 = __floats2bfloat162_rn(o1[2], o1[3]);
        uint2 pk0, pk1;
        pk0.x = *(uint32_t*)&q00; pk0.y = *(uint32_t*)&q01;
        pk1.x = *(uint32_t*)&q10; pk1.y = *(uint32_t*)&q11;
        size_t fb2 = ((size_t)b*INDIM + h*32) * HW;
        *(uint2*)&g_fused_bf[fb2 + (size_t)cm*HW + o + nm]     = pk0;
        *(uint2*)&g_fused_bf[fb2 + (size_t)(cm+1)*HW + o + nm] = pk1;
    }
}

// ---------------- launch ----------------
extern "C" void kernel_launch(void* const* d_in, const int* in_sizes, int n_in,
                              void* d_out, int out_size) {
    (void)in_sizes; (void)n_in; (void)out_size;
    const float* x        = (const float*)d_in[0];
    const float* reduce_w = (const float*)d_in[1];
    const float* reduce_b = (const float*)d_in[2];
    const float* dw_w     = (const float*)d_in[3];
    const float* dw_b     = (const float*)d_in[4];
    const float* bn_gamma = (const float*)d_in[5];
    const float* bn_beta  = (const float*)d_in[6];
    const float* bn_mean  = (const float*)d_in[7];
    const float* bn_var   = (const float*)d_in[8];
    const float* gate_w1  = (const float*)d_in[9];
    const float* gate_b1  = (const float*)d_in[10];
    const float* gate_w2  = (const float*)d_in[11];
    const float* gate_b2  = (const float*)d_in[12];
    const float* temp     = (const float*)d_in[13];
    const float* post_w   = (const float*)d_in[14];
    const float* post_b   = (const float*)d_in[15];
    float* out = (float*)d_out;

    cudaFuncSetAttribute((const void*)k_gemm_red,
                         cudaFuncAttributeMaxDynamicSharedMemorySize, GEMM_SMEM);
    cudaFuncSetAttribute((const void*)k_gemm_pipe,
                         cudaFuncAttributeMaxDynamicSharedMemorySize, GEMM_SMEM);

    __nv_bfloat16 *p_fbf, *p_wred, *p_wpost;
    cudaGetSymbolAddress((void**)&p_fbf,   g_fused_bf);
    cudaGetSymbolAddress((void**)&p_wred,  g_wred);
    cudaGetSymbolAddress((void**)&p_wpost, g_wpost);
    __half* p_buf1h;
    cudaGetSymbolAddress((void**)&p_buf1h, g_buf1h);

    // merged weight conversions
    int n1 = MIDC*INDIM, n2 = INDIM*2*MIDC;
    k_cvt2<<<((n1+n2)/4 + 255)/256, 256>>>(reduce_w, p_wred, n1, post_w, p_wpost, n2);

    // reduce GEMM (fp32 act staged via cp.async, converted in smem) -> fp16
    k_gemm_red<<<dim3(32, 2, BATCH), 256, GEMM_SMEM>>>(
        p_wred, x, reduce_b, p_buf1h, MIDC);

    // dw + BN + ReLU + stats -> xr fp16 (2 px/thread)
    k_dw<<<BATCH*MIDC, 256>>>(dw_w, dw_b, bn_gamma, bn_beta, bn_mean, bn_var);
    k_gate<<<BATCH, 256>>>(gate_w1, gate_b1, gate_w2, gate_b2);

    // packed-real fwm (2 planes per CTA, radix-8, 512 threads)
    k_fwm2<<<BATCH*MIDC/2, 512>>>();

    // spatial attention
    k_gram<<<dim3(8, HEADS, BATCH), 256>>>();
    k_soft<<<dim3(HEADS, BATCH), 256>>>(temp);
    k_mix<<<dim3(8, HEADS, BATCH), 256>>>();

    // post GEMM (cp.async pipelined, bias + residual)
    k_gemm_pipe<<<dim3(32, 4, BATCH), 256, GEMM_SMEM>>>(
        p_wpost, p_fbf, post_b, x, out, INDIM);
}

// round 11
// speedup vs baseline: 2.3790x; 1.0623x over previous
#include <cuda_runtime.h>
#include <cuda_bf16.h>
#include <cuda_fp16.h>
#include <mma.h>
#include <math.h>
#include <stdint.h>

using namespace nvcuda;

#define BATCH 16
#define INDIM 512
#define MIDC  256
#define HW    4096
#define HEADS 8

// ---------------- scratch (device globals; no allocation) ----------------
__device__ __half g_buf1h[BATCH*MIDC*HW];   // reduce-GEMM output (pre-dw), fp16
__device__ __half g_xr_h[BATCH*MIDC*HW];    // xr (post dw+BN+ReLU), fp16, spatial
__device__ float  g_means[BATCH*MIDC];
__device__ float  g_nrm  [BATCH*MIDC];
__device__ float  g_gate [BATCH*MIDC];
__device__ float  g_gram_part[BATCH*HEADS*8*1024];
__device__ float  g_attnW[BATCH*HEADS*1024];
__device__ __nv_bfloat16 g_fused_bf[BATCH*INDIM*HW]; // [attn_out | gated fwm]
__device__ __nv_bfloat16 g_wred    [MIDC*INDIM];
__device__ __nv_bfloat16 g_wpost   [INDIM*2*MIDC];

// ================= GEMM common =================
#define AS_STRIDE 40
#define BS_STRIDE 136
#define BF_STRIDE 132
#define CS_STRIDE 132
#define GEMM_SMEM (128*CS_STRIDE*4)

__device__ __forceinline__ void cp16(void* sdst, const void* gsrc) {
    uint32_t a = (uint32_t)__cvta_generic_to_shared(sdst);
    asm volatile("cp.async.cg.shared.global [%0], [%1], 16;\n" :: "r"(a), "l"(gsrc));
}
#define CP_COMMIT() asm volatile("cp.async.commit_group;\n" ::: "memory")
#define CP_WAIT(n)  asm volatile("cp.async.wait_group %0;\n" :: "n"(n) : "memory")

__device__ __forceinline__ void mma_step(
    const __nv_bfloat16* As, const __nv_bfloat16* Bs, int wm, int wn,
    wmma::fragment<wmma::accumulator, 16, 16, 16, float> acc[2][4]) {
#pragma unroll
    for (int ks = 0; ks < 2; ks++) {
        wmma::fragment<wmma::matrix_a, 16, 16, 16, __nv_bfloat16, wmma::row_major> af[2];
        wmma::fragment<wmma::matrix_b, 16, 16, 16, __nv_bfloat16, wmma::row_major> bf[4];
#pragma unroll
        for (int i = 0; i < 2; i++)
            wmma::load_matrix_sync(af[i], As + (wm*32 + i*16) * AS_STRIDE + ks*16, AS_STRIDE);
#pragma unroll
        for (int j = 0; j < 4; j++)
            wmma::load_matrix_sync(bf[j], Bs + (ks*16) * BS_STRIDE + wn*64 + j*16, BS_STRIDE);
#pragma unroll
        for (int i = 0; i < 2; i++)
#pragma unroll
            for (int j = 0; j < 4; j++)
                wmma::mma_sync(acc[i][j], af[i], bf[j], acc[i][j]);
    }
}

// ---------------- reduce GEMM: fp32 act, cp.async-staged + smem convert -----------
__global__ void __launch_bounds__(256)
k_gemm_red(const __nv_bfloat16* __restrict__ W,
           const float* __restrict__ act,
           const float* __restrict__ bias,
           __half* __restrict__ out,
           int Mtot) {
    extern __shared__ char sm[];
    __nv_bfloat16* As0 = (__nv_bfloat16*)sm;
    float*         Bf0 = (float*)(sm + 2*128*AS_STRIDE*2);
    __nv_bfloat16* Bs  = (__nv_bfloat16*)(sm + 2*128*AS_STRIDE*2 + 2*32*BF_STRIDE*4);
    float*         Cs  = (float*)sm;

    int tid = threadIdx.x;
    int w   = tid >> 5;
    int wm  = w & 3;
    int wn  = w >> 2;
    int nb = blockIdx.x * 128, mb = blockIdx.y * 128, b = blockIdx.z;

    const __nv_bfloat16* Ag = W + (size_t)mb * 512;
    const float* Bg = act + (size_t)b * 512 * 4096 + nb;

    int ar0 = tid >> 2,  ac0 = (tid & 3) * 8;
    int br0 = tid >> 5,  bs0 = (tid & 31) * 4;

    wmma::fragment<wmma::accumulator, 16, 16, 16, float> acc[2][4];
#pragma unroll
    for (int i = 0; i < 2; i++)
#pragma unroll
        for (int j = 0; j < 4; j++) wmma::fill_fragment(acc[i][j], 0.0f);

    {
#pragma unroll
        for (int t = 0; t < 2; t++) {
            int r = ar0 + t*64;
            cp16(As0 + r*AS_STRIDE + ac0, Ag + (size_t)r*512 + ac0);
        }
#pragma unroll
        for (int t = 0; t < 4; t++) {
            int r = br0 + t*8;
            cp16(Bf0 + r*BF_STRIDE + bs0, Bg + (size_t)r*4096 + bs0);
        }
        CP_COMMIT();
    }

    for (int it = 0; it < 16; it++) {
        int cur = it & 1;
        if (it < 15) {
            int kc = (it + 1) * 32;
            __nv_bfloat16* As = As0 + (cur^1)*128*AS_STRIDE;
            float*         Bf = Bf0 + (cur^1)*32*BF_STRIDE;
#pragma unroll
            for (int t = 0; t < 2; t++) {
                int r = ar0 + t*64;
                cp16(As + r*AS_STRIDE + ac0, Ag + (size_t)r*512 + kc + ac0);
            }
#pragma unroll
            for (int t = 0; t < 4; t++) {
                int r = br0 + t*8;
                cp16(Bf + r*BF_STRIDE + bs0, Bg + (size_t)(kc + r)*4096 + bs0);
            }
            CP_COMMIT();
            CP_WAIT(1);
        } else {
            CP_WAIT(0);
        }
        __syncthreads();
        const float* Bf = Bf0 + cur*32*BF_STRIDE;
#pragma unroll
        for (int t = 0; t < 8; t++) {
            int e2 = (tid + t*256) * 2;
            int r = e2 >> 7, c = e2 & 127;
            __nv_bfloat162 pk = __floats2bfloat162_rn(Bf[r*BF_STRIDE + c],
                                                      Bf[r*BF_STRIDE + c + 1]);
            *(uint32_t*)(Bs + r*BS_STRIDE + c) = *(uint32_t*)&pk;
        }
        __syncthreads();
        mma_step(As0 + cur*128*AS_STRIDE, Bs, wm, wn, acc);
        __syncthreads();
    }
#pragma unroll
    for (int i = 0; i < 2; i++)
#pragma unroll
        for (int j = 0; j < 4; j++)
            wmma::store_matrix_sync(Cs + (wm*32 + i*16) * CS_STRIDE + wn*64 + j*16,
                                    acc[i][j], CS_STRIDE, wmma::mem_row_major);
    __syncthreads();
#pragma unroll
    for (int t = 0; t < 16; t++) {
        int id = tid + t * 256;
        int r = id >> 5, c = (id & 31) * 4;
        float bi = bias[mb + r];
        float4 v = *(float4*)(Cs + r * CS_STRIDE + c);
        __half2 h0 = __floats2half2_rn(v.x + bi, v.y + bi);
        __half2 h1 = __floats2half2_rn(v.z + bi, v.w + bi);
        uint2 pk; pk.x = *(uint32_t*)&h0; pk.y = *(uint32_t*)&h1;
        size_t off = ((size_t)b * Mtot + mb + r) * 4096 + nb + c;
        *(uint2*)(out + off) = pk;
    }
}

// ---------------- post GEMM: bf16 act, cp.async 2-stage pipeline ----------------
__global__ void __launch_bounds__(256)
k_gemm_pipe(const __nv_bfloat16* __restrict__ W,
            const __nv_bfloat16* __restrict__ act,
            const float* __restrict__ bias,
            const float* __restrict__ resid,
            float* __restrict__ out,
            int Mtot) {
    extern __shared__ char sm[];
    __nv_bfloat16* As0 = (__nv_bfloat16*)sm;
    __nv_bfloat16* Bs0 = (__nv_bfloat16*)(sm + 2*128*AS_STRIDE*2);
    float*         Cs  = (float*)sm;

    int tid = threadIdx.x;
    int w   = tid >> 5;
    int wm  = w & 3;
    int wn  = w >> 2;
    int nb = blockIdx.x * 128, mb = blockIdx.y * 128, b = blockIdx.z;

    const __nv_bfloat16* Ag = W + (size_t)mb * 512;
    const __nv_bfloat16* Bg = act + (size_t)b * 512 * 4096 + nb;

    int ar0 = tid >> 2,  ac0 = (tid & 3) * 8;
    int br0 = tid >> 4,  bc0 = (tid & 15) * 8;

    wmma::fragment<wmma::accumulator, 16, 16, 16, float> acc[2][4];
#pragma unroll
    for (int i = 0; i < 2; i++)
#pragma unroll
        for (int j = 0; j < 4; j++) wmma::fill_fragment(acc[i][j], 0.0f);

    {
#pragma unroll
        for (int t = 0; t < 2; t++) {
            int r = ar0 + t*64;
            cp16(As0 + r*AS_STRIDE + ac0, Ag + (size_t)r*512 + ac0);
        }
#pragma unroll
        for (int t = 0; t < 2; t++) {
            int r = br0 + t*16;
            cp16(Bs0 + r*BS_STRIDE + bc0, Bg + (size_t)r*4096 + bc0);
        }
        CP_COMMIT();
    }

    for (int it = 0; it < 16; it++) {
        int cur = it & 1;
        if (it < 15) {
            int kc = (it + 1) * 32;
            __nv_bfloat16* As = As0 + (cur^1)*128*AS_STRIDE;
            __nv_bfloat16* Bs = Bs0 + (cur^1)*32*BS_STRIDE;
#pragma unroll
            for (int t = 0; t < 2; t++) {
                int r = ar0 + t*64;
                cp16(As + r*AS_STRIDE + ac0, Ag + (size_t)r*512 + kc + ac0);
            }
#pragma unroll
            for (int t = 0; t < 2; t++) {
                int r = br0 + t*16;
                cp16(Bs + r*BS_STRIDE + bc0, Bg + (size_t)(kc + r)*4096 + bc0);
            }
            CP_COMMIT();
            CP_WAIT(1);
        } else {
            CP_WAIT(0);
        }
        __syncthreads();
        mma_step(As0 + cur*128*AS_STRIDE, Bs0 + cur*32*BS_STRIDE, wm, wn, acc);
        __syncthreads();
    }
#pragma unroll
    for (int i = 0; i < 2; i++)
#pragma unroll
        for (int j = 0; j < 4; j++)
            wmma::store_matrix_sync(Cs + (wm*32 + i*16) * CS_STRIDE + wn*64 + j*16,
                                    acc[i][j], CS_STRIDE, wmma::mem_row_major);
    __syncthreads();
#pragma unroll
    for (int t = 0; t < 16; t++) {
        int id = tid + t * 256;
        int r = id >> 5, c = (id & 31) * 4;
        float bi = bias[mb + r];
        float4 v = *(float4*)(Cs + r * CS_STRIDE + c);
        v.x += bi; v.y += bi; v.z += bi; v.w += bi;
        size_t off = ((size_t)b * Mtot + mb + r) * 4096 + nb + c;
        float4 rr = *(const float4*)(resid + off);
        v.x += rr.x; v.y += rr.y; v.z += rr.z; v.w += rr.w;
        *(float4*)(out + off) = v;
    }
}

// ---------------- merged weight conversion ----------------
__global__ void __launch_bounds__(256) k_cvt2(const float* __restrict__ s1,
                                              __nv_bfloat16* __restrict__ d1, int n1,
                                              const float* __restrict__ s2,
                                              __nv_bfloat16* __restrict__ d2, int n2) {
    int i = (blockIdx.x * 256 + threadIdx.x) * 4;
    const float* src; __nv_bfloat16* dst; int idx;
    if (i < n1) { src = s1; dst = d1; idx = i; }
    else { idx = i - n1; if (idx >= n2) return; src = s2; dst = d2; }
    float4 v = *(const float4*)(src + idx);
    __nv_bfloat162 p0 = __floats2bfloat162_rn(v.x, v.y);
    __nv_bfloat162 p1 = __floats2bfloat162_rn(v.z, v.w);
    uint2 pk;
    pk.x = *(uint32_t*)&p0; pk.y = *(uint32_t*)&p1;
    *(uint2*)(dst + idx) = pk;
}

// ================= radix-8 FFT (64-pt, 2 stages/dim, 512 threads, 1 bfly/thr) ======
template<int Q, int M, bool INV>
__device__ __forceinline__ void fft8s(float* Ar, float* Ai,
                                      const float* twr, const float* twi,
                                      int tid, bool col) {
    const float S2 = 0.70710678118654752440f;
    int bf = tid;
    int line = bf & 63;
    int j8 = bf >> 6;
    int blk = j8 / Q, j = j8 - blk * Q;
    int base = blk * (8 * Q) + j;
    int idx[8];
#pragma unroll
    for (int r = 0; r < 8; r++) {
        int p = base + r * Q;
        idx[r] = col ? p*65 + line : line*65 + p;
    }
    float xr[8], xi[8];
#pragma unroll
    for (int r = 0; r < 8; r++) { xr[r] = Ar[idx[r]]; xi[r] = Ai[idx[r]]; }
    if (INV) {
#pragma unroll
        for (int r = 1; r < 8; r++) {
            float wr = twr[M*j*r], wi = twi[M*j*r];
            float a = xr[r], bb = xi[r];
            xr[r] = a*wr + bb*wi;
            xi[r] = bb*wr - a*wi;
        }
    }
    float t0r=xr[0]+xr[4], t0i=xi[0]+xi[4];
    float t1r=xr[0]-xr[4], t1i=xi[0]-xi[4];
    float t2r=xr[2]+xr[6], t2i=xi[2]+xi[6];
    float d2r=xr[2]-xr[6], d2i=xi[2]-xi[6];
    float t3r, t3i;
    if (INV) { t3r = -d2i; t3i =  d2r; } else { t3r =  d2i; t3i = -d2r; }
    float e0r=t0r+t2r, e0i=t0i+t2i;
    float e1r=t1r+t3r, e1i=t1i+t3i;
    float e2r=t0r-t2r, e2i=t0i-t2i;
    float e3r=t1r-t3r, e3i=t1i-t3i;
    float u0r=xr[1]+xr[5], u0i=xi[1]+xi[5];
    float u1r=xr[1]-xr[5], u1i=xi[1]-xi[5];
    float u2r=xr[3]+xr[7], u2i=xi[3]+xi[7];
    float v2r=xr[3]-xr[7], v2i=xi[3]-xi[7];
    float u3r, u3i;
    if (INV) { u3r = -v2i; u3i =  v2r; } else { u3r =  v2i; u3i = -v2r; }
    float o0r=u0r+u2r, o0i=u0i+u2i;
    float o1r=u1r+u3r, o1i=u1i+u3i;
    float o2r=u0r-u2r, o2i=u0i-u2i;
    float o3r=u1r-u3r, o3i=u1i-u3i;
    float w1i = INV ?  S2 : -S2;
    { float a=o1r, bb=o1i; o1r = S2*a - w1i*bb; o1i = S2*bb + w1i*a; }
    { float a=o2r, bb=o2i; if (INV) { o2r = -bb; o2i = a; } else { o2r = bb; o2i = -a; } }
    { float a=o3r, bb=o3i; o3r = -S2*a - w1i*bb; o3i = -S2*bb + w1i*a; }
    float yr[8], yi[8];
    yr[0]=e0r+o0r; yi[0]=e0i+o0i;
    yr[1]=e1r+o1r; yi[1]=e1i+o1i;
    yr[2]=e2r+o2r; yi[2]=e2i+o2i;
    yr[3]=e3r+o3r; yi[3]=e3i+o3i;
    yr[4]=e0r-o0r; yi[4]=e0i-o0i;
    yr[5]=e1r-o1r; yi[5]=e1i-o1i;
    yr[6]=e2r-o2r; yi[6]=e2i-o2i;
    yr[7]=e3r-o3r; yi[7]=e3i-o3i;
    if (!INV) {
#pragma unroll
        for (int r = 1; r < 8; r++) {
            float wr = twr[M*j*r], wi = twi[M*j*r];
            float a = yr[r], bb = yi[r];
            yr[r] = a*wr - bb*wi;
            yi[r] = a*wi + bb*wr;
        }
    }
#pragma unroll
    for (int r = 0; r < 8; r++) { Ar[idx[r]] = yr[r]; Ai[idx[r]] = yi[r]; }
}

__device__ __forceinline__ void fft8_fwd_dim(float* Ar, float* Ai,
                                             const float* twr, const float* twi,
                                             int tid, bool col) {
    fft8s<8,1,false>(Ar, Ai, twr, twi, tid, col); __syncthreads();
    fft8s<1,8,false>(Ar, Ai, twr, twi, tid, col); __syncthreads();
}
__device__ __forceinline__ void fft8_inv_dim(float* Ar, float* Ai,
                                             const float* twr, const float* twi,
                                             int tid, bool col) {
    fft8s<1,8,true>(Ar, Ai, twr, twi, tid, col); __syncthreads();
    fft8s<8,1,true>(Ar, Ai, twr, twi, tid, col); __syncthreads();
}

__device__ __forceinline__ void fft_load_tw64(float* twr, float* twi, int tid) {
    if (tid < 64) {
        float s, c;
        sincosf(-6.28318530717958647692f * (float)tid * (1.0f/64.0f), &s, &c);
        twr[tid] = c; twi[tid] = s;
    }
}

// ---------------- K2: dw 3x3 + BN + ReLU + stats, 2 px/thread ----------
__global__ void __launch_bounds__(256) k_dw(const float* __restrict__ dww,
                                            const float* __restrict__ dwb,
                                            const float* __restrict__ gamma,
                                            const float* __restrict__ beta,
                                            const float* __restrict__ mean,
                                            const float* __restrict__ var) {
    int plane = blockIdx.x;
    int c = plane & (MIDC-1);
    __shared__ float tile[66*66];
    __shared__ float rs[8], rq[8];
    const __half* src = g_buf1h + (size_t)plane*HW;
    int tid = threadIdx.x;
#pragma unroll
    for (int i = 0; i < 8; i++) {
        int e = tid + i*256;
        int p = e*2;
        int r = p >> 6, cc = p & 63;
        __half2 h = *(const __half2*)(src + p);
        float2 f = __half22float2(h);
        float* t = &tile[(r+1)*66 + cc + 1];
        t[0] = f.x; t[1] = f.y;
    }
    for (int i = tid; i < 260; i += 256) {
        int a;
        if (i < 66)       a = i;
        else if (i < 132) a = 65*66 + (i - 66);
        else if (i < 196) a = (i - 131)*66;
        else              a = (i - 195)*66 + 65;
        tile[a] = 0.f;
    }
    __syncthreads();
    float w0 = dww[c*9+0], w1 = dww[c*9+1], w2 = dww[c*9+2];
    float w3 = dww[c*9+3], w4 = dww[c*9+4], w5 = dww[c*9+5];
    float w6 = dww[c*9+6], w7 = dww[c*9+7], w8 = dww[c*9+8];
    float scale = gamma[c] * rsqrtf(var[c] + 1e-5f);
    float shift = beta[c] - mean[c]*scale;
    float bia = dwb[c];
    float s = 0.f, sq = 0.f;
    __half* dst = g_xr_h + (size_t)plane*HW;
#pragma unroll
    for (int i = 0; i < 8; i++) {
        int e = tid + i*256;
        int p = e*2;
        int py = p >> 6, px = p & 63;
        const float* t0 = &tile[py*66 + px];
        float r00=t0[0],  r01=t0[1],  r02=t0[2],  r03=t0[3];
        float r10=t0[66], r11=t0[67], r12=t0[68], r13=t0[69];
        float r20=t0[132],r21=t0[133],r22=t0[134],r23=t0[135];
        float a0 = r00*w0 + r01*w1 + r02*w2
                 + r10*w3 + r11*w4 + r12*w5
                 + r20*w6 + r21*w7 + r22*w8;
        float a1 = r01*w0 + r02*w1 + r03*w2
                 + r11*w3 + r12*w4 + r13*w5
                 + r21*w6 + r22*w7 + r23*w8;
        a0 = fmaxf((a0 + bia)*scale + shift, 0.f);
        a1 = fmaxf((a1 + bia)*scale + shift, 0.f);
        *(__half2*)(dst + p) = __floats2half2_rn(a0, a1);
        s += a0 + a1; sq += a0*a0 + a1*a1;
    }
#pragma unroll
    for (int o = 16; o; o >>= 1) {
        s  += __shfl_xor_sync(0xffffffffu, s,  o);
        sq += __shfl_xor_sync(0xffffffffu, sq, o);
    }
    int wid = tid >> 5;
    if ((tid & 31) == 0) { rs[wid] = s; rq[wid] = sq; }
    __syncthreads();
    if (tid == 0) {
        float ts = 0.f, tq = 0.f;
#pragma unroll
        for (int w = 0; w < 8; w++) { ts += rs[w]; tq += rq[w]; }
        g_means[plane] = ts * (1.f/4096.f);
        g_nrm[plane]   = sqrtf(tq);   // Parseval
    }
}

// ---- K7: packed-real fwm, 2 planes/CTA, radix-8, 512 threads, gated output ----
__global__ void __launch_bounds__(512) k_fwm2() {
    __shared__ float Ar[64*65], Ai[64*65], twr[64], twi[64];
    __shared__ int mate[64];
    int pp = blockIdx.x;
    int plane0 = pp * 2;
    int b = plane0 >> 8, c0 = plane0 & (MIDC-1);
    int tid = threadIdx.x;
    const __half* x0 = g_xr_h + (size_t)plane0*HW;
    const __half* x1 = x0 + HW;
#pragma unroll
    for (int i = 0; i < 8; i++) {
        int p = tid + i*512; int r = p >> 6, cc = p & 63;
        Ar[r*65+cc] = __half2float(x0[p]);
        Ai[r*65+cc] = __half2float(x1[p]);
    }
    fft_load_tw64(twr, twi, tid);
    if (tid < 64) {
        int rv = ((tid & 7) << 3) | (tid >> 3);
        int nk = (64 - rv) & 63;
        mate[tid] = ((nk & 7) << 3) | (nk >> 3);
    }
    __syncthreads();
    fft8_fwd_dim(Ar, Ai, twr, twi, tid, false);
    fft8_fwd_dim(Ar, Ai, twr, twi, tid, true);
#pragma unroll
    for (int i = 0; i < 8; i++) {
        int p = tid + i*512; int r = p >> 6, cc = p & 63;
        int mr = mate[r], mc = mate[cc];
        int fm = mr*64 + mc;
        if (p <= fm) {
            int a  = r*65 + cc;
            int am = mr*65 + mc;
            float zpr = Ar[a],  zpi = Ai[a];
            float zmr = Ar[am], zmi = Ai[am];
            float f1r = 0.5f*(zpr + zmr), f1i = 0.5f*(zpi - zmi);
            float f2r = 0.5f*(zpi + zmi), f2i = 0.5f*(zmr - zpr);
            float W1r = f1r*f1r - f1i*f1i, W1i = 2.f*f1r*f1i;
            float W2r = f2r*f2r - f2i*f2i, W2i = 2.f*f2r*f2i;
            Ar[a]  = W1r - W2i;  Ai[a]  = W1i + W2r;
            Ar[am] = W1r + W2i;  Ai[am] = W2r - W1i;
        }
    }
    __syncthreads();
    fft8_inv_dim(Ar, Ai, twr, twi, tid, false);
    fft8_inv_dim(Ar, Ai, twr, twi, tid, true);
    float sc0 = g_gate[b*MIDC + c0]     * (1.f/262144.f);
    float sc1 = g_gate[b*MIDC + c0 + 1] * (1.f/262144.f);
    __nv_bfloat16* dst0 = g_fused_bf + ((size_t)b*INDIM + MIDC + c0)*HW;
    __nv_bfloat16* dst1 = dst0 + HW;
#pragma unroll
    for (int i = 0; i < 8; i++) {
        int p = tid + i*512; int r = p >> 6, cc = p & 63;
        int a = r*65 + cc;
        dst0[p] = __float2bfloat16(Ar[a] * sc0);
        dst1[p] = __float2bfloat16(Ai[a] * sc1);
    }
}

// ---------------- K3: SE gate MLP (parallel reduction) ----------------
__global__ void __launch_bounds__(256) k_gate(const float* __restrict__ w1,
                                              const float* __restrict__ b1,
                                              const float* __restrict__ w2,
                                              const float* __restrict__ b2) {
    int b = blockIdx.x;
    __shared__ float sm[MIDC];
    __shared__ float sh[32];
    int tid = threadIdx.x;
    sm[tid] = g_means[b*MIDC + tid];
    __syncthreads();
    // layer 1: 32 outputs, 8 threads each (consecutive lanes)
    {
        int o = tid >> 3, part = tid & 7;
        const float* wr = w1 + o*MIDC + part*32;
        const float* mr = sm + part*32;
        float a = 0.f;
#pragma unroll
        for (int j = 0; j < 32; j++) a += wr[j]*mr[j];
#pragma unroll
        for (int off = 4; off; off >>= 1)
            a += __shfl_down_sync(0xffffffffu, a, off, 8);
        if (part == 0) sh[o] = fmaxf(a + b1[o], 0.f);
    }
    __syncthreads();
    // layer 2: 256 outputs, 1 thread each (k=32)
    float a = b2[tid];
    const float* wr = w2 + tid*32;
#pragma unroll
    for (int j = 0; j < 32; j++) a += wr[j]*sh[j];
    g_gate[b*MIDC + tid] = 1.f / (1.f + expf(-a));
}

// ------- K4a: spatial Gram via wmma: C[32,32] = X[32,512] * Y^T, fp16 in / fp32 acc ---
#define GX_STRIDE 72
__global__ void __launch_bounds__(256) k_gram() {
    int sl = blockIdx.x, h = blockIdx.y, b = blockIdx.z;
    size_t base = ((size_t)b*MIDC + h*32) * HW;
    __shared__ __align__(16) __half sX[32*GX_STRIDE];
    __shared__ __align__(16) __half sY[32*GX_STRIDE];
    __shared__ float sC[8][256];
    int tid = threadIdx.x;
    int warp = tid >> 5;
    int tile = warp & 3;          // 2x2 C tiles: ti = tile>>1 (rows), tj = tile&1 (cols)
    int kgrp = warp >> 2;         // n0-iteration parity handled by this warp
    int ti = tile >> 1, tj = tile & 1;

    wmma::fragment<wmma::accumulator, 16, 16, 16, float> acc;
    wmma::fill_fragment(acc, 0.0f);

    for (int it = 0; it < 8; it++) {
        int o = sl*512 + it*64;
        int row = o >> 6;
        int grow = (64 - row) & 63;
        __syncthreads();
        for (int idx = tid; idx < 1024; idx += 256) {
            int cc = idx >> 5, nn = (idx & 31) * 2;
            __half2 hx = *(const __half2*)(&g_xr_h[base + (size_t)cc*HW + o + nn]);
            sX[cc*GX_STRIDE + nn]     = __low2half(hx);
            sX[cc*GX_STRIDE + nn + 1] = __high2half(hx);
            __half2 hy = *(const __half2*)(&g_xr_h[base + (size_t)cc*HW + grow*64 + nn]);
            sY[cc*GX_STRIDE + ((64 - nn) & 63)] = __low2half(hy);
            sY[cc*GX_STRIDE + 63 - nn]          = __high2half(hy);
        }
        __syncthreads();
        if ((it & 1) == kgrp) {
#pragma unroll
            for (int ks = 0; ks < 4; ks++) {
                wmma::fragment<wmma::matrix_a, 16, 16, 16, __half, wmma::row_major> af;
                wmma::fragment<wmma::matrix_b, 16, 16, 16, __half, wmma::col_major> bf;
                wmma::load_matrix_sync(af, sX + (ti*16)*GX_STRIDE + ks*16, GX_STRIDE);
                wmma::load_matrix_sync(bf, sY + (tj*16)*GX_STRIDE + ks*16, GX_STRIDE);
                wmma::mma_sync(acc, af, bf, acc);
            }
        }
    }
    __syncthreads();
    wmma::store_matrix_sync(sC[warp], acc, 16, wmma::mem_row_major);
    __syncthreads();
    float* part = g_gram_part + ((size_t)(b*HEADS + h)*8 + sl)*1024;
    for (int e = tid; e < 1024; e += 256) {
        int c = e >> 5, d = e & 31;
        int t = (c >> 4)*2 + (d >> 4);
        int lr = c & 15, lc = d & 15;
        part[e] = sC[t][lr*16 + lc] + sC[t+4][lr*16 + lc];
    }
}

// ---------------- K4b: reduce partials + normalize + softmax ----------------
__global__ void __launch_bounds__(256) k_soft(const float* __restrict__ temp) {
    int h = blockIdx.x, b = blockIdx.y;
    __shared__ float sA[32][33], sN[32];
    int tid = threadIdx.x;
    if (tid < 32) sN[tid] = fmaxf(g_nrm[b*MIDC + h*32 + tid], 1e-12f);
    __syncthreads();
    float tK = temp[h];
    const float* part = g_gram_part + (size_t)(b*HEADS + h)*8*1024;
#pragma unroll
    for (int q = 0; q < 4; q++) {
        int e = tid*4 + q;
        int c = e >> 5, d = e & 31;
        float v = 0.f;
#pragma unroll
        for (int s = 0; s < 8; s++) v += part[s*1024 + e];
        sA[c][d] = v * tK / (sN[c] * sN[d]);
    }
    __syncthreads();
    int lane = tid & 31;
    float* aw = g_attnW + (size_t)(b*HEADS + h)*1024;
#pragma unroll
    for (int rr = 0; rr < 4; rr++) {
        int row = (tid >> 5)*4 + rr;
        float v = sA[row][lane];
        float mx = v;
#pragma unroll
        for (int o = 16; o; o >>= 1) mx = fmaxf(mx, __shfl_xor_sync(0xffffffffu, mx, o));
        float e = expf(v - mx);
        float smv = e;
#pragma unroll
        for (int o = 16; o; o >>= 1) smv += __shfl_xor_sync(0xffffffffu, smv, o);
        aw[row*32 + lane] = e / smv;
    }
}

// ---- K4c: spatial mix: out[c](n) = sum_d A[c,d]*(xr_d(n)+xr_d(-n))/2 ----
__global__ void __launch_bounds__(256) k_mix() {
    int sl = blockIdx.x, h = blockIdx.y, b = blockIdx.z;
    size_t base = ((size_t)b*MIDC + h*32) * HW;
    __shared__ float sA[32][33];
    __shared__ float sS[32][65];
    int tid = threadIdx.x;
    const float* aw = g_attnW + (size_t)(b*HEADS + h)*1024;
#pragma unroll
    for (int q = 0; q < 4; q++) {
        int e = tid*4 + q;
        sA[e >> 5][e & 31] = aw[e];
    }
    int cm = (tid >> 4) * 2;
    int nm = (tid & 15) * 4;
    for (int n0 = 0; n0 < 512; n0 += 64) {
        int o = sl*512 + n0;
        int row = o >> 6;
        int grow = (64 - row) & 63;
        __syncthreads();
        for (int idx = tid; idx < 1024; idx += 256) {
            int cc = idx >> 5, nn = (idx & 31) * 2;
            float2 fa = __half22float2(*(const __half2*)(&g_xr_h[base + (size_t)cc*HW + o + nn]));
            sS[cc][nn]   = 0.5f * fa.x;
            sS[cc][nn+1] = 0.5f * fa.y;
        }
        __syncthreads();
        for (int idx = tid; idx < 1024; idx += 256) {
            int cc = idx >> 5, nn = (idx & 31) * 2;
            float2 fb = __half22float2(*(const __half2*)(&g_xr_h[base + (size_t)cc*HW + grow*64 + nn]));
            sS[cc][(64 - nn) & 63] += 0.5f * fb.x;
            sS[cc][63 - nn]        += 0.5f * fb.y;
        }
        __syncthreads();
        float o0[4] = {}, o1[4] = {};
#pragma unroll
        for (int d = 0; d < 32; d++) {
            float a0 = sA[cm][d], a1 = sA[cm+1][d];
            float f0 = sS[d][nm], f1 = sS[d][nm+1], f2 = sS[d][nm+2], f3 = sS[d][nm+3];
            o0[0] += a0*f0; o0[1] += a0*f1; o0[2] += a0*f2; o0[3] += a0*f3;
            o1[0] += a1*f0; o1[1] += a1*f1; o1[2] += a1*f2; o1[3] += a1*f3;
        }
        __nv_bfloat162 q00 = __floats2bfloat162_rn(o0[0], o0[1]);
        __nv_bfloat162 q01 = __floats2bfloat162_rn(o0[2], o0[3]);
        __nv_bfloat162 q10 = __floats2bfloat162_rn(o1[0], o1[1]);
        __nv_bfloat162 q11 = __floats2bfloat162_rn(o1[2], o1[3]);
        uint2 pk0, pk1;
        pk0.x = *(uint32_t*)&q00; pk0.y = *(uint32_t*)&q01;
        pk1.x = *(uint32_t*)&q10; pk1.y = *(uint32_t*)&q11;
        size_t fb2 = ((size_t)b*INDIM + h*32) * HW;
        *(uint2*)&g_fused_bf[fb2 + (size_t)cm*HW + o + nm]     = pk0;
        *(uint2*)&g_fused_bf[fb2 + (size_t)(cm+1)*HW + o + nm] = pk1;
    }
}

// ---------------- launch ----------------
extern "C" void kernel_launch(void* const* d_in, const int* in_sizes, int n_in,
                              void* d_out, int out_size) {
    (void)in_sizes; (void)n_in; (void)out_size;
    const float* x        = (const float*)d_in[0];
    const float* reduce_w = (const float*)d_in[1];
    const float* reduce_b = (const float*)d_in[2];
    const float* dw_w     = (const float*)d_in[3];
    const float* dw_b     = (const float*)d_in[4];
    const float* bn_gamma = (const float*)d_in[5];
    const float* bn_beta  = (const float*)d_in[6];
    const float* bn_mean  = (const float*)d_in[7];
    const float* bn_var   = (const float*)d_in[8];
    const float* gate_w1  = (const float*)d_in[9];
    const float* gate_b1  = (const float*)d_in[10];
    const float* gate_w2  = (const float*)d_in[11];
    const float* gate_b2  = (const float*)d_in[12];
    const float* temp     = (const float*)d_in[13];
    const float* post_w   = (const float*)d_in[14];
    const float* post_b   = (const float*)d_in[15];
    float* out = (float*)d_out;

    cudaFuncSetAttribute((const void*)k_gemm_red,
                         cudaFuncAttributeMaxDynamicSharedMemorySize, GEMM_SMEM);
    cudaFuncSetAttribute((const void*)k_gemm_pipe,
                         cudaFuncAttributeMaxDynamicSharedMemorySize, GEMM_SMEM);

    __nv_bfloat16 *p_fbf, *p_wred, *p_wpost;
    cudaGetSymbolAddress((void**)&p_fbf,   g_fused_bf);
    cudaGetSymbolAddress((void**)&p_wred,  g_wred);
    cudaGetSymbolAddress((void**)&p_wpost, g_wpost);
    __half* p_buf1h;
    cudaGetSymbolAddress((void**)&p_buf1h, g_buf1h);

    // merged weight conversions
    int n1 = MIDC*INDIM, n2 = INDIM*2*MIDC;
    k_cvt2<<<((n1+n2)/4 + 255)/256, 256>>>(reduce_w, p_wred, n1, post_w, p_wpost, n2);

    // reduce GEMM (fp32 act staged via cp.async, converted in smem) -> fp16
    k_gemm_red<<<dim3(32, 2, BATCH), 256, GEMM_SMEM>>>(
        p_wred, x, reduce_b, p_buf1h, MIDC);

    // dw + BN + ReLU + stats -> xr fp16 (2 px/thread)
    k_dw<<<BATCH*MIDC, 256>>>(dw_w, dw_b, bn_gamma, bn_beta, bn_mean, bn_var);
    k_gate<<<BATCH, 256>>>(gate_w1, gate_b1, gate_w2, gate_b2);

    // packed-real fwm (2 planes per CTA, radix-8, 512 threads)
    k_fwm2<<<BATCH*MIDC/2, 512>>>();

    // spatial attention
    k_gram<<<dim3(8, HEADS, BATCH), 256>>>();
    k_soft<<<dim3(HEADS, BATCH), 256>>>(temp);
    k_mix<<<dim3(8, HEADS, BATCH), 256>>>();

    // post GEMM (cp.async pipelined, bias + residual)
    k_gemm_pipe<<<dim3(32, 4, BATCH), 256, GEMM_SMEM>>>(
        p_wpost, p_fbf, post_b, x, out, INDIM);
}

// round 13
// speedup vs baseline: 2.6316x; 1.1062x over previous
#include <cuda_runtime.h>
#include <cuda_bf16.h>
#include <cuda_fp16.h>
#include <mma.h>
#include <math.h>
#include <stdint.h>

using namespace nvcuda;

#define BATCH 16
#define INDIM 512
#define MIDC  256
#define HW    4096
#define HEADS 8

// ---------------- scratch (device globals; no allocation) ----------------
__device__ __half g_buf1h[BATCH*MIDC*HW];   // reduce-GEMM output (pre-dw), fp16
__device__ __half g_xr_h[BATCH*MIDC*HW];    // xr (post dw+BN+ReLU), fp16, spatial
__device__ float  g_means[BATCH*MIDC];
__device__ float  g_nrm  [BATCH*MIDC];
__device__ float  g_gate [BATCH*MIDC];
__device__ float  g_gram_part[BATCH*HEADS*8*1024];
__device__ float  g_attnW[BATCH*HEADS*1024];
__device__ __nv_bfloat16 g_fused_bf[BATCH*INDIM*HW]; // [attn_out | gated fwm]
__device__ __nv_bfloat16 g_wred    [MIDC*INDIM];
__device__ __nv_bfloat16 g_wpost   [INDIM*2*MIDC];

// ================= GEMM common =================
#define AS_STRIDE 40
#define BS_STRIDE 136
#define BF_STRIDE 132
#define CS_STRIDE 132
#define GEMM_SMEM (128*CS_STRIDE*4)

__device__ __forceinline__ void cp16(void* sdst, const void* gsrc) {
    uint32_t a = (uint32_t)__cvta_generic_to_shared(sdst);
    asm volatile("cp.async.cg.shared.global [%0], [%1], 16;\n" :: "r"(a), "l"(gsrc));
}
#define CP_COMMIT() asm volatile("cp.async.commit_group;\n" ::: "memory")
#define CP_WAIT(n)  asm volatile("cp.async.wait_group %0;\n" :: "n"(n) : "memory")

__device__ __forceinline__ void mma_step(
    const __nv_bfloat16* As, const __nv_bfloat16* Bs, int wm, int wn,
    wmma::fragment<wmma::accumulator, 16, 16, 16, float> acc[2][4]) {
#pragma unroll
    for (int ks = 0; ks < 2; ks++) {
        wmma::fragment<wmma::matrix_a, 16, 16, 16, __nv_bfloat16, wmma::row_major> af[2];
        wmma::fragment<wmma::matrix_b, 16, 16, 16, __nv_bfloat16, wmma::row_major> bf[4];
#pragma unroll
        for (int i = 0; i < 2; i++)
            wmma::load_matrix_sync(af[i], As + (wm*32 + i*16) * AS_STRIDE + ks*16, AS_STRIDE);
#pragma unroll
        for (int j = 0; j < 4; j++)
            wmma::load_matrix_sync(bf[j], Bs + (ks*16) * BS_STRIDE + wn*64 + j*16, BS_STRIDE);
#pragma unroll
        for (int i = 0; i < 2; i++)
#pragma unroll
            for (int j = 0; j < 4; j++)
                wmma::mma_sync(acc[i][j], af[i], bf[j], acc[i][j]);
    }
}

// ---------------- reduce GEMM: fp32 act, cp.async-staged + smem convert -----------
__global__ void __launch_bounds__(256)
k_gemm_red(const __nv_bfloat16* __restrict__ W,
           const float* __restrict__ act,
           const float* __restrict__ bias,
           __half* __restrict__ out,
           int Mtot) {
    extern __shared__ char sm[];
    __nv_bfloat16* As0 = (__nv_bfloat16*)sm;
    float*         Bf0 = (float*)(sm + 2*128*AS_STRIDE*2);
    __nv_bfloat16* Bs  = (__nv_bfloat16*)(sm + 2*128*AS_STRIDE*2 + 2*32*BF_STRIDE*4);
    float*         Cs  = (float*)sm;

    int tid = threadIdx.x;
    int w   = tid >> 5;
    int wm  = w & 3;
    int wn  = w >> 2;
    int nb = blockIdx.x * 128, mb = blockIdx.y * 128, b = blockIdx.z;

    const __nv_bfloat16* Ag = W + (size_t)mb * 512;
    const float* Bg = act + (size_t)b * 512 * 4096 + nb;

    int ar0 = tid >> 2,  ac0 = (tid & 3) * 8;
    int br0 = tid >> 5,  bs0 = (tid & 31) * 4;

    wmma::fragment<wmma::accumulator, 16, 16, 16, float> acc[2][4];
#pragma unroll
    for (int i = 0; i < 2; i++)
#pragma unroll
        for (int j = 0; j < 4; j++) wmma::fill_fragment(acc[i][j], 0.0f);

    {
#pragma unroll
        for (int t = 0; t < 2; t++) {
            int r = ar0 + t*64;
            cp16(As0 + r*AS_STRIDE + ac0, Ag + (size_t)r*512 + ac0);
        }
#pragma unroll
        for (int t = 0; t < 4; t++) {
            int r = br0 + t*8;
            cp16(Bf0 + r*BF_STRIDE + bs0, Bg + (size_t)r*4096 + bs0);
        }
        CP_COMMIT();
    }

    for (int it = 0; it < 16; it++) {
        int cur = it & 1;
        if (it < 15) {
            int kc = (it + 1) * 32;
            __nv_bfloat16* As = As0 + (cur^1)*128*AS_STRIDE;
            float*         Bf = Bf0 + (cur^1)*32*BF_STRIDE;
#pragma unroll
            for (int t = 0; t < 2; t++) {
                int r = ar0 + t*64;
                cp16(As + r*AS_STRIDE + ac0, Ag + (size_t)r*512 + kc + ac0);
            }
#pragma unroll
            for (int t = 0; t < 4; t++) {
                int r = br0 + t*8;
                cp16(Bf + r*BF_STRIDE + bs0, Bg + (size_t)(kc + r)*4096 + bs0);
            }
            CP_COMMIT();
            CP_WAIT(1);
        } else {
            CP_WAIT(0);
        }
        __syncthreads();
        const float* Bf = Bf0 + cur*32*BF_STRIDE;
#pragma unroll
        for (int t = 0; t < 8; t++) {
            int e2 = (tid + t*256) * 2;
            int r = e2 >> 7, c = e2 & 127;
            __nv_bfloat162 pk = __floats2bfloat162_rn(Bf[r*BF_STRIDE + c],
                                                      Bf[r*BF_STRIDE + c + 1]);
            *(uint32_t*)(Bs + r*BS_STRIDE + c) = *(uint32_t*)&pk;
        }
        __syncthreads();
        mma_step(As0 + cur*128*AS_STRIDE, Bs, wm, wn, acc);
        __syncthreads();
    }
#pragma unroll
    for (int i = 0; i < 2; i++)
#pragma unroll
        for (int j = 0; j < 4; j++)
            wmma::store_matrix_sync(Cs + (wm*32 + i*16) * CS_STRIDE + wn*64 + j*16,
                                    acc[i][j], CS_STRIDE, wmma::mem_row_major);
    __syncthreads();
#pragma unroll
    for (int t = 0; t < 16; t++) {
        int id = tid + t * 256;
        int r = id >> 5, c = (id & 31) * 4;
        float bi = bias[mb + r];
        float4 v = *(float4*)(Cs + r * CS_STRIDE + c);
        __half2 h0 = __floats2half2_rn(v.x + bi, v.y + bi);
        __half2 h1 = __floats2half2_rn(v.z + bi, v.w + bi);
        uint2 pk; pk.x = *(uint32_t*)&h0; pk.y = *(uint32_t*)&h1;
        size_t off = ((size_t)b * Mtot + mb + r) * 4096 + nb + c;
        *(uint2*)(out + off) = pk;
    }
}

// ---------------- post GEMM: bf16 act, cp.async 2-stage pipeline ----------------
__global__ void __launch_bounds__(256)
k_gemm_pipe(const __nv_bfloat16* __restrict__ W,
            const __nv_bfloat16* __restrict__ act,
            const float* __restrict__ bias,
            const float* __restrict__ resid,
            float* __restrict__ out,
            int Mtot) {
    extern __shared__ char sm[];
    __nv_bfloat16* As0 = (__nv_bfloat16*)sm;
    __nv_bfloat16* Bs0 = (__nv_bfloat16*)(sm + 2*128*AS_STRIDE*2);
    float*         Cs  = (float*)sm;

    int tid = threadIdx.x;
    int w   = tid >> 5;
    int wm  = w & 3;
    int wn  = w >> 2;
    int nb = blockIdx.x * 128, mb = blockIdx.y * 128, b = blockIdx.z;

    const __nv_bfloat16* Ag = W + (size_t)mb * 512;
    const __nv_bfloat16* Bg = act + (size_t)b * 512 * 4096 + nb;

    int ar0 = tid >> 2,  ac0 = (tid & 3) * 8;
    int br0 = tid >> 4,  bc0 = (tid & 15) * 8;

    wmma::fragment<wmma::accumulator, 16, 16, 16, float> acc[2][4];
#pragma unroll
    for (int i = 0; i < 2; i++)
#pragma unroll
        for (int j = 0; j < 4; j++) wmma::fill_fragment(acc[i][j], 0.0f);

    {
#pragma unroll
        for (int t = 0; t < 2; t++) {
            int r = ar0 + t*64;
            cp16(As0 + r*AS_STRIDE + ac0, Ag + (size_t)r*512 + ac0);
        }
#pragma unroll
        for (int t = 0; t < 2; t++) {
            int r = br0 + t*16;
            cp16(Bs0 + r*BS_STRIDE + bc0, Bg + (size_t)r*4096 + bc0);
        }
        CP_COMMIT();
    }

    for (int it = 0; it < 16; it++) {
        int cur = it & 1;
        if (it < 15) {
            int kc = (it + 1) * 32;
            __nv_bfloat16* As = As0 + (cur^1)*128*AS_STRIDE;
            __nv_bfloat16* Bs = Bs0 + (cur^1)*32*BS_STRIDE;
#pragma unroll
            for (int t = 0; t < 2; t++) {
                int r = ar0 + t*64;
                cp16(As + r*AS_STRIDE + ac0, Ag + (size_t)r*512 + kc + ac0);
            }
#pragma unroll
            for (int t = 0; t < 2; t++) {
                int r = br0 + t*16;
                cp16(Bs + r*BS_STRIDE + bc0, Bg + (size_t)(kc + r)*4096 + bc0);
            }
            CP_COMMIT();
            CP_WAIT(1);
        } else {
            CP_WAIT(0);
        }
        __syncthreads();
        mma_step(As0 + cur*128*AS_STRIDE, Bs0 + cur*32*BS_STRIDE, wm, wn, acc);
        __syncthreads();
    }
#pragma unroll
    for (int i = 0; i < 2; i++)
#pragma unroll
        for (int j = 0; j < 4; j++)
            wmma::store_matrix_sync(Cs + (wm*32 + i*16) * CS_STRIDE + wn*64 + j*16,
                                    acc[i][j], CS_STRIDE, wmma::mem_row_major);
    __syncthreads();
#pragma unroll
    for (int t = 0; t < 16; t++) {
        int id = tid + t * 256;
        int r = id >> 5, c = (id & 31) * 4;
        float bi = bias[mb + r];
        float4 v = *(float4*)(Cs + r * CS_STRIDE + c);
        v.x += bi; v.y += bi; v.z += bi; v.w += bi;
        size_t off = ((size_t)b * Mtot + mb + r) * 4096 + nb + c;
        float4 rr = *(const float4*)(resid + off);
        v.x += rr.x; v.y += rr.y; v.z += rr.z; v.w += rr.w;
        *(float4*)(out + off) = v;
    }
}

// ---------------- weight conversion ----------------
__global__ void __launch_bounds__(256) k_cvt(const float* __restrict__ src,
                                             __nv_bfloat16* __restrict__ dst, int n) {
    int i = (blockIdx.x * 256 + threadIdx.x) * 4;
    if (i < n) {
        float4 v = *(const float4*)(src + i);
        __nv_bfloat162 p0 = __floats2bfloat162_rn(v.x, v.y);
        __nv_bfloat162 p1 = __floats2bfloat162_rn(v.z, v.w);
        uint2 pk;
        pk.x = *(uint32_t*)&p0; pk.y = *(uint32_t*)&p1;
        *(uint2*)(dst + i) = pk;
    }
}

// ================= radix-8 FFT (64-pt, 2 stages/dim, 512 threads, 1 bfly/thr) ======
template<int Q, int M, bool INV>
__device__ __forceinline__ void fft8s(float* Ar, float* Ai,
                                      const float* twr, const float* twi,
                                      int tid, bool col) {
    const float S2 = 0.70710678118654752440f;
    int bf = tid;
    int line = bf & 63;
    int j8 = bf >> 6;
    int blk = j8 / Q, j = j8 - blk * Q;
    int base = blk * (8 * Q) + j;
    int idx[8];
#pragma unroll
    for (int r = 0; r < 8; r++) {
        int p = base + r * Q;
        idx[r] = col ? p*65 + line : line*65 + p;
    }
    float xr[8], xi[8];
#pragma unroll
    for (int r = 0; r < 8; r++) { xr[r] = Ar[idx[r]]; xi[r] = Ai[idx[r]]; }
    if (INV) {
#pragma unroll
        for (int r = 1; r < 8; r++) {
            float wr = twr[M*j*r], wi = twi[M*j*r];
            float a = xr[r], bb = xi[r];
            xr[r] = a*wr + bb*wi;
            xi[r] = bb*wr - a*wi;
        }
    }
    float t0r=xr[0]+xr[4], t0i=xi[0]+xi[4];
    float t1r=xr[0]-xr[4], t1i=xi[0]-xi[4];
    float t2r=xr[2]+xr[6], t2i=xi[2]+xi[6];
    float d2r=xr[2]-xr[6], d2i=xi[2]-xi[6];
    float t3r, t3i;
    if (INV) { t3r = -d2i; t3i =  d2r; } else { t3r =  d2i; t3i = -d2r; }
    float e0r=t0r+t2r, e0i=t0i+t2i;
    float e1r=t1r+t3r, e1i=t1i+t3i;
    float e2r=t0r-t2r, e2i=t0i-t2i;
    float e3r=t1r-t3r, e3i=t1i-t3i;
    float u0r=xr[1]+xr[5], u0i=xi[1]+xi[5];
    float u1r=xr[1]-xr[5], u1i=xi[1]-xi[5];
    float u2r=xr[3]+xr[7], u2i=xi[3]+xi[7];
    float v2r=xr[3]-xr[7], v2i=xi[3]-xi[7];
    float u3r, u3i;
    if (INV) { u3r = -v2i; u3i =  v2r; } else { u3r =  v2i; u3i = -v2r; }
    float o0r=u0r+u2r, o0i=u0i+u2i;
    float o1r=u1r+u3r, o1i=u1i+u3i;
    float o2r=u0r-u2r, o2i=u0i-u2i;
    float o3r=u1r-u3r, o3i=u1i-u3i;
    float w1i = INV ?  S2 : -S2;
    { float a=o1r, bb=o1i; o1r = S2*a - w1i*bb; o1i = S2*bb + w1i*a; }
    { float a=o2r, bb=o2i; if (INV) { o2r = -bb; o2i = a; } else { o2r = bb; o2i = -a; } }
    { float a=o3r, bb=o3i; o3r = -S2*a - w1i*bb; o3i = -S2*bb + w1i*a; }
    float yr[8], yi[8];
    yr[0]=e0r+o0r; yi[0]=e0i+o0i;
    yr[1]=e1r+o1r; yi[1]=e1i+o1i;
    yr[2]=e2r+o2r; yi[2]=e2i+o2i;
    yr[3]=e3r+o3r; yi[3]=e3i+o3i;
    yr[4]=e0r-o0r; yi[4]=e0i-o0i;
    yr[5]=e1r-o1r; yi[5]=e1i-o1i;
    yr[6]=e2r-o2r; yi[6]=e2i-o2i;
    yr[7]=e3r-o3r; yi[7]=e3i-o3i;
    if (!INV) {
#pragma unroll
        for (int r = 1; r < 8; r++) {
            float wr = twr[M*j*r], wi = twi[M*j*r];
            float a = yr[r], bb = yi[r];
            yr[r] = a*wr - bb*wi;
            yi[r] = a*wi + bb*wr;
        }
    }
#pragma unroll
    for (int r = 0; r < 8; r++) { Ar[idx[r]] = yr[r]; Ai[idx[r]] = yi[r]; }
}

__device__ __forceinline__ void fft8_fwd_dim(float* Ar, float* Ai,
                                             const float* twr, const float* twi,
                                             int tid, bool col) {
    fft8s<8,1,false>(Ar, Ai, twr, twi, tid, col); __syncthreads();
    fft8s<1,8,false>(Ar, Ai, twr, twi, tid, col); __syncthreads();
}
__device__ __forceinline__ void fft8_inv_dim(float* Ar, float* Ai,
                                             const float* twr, const float* twi,
                                             int tid, bool col) {
    fft8s<1,8,true>(Ar, Ai, twr, twi, tid, col); __syncthreads();
    fft8s<8,1,true>(Ar, Ai, twr, twi, tid, col); __syncthreads();
}

__device__ __forceinline__ void fft_load_tw64(float* twr, float* twi, int tid) {
    if (tid < 64) {
        float s, c;
        sincosf(-6.28318530717958647692f * (float)tid * (1.0f/64.0f), &s, &c);
        twr[tid] = c; twi[tid] = s;
    }
}

// ---------------- K2: dw 3x3 + BN + ReLU + stats, 2 px/thread ----------
__global__ void __launch_bounds__(256) k_dw(const float* __restrict__ dww,
                                            const float* __restrict__ dwb,
                                            const float* __restrict__ gamma,
                                            const float* __restrict__ beta,
                                            const float* __restrict__ mean,
                                            const float* __restrict__ var) {
    int plane = blockIdx.x;
    int c = plane & (MIDC-1);
    __shared__ float tile[66*66];
    __shared__ float rs[8], rq[8];
    const __half* src = g_buf1h + (size_t)plane*HW;
    int tid = threadIdx.x;
#pragma unroll
    for (int i = 0; i < 8; i++) {
        int e = tid + i*256;
        int p = e*2;
        int r = p >> 6, cc = p & 63;
        __half2 h = *(const __half2*)(src + p);
        float2 f = __half22float2(h);
        float* t = &tile[(r+1)*66 + cc + 1];
        t[0] = f.x; t[1] = f.y;
    }
    for (int i = tid; i < 260; i += 256) {
        int a;
        if (i < 66)       a = i;
        else if (i < 132) a = 65*66 + (i - 66);
        else if (i < 196) a = (i - 131)*66;
        else              a = (i - 195)*66 + 65;
        tile[a] = 0.f;
    }
    __syncthreads();
    float w0 = dww[c*9+0], w1 = dww[c*9+1], w2 = dww[c*9+2];
    float w3 = dww[c*9+3], w4 = dww[c*9+4], w5 = dww[c*9+5];
    float w6 = dww[c*9+6], w7 = dww[c*9+7], w8 = dww[c*9+8];
    float scale = gamma[c] * rsqrtf(var[c] + 1e-5f);
    float shift = beta[c] - mean[c]*scale;
    float bia = dwb[c];
    float s = 0.f, sq = 0.f;
    __half* dst = g_xr_h + (size_t)plane*HW;
#pragma unroll
    for (int i = 0; i < 8; i++) {
        int e = tid + i*256;
        int p = e*2;
        int py = p >> 6, px = p & 63;
        const float* t0 = &tile[py*66 + px];
        float r00=t0[0],  r01=t0[1],  r02=t0[2],  r03=t0[3];
        float r10=t0[66], r11=t0[67], r12=t0[68], r13=t0[69];
        float r20=t0[132],r21=t0[133],r22=t0[134],r23=t0[135];
        float a0 = r00*w0 + r01*w1 + r02*w2
                 + r10*w3 + r11*w4 + r12*w5
                 + r20*w6 + r21*w7 + r22*w8;
        float a1 = r01*w0 + r02*w1 + r03*w2
                 + r11*w3 + r12*w4 + r13*w5
                 + r21*w6 + r22*w7 + r23*w8;
        a0 = fmaxf((a0 + bia)*scale + shift, 0.f);
        a1 = fmaxf((a1 + bia)*scale + shift, 0.f);
        *(__half2*)(dst + p) = __floats2half2_rn(a0, a1);
        s += a0 + a1; sq += a0*a0 + a1*a1;
    }
#pragma unroll
    for (int o = 16; o; o >>= 1) {
        s  += __shfl_xor_sync(0xffffffffu, s,  o);
        sq += __shfl_xor_sync(0xffffffffu, sq, o);
    }
    int wid = tid >> 5;
    if ((tid & 31) == 0) { rs[wid] = s; rq[wid] = sq; }
    __syncthreads();
    if (tid == 0) {
        float ts = 0.f, tq = 0.f;
#pragma unroll
        for (int w = 0; w < 8; w++) { ts += rs[w]; tq += rq[w]; }
        g_means[plane] = ts * (1.f/4096.f);
        g_nrm[plane]   = sqrtf(tq);   // Parseval
    }
}

// ---- K7: packed-real fwm, 2 planes/CTA, radix-8, 512 threads, gated output ----
__global__ void __launch_bounds__(512) k_fwm2() {
    __shared__ float Ar[64*65], Ai[64*65], twr[64], twi[64];
    __shared__ int mate[64];
    int pp = blockIdx.x;
    int plane0 = pp * 2;
    int b = plane0 >> 8, c0 = plane0 & (MIDC-1);
    int tid = threadIdx.x;
    const __half* x0 = g_xr_h + (size_t)plane0*HW;
    const __half* x1 = x0 + HW;
#pragma unroll
    for (int i = 0; i < 8; i++) {
        int p = tid + i*512; int r = p >> 6, cc = p & 63;
        Ar[r*65+cc] = __half2float(x0[p]);
        Ai[r*65+cc] = __half2float(x1[p]);
    }
    fft_load_tw64(twr, twi, tid);
    if (tid < 64) {
        int rv = ((tid & 7) << 3) | (tid >> 3);
        int nk = (64 - rv) & 63;
        mate[tid] = ((nk & 7) << 3) | (nk >> 3);
    }
    __syncthreads();
    fft8_fwd_dim(Ar, Ai, twr, twi, tid, false);
    fft8_fwd_dim(Ar, Ai, twr, twi, tid, true);
#pragma unroll
    for (int i = 0; i < 8; i++) {
        int p = tid + i*512; int r = p >> 6, cc = p & 63;
        int mr = mate[r], mc = mate[cc];
        int fm = mr*64 + mc;
        if (p <= fm) {
            int a  = r*65 + cc;
            int am = mr*65 + mc;
            float zpr = Ar[a],  zpi = Ai[a];
            float zmr = Ar[am], zmi = Ai[am];
            float f1r = 0.5f*(zpr + zmr), f1i = 0.5f*(zpi - zmi);
            float f2r = 0.5f*(zpi + zmi), f2i = 0.5f*(zmr - zpr);
            float W1r = f1r*f1r - f1i*f1i, W1i = 2.f*f1r*f1i;
            float W2r = f2r*f2r - f2i*f2i, W2i = 2.f*f2r*f2i;
            Ar[a]  = W1r - W2i;  Ai[a]  = W1i + W2r;
            Ar[am] = W1r + W2i;  Ai[am] = W2r - W1i;
        }
    }
    __syncthreads();
    fft8_inv_dim(Ar, Ai, twr, twi, tid, false);
    fft8_inv_dim(Ar, Ai, twr, twi, tid, true);
    float sc0 = g_gate[b*MIDC + c0]     * (1.f/262144.f);
    float sc1 = g_gate[b*MIDC + c0 + 1] * (1.f/262144.f);
    __nv_bfloat16* dst0 = g_fused_bf + ((size_t)b*INDIM + MIDC + c0)*HW;
    __nv_bfloat16* dst1 = dst0 + HW;
#pragma unroll
    for (int i = 0; i < 8; i++) {
        int p = tid + i*512; int r = p >> 6, cc = p & 63;
        int a = r*65 + cc;
        dst0[p] = __float2bfloat16(Ar[a] * sc0);
        dst1[p] = __float2bfloat16(Ai[a] * sc1);
    }
}

// ---------------- K3: SE gate MLP (parallel reduction) ----------------
__global__ void __launch_bounds__(256) k_gate(const float* __restrict__ w1,
                                              const float* __restrict__ b1,
                                              const float* __restrict__ w2,
                                              const float* __restrict__ b2) {
    int b = blockIdx.x;
    __shared__ float sm[MIDC];
    __shared__ float sh[32];
    int tid = threadIdx.x;
    sm[tid] = g_means[b*MIDC + tid];
    __syncthreads();
    {
        int o = tid >> 3, part = tid & 7;
        const float* wr = w1 + o*MIDC + part*32;
        const float* mr = sm + part*32;
        float a = 0.f;
#pragma unroll
        for (int j = 0; j < 32; j++) a += wr[j]*mr[j];
#pragma unroll
        for (int off = 4; off; off >>= 1)
            a += __shfl_down_sync(0xffffffffu, a, off, 8);
        if (part == 0) sh[o] = fmaxf(a + b1[o], 0.f);
    }
    __syncthreads();
    float a = b2[tid];
    const float* wr = w2 + tid*32;
#pragma unroll
    for (int j = 0; j < 32; j++) a += wr[j]*sh[j];
    g_gate[b*MIDC + tid] = 1.f / (1.f + expf(-a));
}

// ------- K4a: spatial Gram via wmma: C[32,32] = X[32,512] * Y^T ---
#define GX_STRIDE 72
__global__ void __launch_bounds__(256) k_gram() {
    int sl = blockIdx.x, h = blockIdx.y, b = blockIdx.z;
    size_t base = ((size_t)b*MIDC + h*32) * HW;
    __shared__ __align__(16) __half sX[32*GX_STRIDE];
    __shared__ __align__(16) __half sY[32*GX_STRIDE];
    __shared__ float sC[8][256];
    int tid = threadIdx.x;
    int warp = tid >> 5;
    int tile = warp & 3;
    int kgrp = warp >> 2;
    int ti = tile >> 1, tj = tile & 1;

    wmma::fragment<wmma::accumulator, 16, 16, 16, float> acc;
    wmma::fill_fragment(acc, 0.0f);

    for (int it = 0; it < 8; it++) {
        int o = sl*512 + it*64;
        int row = o >> 6;
        int grow = (64 - row) & 63;
        __syncthreads();
        for (int idx = tid; idx < 1024; idx += 256) {
            int cc = idx >> 5, nn = (idx & 31) * 2;
            __half2 hx = *(const __half2*)(&g_xr_h[base + (size_t)cc*HW + o + nn]);
            sX[cc*GX_STRIDE + nn]     = __low2half(hx);
            sX[cc*GX_STRIDE + nn + 1] = __high2half(hx);
            __half2 hy = *(const __half2*)(&g_xr_h[base + (size_t)cc*HW + grow*64 + nn]);
            sY[cc*GX_STRIDE + ((64 - nn) & 63)] = __low2half(hy);
            sY[cc*GX_STRIDE + 63 - nn]          = __high2half(hy);
        }
        __syncthreads();
        if ((it & 1) == kgrp) {
#pragma unroll
            for (int ks = 0; ks < 4; ks++) {
                wmma::fragment<wmma::matrix_a, 16, 16, 16, __half, wmma::row_major> af;
                wmma::fragment<wmma::matrix_b, 16, 16, 16, __half, wmma::col_major> bf;
                wmma::load_matrix_sync(af, sX + (ti*16)*GX_STRIDE + ks*16, GX_STRIDE);
                wmma::load_matrix_sync(bf, sY + (tj*16)*GX_STRIDE + ks*16, GX_STRIDE);
                wmma::mma_sync(acc, af, bf, acc);
            }
        }
    }
    __syncthreads();
    wmma::store_matrix_sync(sC[warp], acc, 16, wmma::mem_row_major);
    __syncthreads();
    float* part = g_gram_part + ((size_t)(b*HEADS + h)*8 + sl)*1024;
    for (int e = tid; e < 1024; e += 256) {
        int c = e >> 5, d = e & 31;
        int t = (c >> 4)*2 + (d >> 4);
        int lr = c & 15, lc = d & 15;
        part[e] = sC[t][lr*16 + lc] + sC[t+4][lr*16 + lc];
    }
}

// ---------------- K4b: reduce partials + normalize + softmax ----------------
__global__ void __launch_bounds__(256) k_soft(const float* __restrict__ temp) {
    int h = blockIdx.x, b = blockIdx.y;
    __shared__ float sA[32][33], sN[32];
    int tid = threadIdx.x;
    if (tid < 32) sN[tid] = fmaxf(g_nrm[b*MIDC + h*32 + tid], 1e-12f);
    __syncthreads();
    float tK = temp[h];
    const float* part = g_gram_part + (size_t)(b*HEADS + h)*8*1024;
#pragma unroll
    for (int q = 0; q < 4; q++) {
        int e = tid*4 + q;
        int c = e >> 5, d = e & 31;
        float v = 0.f;
#pragma unroll
        for (int s = 0; s < 8; s++) v += part[s*1024 + e];
        sA[c][d] = v * tK / (sN[c] * sN[d]);
    }
    __syncthreads();
    int lane = tid & 31;
    float* aw = g_attnW + (size_t)(b*HEADS + h)*1024;
#pragma unroll
    for (int rr = 0; rr < 4; rr++) {
        int row = (tid >> 5)*4 + rr;
        float v = sA[row][lane];
        float mx = v;
#pragma unroll
        for (int o = 16; o; o >>= 1) mx = fmaxf(mx, __shfl_xor_sync(0xffffffffu, mx, o));
        float e = expf(v - mx);
        float smv = e;
#pragma unroll
        for (int o = 16; o; o >>= 1) smv += __shfl_xor_sync(0xffffffffu, smv, o);
        aw[row*32 + lane] = e / smv;
    }
}

// ---- K4c: spatial mix via wmma: out[32,64] = A[32,32] * S[32,64] per chunk ----
#define MS_STRIDE 72
#define MA_STRIDE 40
#define MC_STRIDE 68
__global__ void __launch_bounds__(256) k_mix() {
    int sl = blockIdx.x, h = blockIdx.y, b = blockIdx.z;
    size_t base = ((size_t)b*MIDC + h*32) * HW;
    __shared__ __align__(16) __half sA[32*MA_STRIDE];
    __shared__ __align__(16) __half sS[32*MS_STRIDE];
    __shared__ float sC[32*MC_STRIDE];
    int tid = threadIdx.x;
    const float* aw = g_attnW + (size_t)(b*HEADS + h)*1024;
#pragma unroll
    for (int q = 0; q < 4; q++) {
        int e = tid*4 + q;
        sA[(e >> 5)*MA_STRIDE + (e & 31)] = __float2half(aw[e]);
    }
    int warp = tid >> 5;
    int ti = warp >> 2, tj = warp & 3;   // 2 x 4 tiles of 16x16
    size_t fb2 = ((size_t)b*INDIM + h*32) * HW;
    for (int it = 0; it < 8; it++) {
        int o = sl*512 + it*64;
        int row = o >> 6;
        int grow = (64 - row) & 63;
        __syncthreads();   // sC fully read from prev iter, sA ready (iter 0)
        // build symmetric S (fp16): forward pair vectorized, reversed scalars
        for (int idx = tid; idx < 1024; idx += 256) {
            int cc = idx >> 5, nn = (idx & 31) * 2;
            float2 ff = __half22float2(*(const __half2*)(&g_xr_h[base + (size_t)cc*HW + o + nn]));
            const __half* rv = &g_xr_h[base + (size_t)cc*HW + grow*64];
            float r0 = __half2float(rv[(64 - nn) & 63]);   // scalar: alignment-safe
            float r1 = __half2float(rv[63 - nn]);
            *(__half2*)(&sS[cc*MS_STRIDE + nn]) =
                __floats2half2_rn(0.5f*(ff.x + r0), 0.5f*(ff.y + r1));
        }
        __syncthreads();
        {
            wmma::fragment<wmma::accumulator, 16, 16, 16, float> acc;
            wmma::fill_fragment(acc, 0.0f);
#pragma unroll
            for (int ks = 0; ks < 2; ks++) {
                wmma::fragment<wmma::matrix_a, 16, 16, 16, __half, wmma::row_major> af;
                wmma::fragment<wmma::matrix_b, 16, 16, 16, __half, wmma::row_major> bf;
                wmma::load_matrix_sync(af, sA + (ti*16)*MA_STRIDE + ks*16, MA_STRIDE);
                wmma::load_matrix_sync(bf, sS + (ks*16)*MS_STRIDE + tj*16, MS_STRIDE);
                wmma::mma_sync(acc, af, bf, acc);
            }
            wmma::store_matrix_sync(sC + (ti*16)*MC_STRIDE + tj*16, acc,
                                    MC_STRIDE, wmma::mem_row_major);
        }
        __syncthreads();
        for (int idx = tid; idx < 1024; idx += 256) {
            int cc = idx >> 5, nn = (idx & 31) * 2;
            __nv_bfloat162 q = __floats2bfloat162_rn(sC[cc*MC_STRIDE + nn],
                                                     sC[cc*MC_STRIDE + nn + 1]);
            *(uint32_t*)(&g_fused_bf[fb2 + (size_t)cc*HW + o + nn]) = *(uint32_t*)&q;
        }
    }
}

// ---------------- launch ----------------
extern "C" void kernel_launch(void* const* d_in, const int* in_sizes, int n_in,
                              void* d_out, int out_size) {
    (void)in_sizes; (void)n_in; (void)out_size;
    const float* x        = (const float*)d_in[0];
    const float* reduce_w = (const float*)d_in[1];
    const float* reduce_b = (const float*)d_in[2];
    const float* dw_w     = (const float*)d_in[3];
    const float* dw_b     = (const float*)d_in[4];
    const float* bn_gamma = (const float*)d_in[5];
    const float* bn_beta  = (const float*)d_in[6];
    const float* bn_mean  = (const float*)d_in[7];
    const float* bn_var   = (const float*)d_in[8];
    const float* gate_w1  = (const float*)d_in[9];
    const float* gate_b1  = (const float*)d_in[10];
    const float* gate_w2  = (const float*)d_in[11];
    const float* gate_b2  = (const float*)d_in[12];
    const float* temp     = (const float*)d_in[13];
    const float* post_w   = (const float*)d_in[14];
    const float* post_b   = (const float*)d_in[15];
    float* out = (float*)d_out;

    cudaFuncSetAttribute((const void*)k_gemm_red,
                         cudaFuncAttributeMaxDynamicSharedMemorySize, GEMM_SMEM);
    cudaFuncSetAttribute((const void*)k_gemm_pipe,
                         cudaFuncAttributeMaxDynamicSharedMemorySize, GEMM_SMEM);

    __nv_bfloat16 *p_fbf, *p_wred, *p_wpost;
    cudaGetSymbolAddress((void**)&p_fbf,   g_fused_bf);
    cudaGetSymbolAddress((void**)&p_wred,  g_wred);
    cudaGetSymbolAddress((void**)&p_wpost, g_wpost);
    __half* p_buf1h;
    cudaGetSymbolAddress((void**)&p_buf1h, g_buf1h);

    cudaStream_t s2;
    cudaStreamCreateWithFlags(&s2, cudaStreamNonBlocking);
    cudaEvent_t e0, e1, e2;
    cudaEventCreateWithFlags(&e0, cudaEventDisableTiming);
    cudaEventCreateWithFlags(&e1, cudaEventDisableTiming);
    cudaEventCreateWithFlags(&e2, cudaEventDisableTiming);

    // fork side stream at entry
    cudaEventRecord(e0, 0);
    cudaStreamWaitEvent(s2, e0, 0);

    // side: post-weight conversion (only needed by gemm_pipe)
    k_cvt<<<(INDIM*2*MIDC/4 + 255)/256, 256, 0, s2>>>(post_w, p_wpost, INDIM*2*MIDC);

    // main: reduce-weight conversion -> reduce GEMM -> dw
    k_cvt<<<(MIDC*INDIM/4 + 255)/256, 256>>>(reduce_w, p_wred, MIDC*INDIM);
    k_gemm_red<<<dim3(32, 2, BATCH), 256, GEMM_SMEM>>>(
        p_wred, x, reduce_b, p_buf1h, MIDC);
    k_dw<<<BATCH*MIDC, 256>>>(dw_w, dw_b, bn_gamma, bn_beta, bn_mean, bn_var);

    // fork after dw: branch A (gate -> fwm2) on side stream
    cudaEventRecord(e1, 0);
    cudaStreamWaitEvent(s2, e1, 0);
    k_gate<<<BATCH, 256, 0, s2>>>(gate_w1, gate_b1, gate_w2, gate_b2);
    k_fwm2<<<BATCH*MIDC/2, 512, 0, s2>>>();

    // branch B (gram -> soft -> mix) on main
    k_gram<<<dim3(8, HEADS, BATCH), 256>>>();
    k_soft<<<dim3(HEADS, BATCH), 256>>>(temp);
    k_mix<<<dim3(8, HEADS, BATCH), 256>>>();

    // join: post GEMM needs both halves of fused + wpost
    cudaEventRecord(e2, s2);
    cudaStreamWaitEvent(0, e2, 0);
    k_gemm_pipe<<<dim3(32, 4, BATCH), 256, GEMM_SMEM>>>(
        p_wpost, p_fbf, post_b, x, out, INDIM);
}